// round 1
// baseline (speedup 1.0000x reference)
#include <cuda_runtime.h>

typedef unsigned long long ull;

#define D_MODEL 1024
#define NHEAD   16
#define HEAD_DIM 64
#define BATCH   4
#define SEQ     2048
#define M_TOT   (BATCH * SEQ)

// ---------------- scratch (static device memory; no allocations) ----------
__device__ float g_Q[BATCH * NHEAD * SEQ * HEAD_DIM];
__device__ float g_K[BATCH * NHEAD * SEQ * HEAD_DIM];
__device__ float g_V[BATCH * NHEAD * SEQ * HEAD_DIM];
__device__ float g_ctx[M_TOT * D_MODEL];

// ---------------- packed f32x2 helpers (Blackwell) ------------------------
__device__ __forceinline__ ull pk2(float x, float y) {
    ull r; asm("mov.b64 %0, {%1, %2};" : "=l"(r) : "f"(x), "f"(y)); return r;
}
__device__ __forceinline__ void upk2(ull v, float &x, float &y) {
    asm("mov.b64 {%0, %1}, %2;" : "=f"(x), "=f"(y) : "l"(v));
}
__device__ __forceinline__ ull ffma2(ull a, ull b, ull c) {
    ull d; asm("fma.rn.f32x2 %0, %1, %2, %3;" : "=l"(d) : "l"(a), "l"(b), "l"(c)); return d;
}
__device__ __forceinline__ ull fmul2(ull a, ull b) {
    ull d; asm("mul.rn.f32x2 %0, %1, %2;" : "=l"(d) : "l"(a), "l"(b)); return d;
}

// ---------------- projection GEMM: out = (X @ W^T + bias) * scale ---------
// X: [M, 1024], W: [1024, 1024] (row n contiguous in k), bias: [1024]
// TOHEADS: out[b, h, s, dh] layout; else out[m, n].
template <bool TOHEADS>
__global__ void __launch_bounds__(256, 2)
proj_kernel(const float* __restrict__ X, const float* __restrict__ W,
            const float* __restrict__ bias, float* __restrict__ out, float scale)
{
    __shared__ __align__(16) float As[8 * 128];
    __shared__ __align__(16) float Bs[8 * 128];

    const int tid = threadIdx.x;
    const int tm = tid >> 4, tn = tid & 15;
    const int m0 = blockIdx.y << 7, n0 = blockIdx.x << 7;

    ull acc[8][4];
#pragma unroll
    for (int i = 0; i < 8; ++i)
#pragma unroll
        for (int jp = 0; jp < 4; ++jp) acc[i][jp] = 0ull;

    const int lrow = tid >> 1;
    const int lk = (tid & 1) << 2;
    const float* Xp = X + (size_t)(m0 + lrow) * D_MODEL + lk;
    const float* Wp = W + (size_t)(n0 + lrow) * D_MODEL + lk;

    for (int k0 = 0; k0 < D_MODEL; k0 += 8) {
        float4 xa = *(const float4*)(Xp + k0);
        float4 wb = *(const float4*)(Wp + k0);
        __syncthreads();
        As[(lk + 0) * 128 + lrow] = xa.x;
        As[(lk + 1) * 128 + lrow] = xa.y;
        As[(lk + 2) * 128 + lrow] = xa.z;
        As[(lk + 3) * 128 + lrow] = xa.w;
        Bs[(lk + 0) * 128 + lrow] = wb.x;
        Bs[(lk + 1) * 128 + lrow] = wb.y;
        Bs[(lk + 2) * 128 + lrow] = wb.z;
        Bs[(lk + 3) * 128 + lrow] = wb.w;
        __syncthreads();
#pragma unroll
        for (int k = 0; k < 8; ++k) {
            const float* ar = &As[k * 128 + (tm << 3)];
            float4 a0 = *(const float4*)ar;
            float4 a1 = *(const float4*)(ar + 4);
            const ull* br = (const ull*)&Bs[k * 128 + (tn << 3)];
            ull b0 = br[0], b1 = br[1], b2 = br[2], b3 = br[3];
            float av[8] = {a0.x, a0.y, a0.z, a0.w, a1.x, a1.y, a1.z, a1.w};
#pragma unroll
            for (int i = 0; i < 8; ++i) {
                ull aa = pk2(av[i], av[i]);
                acc[i][0] = ffma2(aa, b0, acc[i][0]);
                acc[i][1] = ffma2(aa, b1, acc[i][1]);
                acc[i][2] = ffma2(aa, b2, acc[i][2]);
                acc[i][3] = ffma2(aa, b3, acc[i][3]);
            }
        }
    }

    float bv[8];
    *(float4*)&bv[0] = *(const float4*)&bias[n0 + (tn << 3)];
    *(float4*)&bv[4] = *(const float4*)&bias[n0 + (tn << 3) + 4];

#pragma unroll
    for (int rr = 0; rr < 8; ++rr) {
        float o[8];
#pragma unroll
        for (int jp = 0; jp < 4; ++jp) upk2(acc[rr][jp], o[2 * jp], o[2 * jp + 1]);
#pragma unroll
        for (int c = 0; c < 8; ++c) o[c] = (o[c] + bv[c]) * scale;

        int m = m0 + (tm << 3) + rr;
        float* p;
        if (TOHEADS) {
            int b = m >> 11, srow = m & (SEQ - 1);
            int nb = n0 + (tn << 3);
            int h = nb >> 6, dh = nb & 63;
            p = out + (((size_t)(b * NHEAD + h) * SEQ + srow) * HEAD_DIM + dh);
        } else {
            p = out + (size_t)m * D_MODEL + n0 + (tn << 3);
        }
        *(float4*)p       = make_float4(o[0], o[1], o[2], o[3]);
        *(float4*)(p + 4) = make_float4(o[4], o[5], o[6], o[7]);
    }
}

// ---------------- causal flash attention ----------------------------------
// Q/K/V: [B*H, S, 64] (Q pre-scaled by 1/8). ctx: [B, S, 1024].
__global__ void __launch_bounds__(256, 2)
attn_kernel(const float* __restrict__ Q, const float* __restrict__ K,
            const float* __restrict__ V, float* __restrict__ ctx)
{
    __shared__ __align__(16) float Qt[64 * 64];   // [kk][row]
    __shared__ __align__(16) float Ks[64 * 64];   // K swizzled; later P [r][c]
    __shared__ __align__(16) float Vs[64 * 64];   // [c][d]

    const int tid = threadIdx.x;
    const int tm = tid >> 4, tn = tid & 15;
    const int qt = blockIdx.x, bh = blockIdx.y;
    const size_t base = (size_t)bh * SEQ * HEAD_DIM;

    // load + transpose Q tile (once per block)
    const float* Qg = Q + base + (size_t)qt * 64 * 64;
    for (int idx = tid; idx < 4096; idx += 256) {
        int r = idx >> 6, kk = idx & 63;
        Qt[kk * 64 + r] = Qg[idx];
    }

    float m_i[4], l_i[4];
    ull o2[4][2];
#pragma unroll
    for (int i = 0; i < 4; ++i) {
        m_i[i] = -1e30f; l_i[i] = 0.f; o2[i][0] = 0ull; o2[i][1] = 0ull;
    }
    int bbase[4];
#pragma unroll
    for (int j = 0; j < 4; ++j) bbase[j] = ((tn << 2) + j) << 6;
    const int sw = tn << 2;

    for (int kt = 0; kt <= qt; ++kt) {
        __syncthreads();  // prev PV / Qt-load done before overwriting tiles
        const float4* Kg4 = (const float4*)(K + base + (size_t)kt * 64 * 64);
        const float4* Vg4 = (const float4*)(V + base + (size_t)kt * 64 * 64);
#pragma unroll
        for (int u = 0; u < 4; ++u) {
            int t = tid + u * 256;
            int c = t >> 4, q4 = t & 15;
            int kkp = ((q4 << 2) + ((c >> 2) << 2)) & 63;   // swizzle
            ((float4*)Ks)[(c << 4) + (kkp >> 2)] = Kg4[t];
            ((float4*)Vs)[t] = Vg4[t];
        }
        __syncthreads();

        // S = Q K^T (Q pre-scaled)
        ull acc[4][2] = {0ull, 0ull, 0ull, 0ull, 0ull, 0ull, 0ull, 0ull};
#pragma unroll 4
        for (int kk = 0; kk < 64; ++kk) {
            const ull* qa = (const ull*)&Qt[kk * 64 + (tm << 2)];
            ull a0 = qa[0], a1 = qa[1];
            int kks = (kk + sw) & 63;
#pragma unroll
            for (int j = 0; j < 4; ++j) {
                float b = Ks[bbase[j] + kks];
                ull bb = pk2(b, b);
                acc[j][0] = ffma2(bb, a0, acc[j][0]);
                acc[j][1] = ffma2(bb, a1, acc[j][1]);
            }
        }

        float s[4][4];
#pragma unroll
        for (int j = 0; j < 4; ++j) {
            upk2(acc[j][0], s[0][j], s[1][j]);
            upk2(acc[j][1], s[2][j], s[3][j]);
        }
        if (kt == qt) {
#pragma unroll
            for (int i = 0; i < 4; ++i)
#pragma unroll
                for (int j = 0; j < 4; ++j)
                    if ((tn << 2) + j > (tm << 2) + i) s[i][j] = -1e30f;
        }

        float alpha[4];
#pragma unroll
        for (int i = 0; i < 4; ++i) {
            float mx = fmaxf(fmaxf(s[i][0], s[i][1]), fmaxf(s[i][2], s[i][3]));
#pragma unroll
            for (int off = 1; off < 16; off <<= 1)
                mx = fmaxf(mx, __shfl_xor_sync(0xffffffffu, mx, off));
            float mn = fmaxf(m_i[i], mx);
            float al = __expf(m_i[i] - mn);
            m_i[i] = mn;
            float sum = 0.f;
#pragma unroll
            for (int j = 0; j < 4; ++j) {
                float pv = __expf(s[i][j] - mn);
                s[i][j] = pv;
                sum += pv;
            }
#pragma unroll
            for (int off = 1; off < 16; off <<= 1)
                sum += __shfl_xor_sync(0xffffffffu, sum, off);
            l_i[i] = l_i[i] * al + sum;
            alpha[i] = al;
        }

        __syncthreads();  // everyone finished reading Ks; reuse it as P
#pragma unroll
        for (int i = 0; i < 4; ++i) {
            ull aa = pk2(alpha[i], alpha[i]);
            o2[i][0] = fmul2(o2[i][0], aa);
            o2[i][1] = fmul2(o2[i][1], aa);
#pragma unroll
            for (int j = 0; j < 4; ++j)
                Ks[((tm << 2) + i) * 64 + (tn << 2) + j] = s[i][j];
        }
        __syncthreads();

        // O += P V
#pragma unroll 4
        for (int c = 0; c < 64; ++c) {
            const ull* vp = (const ull*)&Vs[c * 64 + (tn << 2)];
            ull v0 = vp[0], v1 = vp[1];
#pragma unroll
            for (int i = 0; i < 4; ++i) {
                float pv = Ks[((tm << 2) + i) * 64 + c];
                ull pp = pk2(pv, pv);
                o2[i][0] = ffma2(pp, v0, o2[i][0]);
                o2[i][1] = ffma2(pp, v1, o2[i][1]);
            }
        }
    }

    const int b = bh >> 4, h = bh & 15;
#pragma unroll
    for (int i = 0; i < 4; ++i) {
        float inv = 1.0f / l_i[i];
        float q0, q1, q2, q3;
        upk2(o2[i][0], q0, q1);
        upk2(o2[i][1], q2, q3);
        int row = qt * 64 + (tm << 2) + i;
        float* p = ctx + ((size_t)b * SEQ + row) * D_MODEL + h * 64 + (tn << 2);
        *(float4*)p = make_float4(q0 * inv, q1 * inv, q2 * inv, q3 * inv);
    }
}

// ---------------- launcher -------------------------------------------------
extern "C" void kernel_launch(void* const* d_in, const int* in_sizes, int n_in,
                              void* d_out, int out_size)
{
    const float* query = (const float*)d_in[0];
    const float* key_  = (const float*)d_in[1];
    const float* value = (const float*)d_in[2];
    // d_in[3]: causal mask (tril) — structure is fixed; handled analytically.
    const float* Wq = (const float*)d_in[4];
    const float* bq = (const float*)d_in[5];
    const float* Wk = (const float*)d_in[6];
    const float* bk = (const float*)d_in[7];
    const float* Wv = (const float*)d_in[8];
    const float* bv = (const float*)d_in[9];
    const float* Wo = (const float*)d_in[10];
    const float* bo = (const float*)d_in[11];
    float* out = (float*)d_out;

    float *pQ, *pK, *pV, *pC;
    cudaGetSymbolAddress((void**)&pQ, g_Q);
    cudaGetSymbolAddress((void**)&pK, g_K);
    cudaGetSymbolAddress((void**)&pV, g_V);
    cudaGetSymbolAddress((void**)&pC, g_ctx);

    dim3 gp(D_MODEL / 128, M_TOT / 128);  // (8, 64)
    dim3 ga(SEQ / 64, BATCH * NHEAD);     // (32, 64)

    proj_kernel<true><<<gp, 256>>>(query, Wq, bq, pQ, 0.125f);  // 1/sqrt(64) folded
    proj_kernel<true><<<gp, 256>>>(key_,  Wk, bk, pK, 1.0f);
    proj_kernel<true><<<gp, 256>>>(value, Wv, bv, pV, 1.0f);
    attn_kernel<<<ga, 256>>>(pQ, pK, pV, pC);
    proj_kernel<false><<<gp, 256>>>(pC, Wo, bo, out, 1.0f);
}

// round 4
// speedup vs baseline: 1.6760x; 1.6760x over previous
#include <cuda_runtime.h>
#include <cuda_bf16.h>
#include <cstdint>

typedef unsigned long long ull;

#define D_MODEL 1024
#define NHEAD   16
#define HEAD_DIM 64
#define BATCH   4
#define SEQ     2048
#define M_TOT   (BATCH * SEQ)

// ---------------- scratch (static device memory; no allocations) ----------
__device__ float g_Q[BATCH * NHEAD * SEQ * HEAD_DIM];
__device__ float g_K[BATCH * NHEAD * SEQ * HEAD_DIM];
__device__ float g_V[BATCH * NHEAD * SEQ * HEAD_DIM];
__device__ float g_ctx[M_TOT * D_MODEL];
__device__ __nv_bfloat16 g_Xhi[M_TOT * D_MODEL];
__device__ __nv_bfloat16 g_Xlo[M_TOT * D_MODEL];
__device__ __nv_bfloat16 g_Whi[D_MODEL * D_MODEL];
__device__ __nv_bfloat16 g_Wlo[D_MODEL * D_MODEL];

// ---------------- small helpers -------------------------------------------
__device__ __forceinline__ uint32_t smem_u32(const void* p) {
    uint32_t a;
    asm("{ .reg .u64 t; cvta.to.shared.u64 t, %1; cvt.u32.u64 %0, t; }"
        : "=r"(a) : "l"(p));
    return a;
}
__device__ __forceinline__ void cpa16(uint32_t d, const void* s) {
    asm volatile("cp.async.cg.shared.global [%0], [%1], 16;" :: "r"(d), "l"(s));
}
__device__ __forceinline__ void ldsm_x4(uint32_t* r, uint32_t a) {
    asm volatile("ldmatrix.sync.aligned.m8n8.x4.shared.b16 {%0,%1,%2,%3}, [%4];"
                 : "=r"(r[0]), "=r"(r[1]), "=r"(r[2]), "=r"(r[3]) : "r"(a));
}
#define MMA_BF16(acc, a, b) \
    asm volatile("mma.sync.aligned.m16n8k16.row.col.f32.bf16.bf16.f32 " \
        "{%0,%1,%2,%3}, {%4,%5,%6,%7}, {%8,%9}, {%0,%1,%2,%3};" \
        : "+f"((acc)[0]), "+f"((acc)[1]), "+f"((acc)[2]), "+f"((acc)[3]) \
        : "r"((a)[0]), "r"((a)[1]), "r"((a)[2]), "r"((a)[3]), \
          "r"((b)[0]), "r"((b)[1]))

// ---------------- packed f32x2 helpers (attention) ------------------------
__device__ __forceinline__ ull pk2(float x, float y) {
    ull r; asm("mov.b64 %0, {%1, %2};" : "=l"(r) : "f"(x), "f"(y)); return r;
}
__device__ __forceinline__ void upk2(ull v, float &x, float &y) {
    asm("mov.b64 {%0, %1}, %2;" : "=f"(x), "=f"(y) : "l"(v));
}
__device__ __forceinline__ ull ffma2(ull a, ull b, ull c) {
    ull d; asm("fma.rn.f32x2 %0, %1, %2, %3;" : "=l"(d) : "l"(a), "l"(b), "l"(c)); return d;
}
__device__ __forceinline__ ull fmul2(ull a, ull b) {
    ull d; asm("mul.rn.f32x2 %0, %1, %2;" : "=l"(d) : "l"(a), "l"(b)); return d;
}

// ---------------- fp32 -> bf16 hi/lo conversion ---------------------------
__global__ void __launch_bounds__(512)
cvt_kernel(const float* __restrict__ x, __nv_bfloat16* __restrict__ hi,
           __nv_bfloat16* __restrict__ lo, int n4)
{
    int i = blockIdx.x * blockDim.x + threadIdx.x;
    int stride = gridDim.x * blockDim.x;
    for (; i < n4; i += stride) {
        float4 v = ((const float4*)x)[i];
        __nv_bfloat16 h0 = __float2bfloat16(v.x);
        __nv_bfloat16 h1 = __float2bfloat16(v.y);
        __nv_bfloat16 h2 = __float2bfloat16(v.z);
        __nv_bfloat16 h3 = __float2bfloat16(v.w);
        __nv_bfloat16 l0 = __float2bfloat16(v.x - __bfloat162float(h0));
        __nv_bfloat16 l1 = __float2bfloat16(v.y - __bfloat162float(h1));
        __nv_bfloat16 l2 = __float2bfloat16(v.z - __bfloat162float(h2));
        __nv_bfloat16 l3 = __float2bfloat16(v.w - __bfloat162float(h3));
        __nv_bfloat162* H = (__nv_bfloat162*)hi;
        __nv_bfloat162* L = (__nv_bfloat162*)lo;
        H[2 * i]     = __nv_bfloat162(h0, h1);
        H[2 * i + 1] = __nv_bfloat162(h2, h3);
        L[2 * i]     = __nv_bfloat162(l0, l1);
        L[2 * i + 1] = __nv_bfloat162(l2, l3);
    }
}

// ---------------- mma.sync projection GEMM --------------------------------
// out = (X @ W^T + bias) * scale via split-bf16 3-MMA.
// X(hi/lo): [8192,1024] bf16, W(hi/lo): [1024,1024] bf16 ([n][k] = "col" B).
#define KC          64
#define NCHUNKS     (D_MODEL / KC)
#define RA_H        0
#define RA_L        16384
#define RB_H        32768
#define RB_L        49152
#define STAGE_BYTES 65536
#define PROJ_SMEM   (2 * STAGE_BYTES)

template <bool TOHEADS>
__global__ void __launch_bounds__(256)
mma_proj(const __nv_bfloat16* __restrict__ Xhi, const __nv_bfloat16* __restrict__ Xlo,
         const __nv_bfloat16* __restrict__ Whi, const __nv_bfloat16* __restrict__ Wlo,
         const float* __restrict__ bias, float* __restrict__ out, float scale)
{
    extern __shared__ __align__(128) char smem[];
    const uint32_t dyn0 = smem_u32(smem);

    const int tid = threadIdx.x;
    const int wid = tid >> 5, lane = tid & 31;
    const int m0 = blockIdx.y << 7, n0 = blockIdx.x << 7;
    const int wm = (wid & 1) << 6, wn = (wid >> 1) << 5;

    // per-thread gmem source offsets for the loader (16B granules)
    const int lrow = tid >> 3;        // 0..31 (row step 32 over j)
    const int lc16 = tid & 7;         // 16B granule within 128B row

    float acc[4][4][4];
#pragma unroll
    for (int i = 0; i < 4; ++i)
#pragma unroll
        for (int j = 0; j < 4; ++j)
#pragma unroll
            for (int q = 0; q < 4; ++q) acc[i][j][q] = 0.f;

    auto load_stage = [&](int stage, int kc) {
        const uint32_t sb = dyn0 + stage * STAGE_BYTES;
        const int kof = kc * KC + lc16 * 8;
#pragma unroll
        for (int j = 0; j < 4; ++j) {
            const int row = lrow + j * 32;
            const uint32_t soff = (row << 7) + ((lc16 ^ (row & 7)) << 4);
            const size_t ga = (size_t)(m0 + row) * D_MODEL + kof;
            const size_t gb = (size_t)(n0 + row) * D_MODEL + kof;
            cpa16(sb + RA_H + soff, Xhi + ga);
            cpa16(sb + RA_L + soff, Xlo + ga);
            cpa16(sb + RB_H + soff, Whi + gb);
            cpa16(sb + RB_L + soff, Wlo + gb);
        }
        asm volatile("cp.async.commit_group;" ::: "memory");
    };

    load_stage(0, 0);
    load_stage(1, 1);

    for (int kc = 0; kc < NCHUNKS; ++kc) {
        const int s = kc & 1;
        if (kc < NCHUNKS - 2)
            asm volatile("cp.async.wait_group 1;" ::: "memory");
        else
            asm volatile("cp.async.wait_group 0;" ::: "memory");
        __syncthreads();

        const uint32_t sb = dyn0 + s * STAGE_BYTES;
#pragma unroll
        for (int k16 = 0; k16 < 4; ++k16) {
            uint32_t ah[4][4], al[4][4], bh[2][4], bl[2][4];
#pragma unroll
            for (int am = 0; am < 4; ++am) {
                const int rowA = wm + am * 16 + (lane & 15);
                const int g = k16 * 2 + (lane >> 4);
                const uint32_t off = (rowA << 7) + ((g ^ (rowA & 7)) << 4);
                ldsm_x4(ah[am], sb + RA_H + off);
                ldsm_x4(al[am], sb + RA_L + off);
            }
#pragma unroll
            for (int p = 0; p < 2; ++p) {
                const int rowB = wn + p * 16 + ((lane >> 4) << 3) + (lane & 7);
                const int g = k16 * 2 + ((lane >> 3) & 1);
                const uint32_t off = (rowB << 7) + ((g ^ (rowB & 7)) << 4);
                ldsm_x4(bh[p], sb + RB_H + off);
                ldsm_x4(bl[p], sb + RB_L + off);
            }
#pragma unroll
            for (int am = 0; am < 4; ++am)
#pragma unroll
                for (int an = 0; an < 4; ++an) {
                    uint32_t* B0 = &bh[an >> 1][(an & 1) * 2];
                    uint32_t* BL = &bl[an >> 1][(an & 1) * 2];
                    MMA_BF16(acc[am][an], ah[am], B0);
                    MMA_BF16(acc[am][an], ah[am], BL);
                    MMA_BF16(acc[am][an], al[am], B0);
                }
        }
        __syncthreads();
        if (kc + 2 < NCHUNKS) load_stage(s, kc + 2);
    }

    // epilogue: bias + scale, fused head-layout store
#pragma unroll
    for (int am = 0; am < 4; ++am) {
#pragma unroll
        for (int an = 0; an < 4; ++an) {
            const int m = m0 + wm + am * 16 + (lane >> 2);
            const int c = n0 + wn + an * 8 + ((lane & 3) << 1);
            const float2 bv = *(const float2*)&bias[c];
#pragma unroll
            for (int h2 = 0; h2 < 2; ++h2) {
                const int row = m + h2 * 8;
                float2 o;
                o.x = (acc[am][an][2 * h2]     + bv.x) * scale;
                o.y = (acc[am][an][2 * h2 + 1] + bv.y) * scale;
                float* p;
                if (TOHEADS) {
                    const int b = row >> 11, srow = row & (SEQ - 1);
                    const int hh = c >> 6, dh = c & 63;
                    p = out + (((size_t)(b * NHEAD + hh) * SEQ + srow) * HEAD_DIM + dh);
                } else {
                    p = out + (size_t)row * D_MODEL + c;
                }
                *(float2*)p = o;
            }
        }
    }
}

// ---------------- causal flash attention (fp32x2, unchanged) --------------
__global__ void __launch_bounds__(256, 2)
attn_kernel(const float* __restrict__ Q, const float* __restrict__ K,
            const float* __restrict__ V, float* __restrict__ ctx)
{
    __shared__ __align__(16) float Qt[64 * 64];
    __shared__ __align__(16) float Ks[64 * 64];
    __shared__ __align__(16) float Vs[64 * 64];

    const int tid = threadIdx.x;
    const int tm = tid >> 4, tn = tid & 15;
    const int qt = blockIdx.x, bh = blockIdx.y;
    const size_t base = (size_t)bh * SEQ * HEAD_DIM;

    const float* Qg = Q + base + (size_t)qt * 64 * 64;
    for (int idx = tid; idx < 4096; idx += 256) {
        int r = idx >> 6, kk = idx & 63;
        Qt[kk * 64 + r] = Qg[idx];
    }

    float m_i[4], l_i[4];
    ull o2[4][2];
#pragma unroll
    for (int i = 0; i < 4; ++i) {
        m_i[i] = -1e30f; l_i[i] = 0.f; o2[i][0] = 0ull; o2[i][1] = 0ull;
    }
    int bbase[4];
#pragma unroll
    for (int j = 0; j < 4; ++j) bbase[j] = ((tn << 2) + j) << 6;
    const int sw = tn << 2;

    for (int kt = 0; kt <= qt; ++kt) {
        __syncthreads();
        const float4* Kg4 = (const float4*)(K + base + (size_t)kt * 64 * 64);
        const float4* Vg4 = (const float4*)(V + base + (size_t)kt * 64 * 64);
#pragma unroll
        for (int u = 0; u < 4; ++u) {
            int t = tid + u * 256;
            int c = t >> 4, q4 = t & 15;
            int kkp = ((q4 << 2) + ((c >> 2) << 2)) & 63;
            ((float4*)Ks)[(c << 4) + (kkp >> 2)] = Kg4[t];
            ((float4*)Vs)[t] = Vg4[t];
        }
        __syncthreads();

        ull acc[4][2] = {0ull, 0ull, 0ull, 0ull, 0ull, 0ull, 0ull, 0ull};
#pragma unroll 4
        for (int kk = 0; kk < 64; ++kk) {
            const ull* qa = (const ull*)&Qt[kk * 64 + (tm << 2)];
            ull a0 = qa[0], a1 = qa[1];
            int kks = (kk + sw) & 63;
#pragma unroll
            for (int j = 0; j < 4; ++j) {
                float bscal = Ks[bbase[j] + kks];
                ull bb = pk2(bscal, bscal);
                acc[j][0] = ffma2(bb, a0, acc[j][0]);
                acc[j][1] = ffma2(bb, a1, acc[j][1]);
            }
        }

        float s[4][4];
#pragma unroll
        for (int j = 0; j < 4; ++j) {
            upk2(acc[j][0], s[0][j], s[1][j]);
            upk2(acc[j][1], s[2][j], s[3][j]);
        }
        if (kt == qt) {
#pragma unroll
            for (int i = 0; i < 4; ++i)
#pragma unroll
                for (int j = 0; j < 4; ++j)
                    if ((tn << 2) + j > (tm << 2) + i) s[i][j] = -1e30f;
        }

        float alpha[4];
#pragma unroll
        for (int i = 0; i < 4; ++i) {
            float mx = fmaxf(fmaxf(s[i][0], s[i][1]), fmaxf(s[i][2], s[i][3]));
#pragma unroll
            for (int off = 1; off < 16; off <<= 1)
                mx = fmaxf(mx, __shfl_xor_sync(0xffffffffu, mx, off));
            float mn = fmaxf(m_i[i], mx);
            float al = __expf(m_i[i] - mn);
            m_i[i] = mn;
            float sum = 0.f;
#pragma unroll
            for (int j = 0; j < 4; ++j) {
                float pv = __expf(s[i][j] - mn);
                s[i][j] = pv;
                sum += pv;
            }
#pragma unroll
            for (int off = 1; off < 16; off <<= 1)
                sum += __shfl_xor_sync(0xffffffffu, sum, off);
            l_i[i] = l_i[i] * al + sum;
            alpha[i] = al;
        }

        __syncthreads();
#pragma unroll
        for (int i = 0; i < 4; ++i) {
            ull aa = pk2(alpha[i], alpha[i]);
            o2[i][0] = fmul2(o2[i][0], aa);
            o2[i][1] = fmul2(o2[i][1], aa);
#pragma unroll
            for (int j = 0; j < 4; ++j)
                Ks[((tm << 2) + i) * 64 + (tn << 2) + j] = s[i][j];
        }
        __syncthreads();

#pragma unroll 4
        for (int c = 0; c < 64; ++c) {
            const ull* vp = (const ull*)&Vs[c * 64 + (tn << 2)];
            ull v0 = vp[0], v1 = vp[1];
#pragma unroll
            for (int i = 0; i < 4; ++i) {
                float pv = Ks[((tm << 2) + i) * 64 + c];
                ull pp = pk2(pv, pv);
                o2[i][0] = ffma2(pp, v0, o2[i][0]);
                o2[i][1] = ffma2(pp, v1, o2[i][1]);
            }
        }
    }

    const int b = bh >> 4, h = bh & 15;
#pragma unroll
    for (int i = 0; i < 4; ++i) {
        float inv = 1.0f / l_i[i];
        float q0, q1, q2, q3;
        upk2(o2[i][0], q0, q1);
        upk2(o2[i][1], q2, q3);
        int row = qt * 64 + (tm << 2) + i;
        float* p = ctx + ((size_t)b * SEQ + row) * D_MODEL + h * 64 + (tn << 2);
        *(float4*)p = make_float4(q0 * inv, q1 * inv, q2 * inv, q3 * inv);
    }
}

// ---------------- launcher -------------------------------------------------
extern "C" void kernel_launch(void* const* d_in, const int* in_sizes, int n_in,
                              void* d_out, int out_size)
{
    const float* query = (const float*)d_in[0];
    const float* key_  = (const float*)d_in[1];
    const float* value = (const float*)d_in[2];
    const float* Wq = (const float*)d_in[4];
    const float* bq = (const float*)d_in[5];
    const float* Wk = (const float*)d_in[6];
    const float* bk = (const float*)d_in[7];
    const float* Wv = (const float*)d_in[8];
    const float* bv = (const float*)d_in[9];
    const float* Wo = (const float*)d_in[10];
    const float* bo = (const float*)d_in[11];
    float* out = (float*)d_out;

    float *pQ, *pK, *pV, *pC;
    __nv_bfloat16 *pXhi, *pXlo, *pWhi, *pWlo;
    cudaGetSymbolAddress((void**)&pQ, g_Q);
    cudaGetSymbolAddress((void**)&pK, g_K);
    cudaGetSymbolAddress((void**)&pV, g_V);
    cudaGetSymbolAddress((void**)&pC, g_ctx);
    cudaGetSymbolAddress((void**)&pXhi, g_Xhi);
    cudaGetSymbolAddress((void**)&pXlo, g_Xlo);
    cudaGetSymbolAddress((void**)&pWhi, g_Whi);
    cudaGetSymbolAddress((void**)&pWlo, g_Wlo);

    cudaFuncSetAttribute(mma_proj<true>,  cudaFuncAttributeMaxDynamicSharedMemorySize, PROJ_SMEM);
    cudaFuncSetAttribute(mma_proj<false>, cudaFuncAttributeMaxDynamicSharedMemorySize, PROJ_SMEM);

    const int NX4 = (M_TOT * D_MODEL) / 4;
    const int NW4 = (D_MODEL * D_MODEL) / 4;
    dim3 gp(D_MODEL / 128, M_TOT / 128);   // (8, 64)
    dim3 ga(SEQ / 64, BATCH * NHEAD);      // (32, 64)

    // Q projection (softmax scale folded into output scale)
    cvt_kernel<<<2048, 512>>>(query, pXhi, pXlo, NX4);
    cvt_kernel<<<512, 512>>>(Wq, pWhi, pWlo, NW4);
    mma_proj<true><<<gp, 256, PROJ_SMEM>>>(pXhi, pXlo, pWhi, pWlo, bq, pQ, 0.125f);
    // K projection
    cvt_kernel<<<2048, 512>>>(key_, pXhi, pXlo, NX4);
    cvt_kernel<<<512, 512>>>(Wk, pWhi, pWlo, NW4);
    mma_proj<true><<<gp, 256, PROJ_SMEM>>>(pXhi, pXlo, pWhi, pWlo, bk, pK, 1.0f);
    // V projection
    cvt_kernel<<<2048, 512>>>(value, pXhi, pXlo, NX4);
    cvt_kernel<<<512, 512>>>(Wv, pWhi, pWlo, NW4);
    mma_proj<true><<<gp, 256, PROJ_SMEM>>>(pXhi, pXlo, pWhi, pWlo, bv, pV, 1.0f);
    // attention
    attn_kernel<<<ga, 256>>>(pQ, pK, pV, pC);
    // output projection
    cvt_kernel<<<2048, 512>>>(pC, pXhi, pXlo, NX4);
    cvt_kernel<<<512, 512>>>(Wo, pWhi, pWlo, NW4);
    mma_proj<false><<<gp, 256, PROJ_SMEM>>>(pXhi, pXlo, pWhi, pWlo, bo, out, 1.0f);
}

// round 5
// speedup vs baseline: 3.1479x; 1.8782x over previous
#include <cuda_runtime.h>
#include <cuda_bf16.h>
#include <cstdint>

#define D_MODEL 1024
#define NHEAD   16
#define HEAD_DIM 64
#define BATCH   4
#define SEQ     2048
#define M_TOT   (BATCH * SEQ)

// ---------------- scratch (static device memory; no allocations) ----------
__device__ __nv_bfloat16 g_Qh[BATCH * NHEAD * SEQ * HEAD_DIM];
__device__ __nv_bfloat16 g_Ql[BATCH * NHEAD * SEQ * HEAD_DIM];
__device__ __nv_bfloat16 g_Kh[BATCH * NHEAD * SEQ * HEAD_DIM];
__device__ __nv_bfloat16 g_Kl[BATCH * NHEAD * SEQ * HEAD_DIM];
__device__ __nv_bfloat16 g_Vh[BATCH * NHEAD * SEQ * HEAD_DIM];
__device__ __nv_bfloat16 g_Vl[BATCH * NHEAD * SEQ * HEAD_DIM];
__device__ __nv_bfloat16 g_Xhi[M_TOT * D_MODEL];
__device__ __nv_bfloat16 g_Xlo[M_TOT * D_MODEL];
__device__ __nv_bfloat16 g_Whi[D_MODEL * D_MODEL];
__device__ __nv_bfloat16 g_Wlo[D_MODEL * D_MODEL];

// ---------------- small helpers -------------------------------------------
__device__ __forceinline__ uint32_t smem_u32(const void* p) {
    uint32_t a;
    asm("{ .reg .u64 t; cvta.to.shared.u64 t, %1; cvt.u32.u64 %0, t; }"
        : "=r"(a) : "l"(p));
    return a;
}
__device__ __forceinline__ void cpa16(uint32_t d, const void* s) {
    asm volatile("cp.async.cg.shared.global [%0], [%1], 16;" :: "r"(d), "l"(s));
}
__device__ __forceinline__ void ldsm_x4(uint32_t* r, uint32_t a) {
    asm volatile("ldmatrix.sync.aligned.m8n8.x4.shared.b16 {%0,%1,%2,%3}, [%4];"
                 : "=r"(r[0]), "=r"(r[1]), "=r"(r[2]), "=r"(r[3]) : "r"(a));
}
__device__ __forceinline__ void ldsm_x4_t(uint32_t* r, uint32_t a) {
    asm volatile("ldmatrix.sync.aligned.m8n8.x4.trans.shared.b16 {%0,%1,%2,%3}, [%4];"
                 : "=r"(r[0]), "=r"(r[1]), "=r"(r[2]), "=r"(r[3]) : "r"(a));
}
#define MMA_BF16(acc, a, b) \
    asm volatile("mma.sync.aligned.m16n8k16.row.col.f32.bf16.bf16.f32 " \
        "{%0,%1,%2,%3}, {%4,%5,%6,%7}, {%8,%9}, {%0,%1,%2,%3};" \
        : "+f"((acc)[0]), "+f"((acc)[1]), "+f"((acc)[2]), "+f"((acc)[3]) \
        : "r"((a)[0]), "r"((a)[1]), "r"((a)[2]), "r"((a)[3]), \
          "r"((b)[0]), "r"((b)[1]))

__device__ __forceinline__ uint32_t pkbf(float lo, float hi) {
    uint32_t r; asm("cvt.rn.bf16x2.f32 %0, %1, %2;" : "=r"(r) : "f"(hi), "f"(lo)); return r;
}
__device__ __forceinline__ void split2(float x, float y, uint32_t& h, uint32_t& l) {
    h = pkbf(x, y);
    float fx = __int_as_float(h << 16);
    float fy = __int_as_float(h & 0xffff0000u);
    l = pkbf(x - fx, y - fy);
}
__device__ __forceinline__ float ex2(float x) {
    float y; asm("ex2.approx.ftz.f32 %0, %1;" : "=f"(y) : "f"(x)); return y;
}

// ---------------- fp32 -> bf16 hi/lo conversion ---------------------------
__global__ void __launch_bounds__(512)
cvt_kernel(const float* __restrict__ x, __nv_bfloat16* __restrict__ hi,
           __nv_bfloat16* __restrict__ lo, int n4)
{
    int i = blockIdx.x * blockDim.x + threadIdx.x;
    int stride = gridDim.x * blockDim.x;
    for (; i < n4; i += stride) {
        float4 v = ((const float4*)x)[i];
        uint32_t h0, l0, h1, l1;
        split2(v.x, v.y, h0, l0);
        split2(v.z, v.w, h1, l1);
        ((uint32_t*)hi)[2 * i] = h0;  ((uint32_t*)hi)[2 * i + 1] = h1;
        ((uint32_t*)lo)[2 * i] = l0;  ((uint32_t*)lo)[2 * i + 1] = l1;
    }
}

// ---------------- mma.sync projection GEMM --------------------------------
// out = (X @ W^T + bias) * scale via split-bf16 3-MMA.
// MODE 0: fp32 out [m][1024]. MODE 1: bf16 hi/lo, head layout [b,h,s,dh].
#define KC          64
#define NCHUNKS     (D_MODEL / KC)
#define RA_H        0
#define RA_L        16384
#define RB_H        32768
#define RB_L        49152
#define STAGE_BYTES 65536
#define PROJ_SMEM   (2 * STAGE_BYTES)

template <int MODE>
__global__ void __launch_bounds__(256)
mma_proj(const __nv_bfloat16* __restrict__ Xhi, const __nv_bfloat16* __restrict__ Xlo,
         const __nv_bfloat16* __restrict__ Whi, const __nv_bfloat16* __restrict__ Wlo,
         const float* __restrict__ bias, float* __restrict__ out,
         __nv_bfloat16* __restrict__ oh, __nv_bfloat16* __restrict__ ol, float scale)
{
    extern __shared__ __align__(128) char smem[];
    const uint32_t dyn0 = smem_u32(smem);

    const int tid = threadIdx.x;
    const int wid = tid >> 5, lane = tid & 31;
    const int m0 = blockIdx.y << 7, n0 = blockIdx.x << 7;
    const int wm = (wid & 1) << 6, wn = (wid >> 1) << 5;

    const int lrow = tid >> 3;
    const int lc16 = tid & 7;

    float acc[4][4][4];
#pragma unroll
    for (int i = 0; i < 4; ++i)
#pragma unroll
        for (int j = 0; j < 4; ++j)
#pragma unroll
            for (int q = 0; q < 4; ++q) acc[i][j][q] = 0.f;

    auto load_stage = [&](int stage, int kc) {
        const uint32_t sb = dyn0 + stage * STAGE_BYTES;
        const int kof = kc * KC + lc16 * 8;
#pragma unroll
        for (int j = 0; j < 4; ++j) {
            const int row = lrow + j * 32;
            const uint32_t soff = (row << 7) + ((lc16 ^ (row & 7)) << 4);
            const size_t ga = (size_t)(m0 + row) * D_MODEL + kof;
            const size_t gb = (size_t)(n0 + row) * D_MODEL + kof;
            cpa16(sb + RA_H + soff, Xhi + ga);
            cpa16(sb + RA_L + soff, Xlo + ga);
            cpa16(sb + RB_H + soff, Whi + gb);
            cpa16(sb + RB_L + soff, Wlo + gb);
        }
        asm volatile("cp.async.commit_group;" ::: "memory");
    };

    load_stage(0, 0);
    load_stage(1, 1);

    for (int kc = 0; kc < NCHUNKS; ++kc) {
        const int s = kc & 1;
        if (kc < NCHUNKS - 2)
            asm volatile("cp.async.wait_group 1;" ::: "memory");
        else
            asm volatile("cp.async.wait_group 0;" ::: "memory");
        __syncthreads();

        const uint32_t sb = dyn0 + s * STAGE_BYTES;
#pragma unroll
        for (int k16 = 0; k16 < 4; ++k16) {
            uint32_t ah[4][4], al[4][4], bh[2][4], bl[2][4];
#pragma unroll
            for (int am = 0; am < 4; ++am) {
                const int rowA = wm + am * 16 + (lane & 15);
                const int g = k16 * 2 + (lane >> 4);
                const uint32_t off = (rowA << 7) + ((g ^ (rowA & 7)) << 4);
                ldsm_x4(ah[am], sb + RA_H + off);
                ldsm_x4(al[am], sb + RA_L + off);
            }
#pragma unroll
            for (int p = 0; p < 2; ++p) {
                const int rowB = wn + p * 16 + ((lane >> 4) << 3) + (lane & 7);
                const int g = k16 * 2 + ((lane >> 3) & 1);
                const uint32_t off = (rowB << 7) + ((g ^ (rowB & 7)) << 4);
                ldsm_x4(bh[p], sb + RB_H + off);
                ldsm_x4(bl[p], sb + RB_L + off);
            }
#pragma unroll
            for (int am = 0; am < 4; ++am)
#pragma unroll
                for (int an = 0; an < 4; ++an) {
                    uint32_t* B0 = &bh[an >> 1][(an & 1) * 2];
                    uint32_t* BL = &bl[an >> 1][(an & 1) * 2];
                    MMA_BF16(acc[am][an], ah[am], B0);
                    MMA_BF16(acc[am][an], ah[am], BL);
                    MMA_BF16(acc[am][an], al[am], B0);
                }
        }
        __syncthreads();
        if (kc + 2 < NCHUNKS) load_stage(s, kc + 2);
    }

#pragma unroll
    for (int am = 0; am < 4; ++am) {
#pragma unroll
        for (int an = 0; an < 4; ++an) {
            const int m = m0 + wm + am * 16 + (lane >> 2);
            const int c = n0 + wn + an * 8 + ((lane & 3) << 1);
            const float2 bv = *(const float2*)&bias[c];
#pragma unroll
            for (int h2 = 0; h2 < 2; ++h2) {
                const int row = m + h2 * 8;
                float ox = (acc[am][an][2 * h2]     + bv.x) * scale;
                float oy = (acc[am][an][2 * h2 + 1] + bv.y) * scale;
                if (MODE == 1) {
                    const int b = row >> 11, srow = row & (SEQ - 1);
                    const int hh = c >> 6, dh = c & 63;
                    const size_t idx = (((size_t)(b * NHEAD + hh) * SEQ + srow) * HEAD_DIM + dh);
                    uint32_t h, l;
                    split2(ox, oy, h, l);
                    *(uint32_t*)(oh + idx) = h;
                    *(uint32_t*)(ol + idx) = l;
                } else {
                    *(float2*)(out + (size_t)row * D_MODEL + c) = make_float2(ox, oy);
                }
            }
        }
    }
}

// ---------------- mma.sync causal flash attention -------------------------
// Q/K/V bf16 hi/lo [bh][s][64] (Q pre-scaled by log2(e)/8). Out: ctx hi/lo bf16
// [B*S][1024] (head-interleaved columns), feeding the output projection.
#define AT_SMEM 65536

__global__ void __launch_bounds__(256)
attn_mma(const __nv_bfloat16* __restrict__ Qh, const __nv_bfloat16* __restrict__ Ql,
         const __nv_bfloat16* __restrict__ Kh, const __nv_bfloat16* __restrict__ Kl,
         const __nv_bfloat16* __restrict__ Vh, const __nv_bfloat16* __restrict__ Vl,
         __nv_bfloat16* __restrict__ Ch, __nv_bfloat16* __restrict__ Cl)
{
    extern __shared__ __align__(128) char smem[];
    const uint32_t dyn0 = smem_u32(smem);
    const int tid = threadIdx.x, wid = tid >> 5, lane = tid & 31;
    const int bx = (int)gridDim.x - 1 - (int)blockIdx.x;   // big tiles first
    const int bh = blockIdx.y;
    const int q0 = bx << 7;
    const size_t base = (size_t)bh * SEQ * HEAD_DIM;

    // ---- stage Q tile (128x64 hi/lo) through stage-0 smem, extract A frags
    {
        const int r = tid >> 3, g = tid & 7;
#pragma unroll
        for (int j = 0; j < 4; ++j) {
            const int row = r + j * 32;
            const uint32_t soff = (row << 7) + ((g ^ (row & 7)) << 4);
            const size_t go = base + (size_t)(q0 + row) * HEAD_DIM + g * 8;
            cpa16(dyn0 + soff, Qh + go);
            cpa16(dyn0 + 16384 + soff, Ql + go);
        }
        asm volatile("cp.async.commit_group;" ::: "memory");
        asm volatile("cp.async.wait_group 0;" ::: "memory");
        __syncthreads();
    }
    uint32_t qh[4][4], ql[4][4];
#pragma unroll
    for (int k16 = 0; k16 < 4; ++k16) {
        const int rowA = wid * 16 + (lane & 15);
        const int g = k16 * 2 + (lane >> 4);
        const uint32_t off = (rowA << 7) + ((g ^ (rowA & 7)) << 4);
        ldsm_x4(qh[k16], dyn0 + off);
        ldsm_x4(ql[k16], dyn0 + 16384 + off);
    }
    __syncthreads();   // Q frags extracted before K/V loads overwrite stage 0

    float O[8][4];
#pragma unroll
    for (int j = 0; j < 8; ++j)
#pragma unroll
        for (int q = 0; q < 4; ++q) O[j][q] = 0.f;
    float m0 = -1e30f, m1 = -1e30f, l0 = 0.f, l1 = 0.f;

    const int ktend = 2 * bx + 2;
    auto load_kv = [&](int stage, int kt) {
        const uint32_t sb = dyn0 + stage * 32768;
        const int r = tid >> 3, g = tid & 7;
#pragma unroll
        for (int j = 0; j < 2; ++j) {
            const int row = r + j * 32;
            const uint32_t soff = (row << 7) + ((g ^ (row & 7)) << 4);
            const size_t go = base + (size_t)(kt * 64 + row) * HEAD_DIM + g * 8;
            cpa16(sb + soff,         Kh + go);
            cpa16(sb +  8192 + soff, Kl + go);
            cpa16(sb + 16384 + soff, Vh + go);
            cpa16(sb + 24576 + soff, Vl + go);
        }
        asm volatile("cp.async.commit_group;" ::: "memory");
    };
    load_kv(0, 0);
    load_kv(1, 1);   // ktend >= 2 always

    const int rrow = lane >> 2;
    const int ccol = (lane & 3) << 1;

    for (int kt = 0; kt < ktend; ++kt) {
        const int s = kt & 1;
        if (kt < ktend - 2)
            asm volatile("cp.async.wait_group 1;" ::: "memory");
        else
            asm volatile("cp.async.wait_group 0;" ::: "memory");
        __syncthreads();
        const uint32_t sb = dyn0 + s * 32768;

        const bool active = (kt * 64 <= q0 + wid * 16 + 15);
        if (active) {
            // ---- S = Q K^T (3-MMA split)
            float S[8][4];
#pragma unroll
            for (int j = 0; j < 8; ++j)
#pragma unroll
                for (int q = 0; q < 4; ++q) S[j][q] = 0.f;
#pragma unroll
            for (int p = 0; p < 4; ++p) {
#pragma unroll
                for (int k16 = 0; k16 < 4; ++k16) {
                    uint32_t bkh[4], bkl[4];
                    const int rowB = p * 16 + ((lane >> 4) << 3) + (lane & 7);
                    const int g = k16 * 2 + ((lane >> 3) & 1);
                    const uint32_t off = (rowB << 7) + ((g ^ (rowB & 7)) << 4);
                    ldsm_x4(bkh, sb + off);
                    ldsm_x4(bkl, sb + 8192 + off);
                    MMA_BF16(S[2 * p],     qh[k16], &bkh[0]);
                    MMA_BF16(S[2 * p],     qh[k16], &bkl[0]);
                    MMA_BF16(S[2 * p],     ql[k16], &bkh[0]);
                    MMA_BF16(S[2 * p + 1], qh[k16], &bkh[2]);
                    MMA_BF16(S[2 * p + 1], qh[k16], &bkl[2]);
                    MMA_BF16(S[2 * p + 1], ql[k16], &bkh[2]);
                }
            }

            // ---- causal mask (only on the 2 diagonal chunks)
            if (kt >= 2 * bx) {
                const int r0g = q0 + wid * 16 + rrow;
#pragma unroll
                for (int jt = 0; jt < 8; ++jt) {
                    const int cg = kt * 64 + jt * 8 + ccol;
                    if (cg     > r0g)     S[jt][0] = -1e30f;
                    if (cg + 1 > r0g)     S[jt][1] = -1e30f;
                    if (cg     > r0g + 8) S[jt][2] = -1e30f;
                    if (cg + 1 > r0g + 8) S[jt][3] = -1e30f;
                }
            }

            // ---- online softmax (base-2; log2e folded into Q scale)
            float mx0 = -1e30f, mx1 = -1e30f;
#pragma unroll
            for (int jt = 0; jt < 8; ++jt) {
                mx0 = fmaxf(mx0, fmaxf(S[jt][0], S[jt][1]));
                mx1 = fmaxf(mx1, fmaxf(S[jt][2], S[jt][3]));
            }
            mx0 = fmaxf(mx0, __shfl_xor_sync(0xffffffffu, mx0, 1));
            mx0 = fmaxf(mx0, __shfl_xor_sync(0xffffffffu, mx0, 2));
            mx1 = fmaxf(mx1, __shfl_xor_sync(0xffffffffu, mx1, 1));
            mx1 = fmaxf(mx1, __shfl_xor_sync(0xffffffffu, mx1, 2));
            const float nm0 = fmaxf(m0, mx0), nm1 = fmaxf(m1, mx1);
            const float a0 = ex2(m0 - nm0), a1 = ex2(m1 - nm1);
            m0 = nm0; m1 = nm1;
            float s0 = 0.f, s1 = 0.f;
#pragma unroll
            for (int jt = 0; jt < 8; ++jt) {
                S[jt][0] = ex2(S[jt][0] - m0);
                S[jt][1] = ex2(S[jt][1] - m0);
                S[jt][2] = ex2(S[jt][2] - m1);
                S[jt][3] = ex2(S[jt][3] - m1);
                s0 += S[jt][0] + S[jt][1];
                s1 += S[jt][2] + S[jt][3];
            }
            s0 += __shfl_xor_sync(0xffffffffu, s0, 1);
            s0 += __shfl_xor_sync(0xffffffffu, s0, 2);
            s1 += __shfl_xor_sync(0xffffffffu, s1, 1);
            s1 += __shfl_xor_sync(0xffffffffu, s1, 2);
            l0 = l0 * a0 + s0;
            l1 = l1 * a1 + s1;
#pragma unroll
            for (int jt = 0; jt < 8; ++jt) {
                O[jt][0] *= a0; O[jt][1] *= a0;
                O[jt][2] *= a1; O[jt][3] *= a1;
            }

            // ---- pack P into bf16 hi/lo A fragments
            uint32_t ph[4][4], pl[4][4];
#pragma unroll
            for (int kk = 0; kk < 4; ++kk) {
                split2(S[2 * kk][0],     S[2 * kk][1],     ph[kk][0], pl[kk][0]);
                split2(S[2 * kk][2],     S[2 * kk][3],     ph[kk][1], pl[kk][1]);
                split2(S[2 * kk + 1][0], S[2 * kk + 1][1], ph[kk][2], pl[kk][2]);
                split2(S[2 * kk + 1][2], S[2 * kk + 1][3], ph[kk][3], pl[kk][3]);
            }

            // ---- O += P V (3-MMA split, V^T via ldmatrix.trans)
#pragma unroll
            for (int p = 0; p < 4; ++p) {
#pragma unroll
                for (int kk = 0; kk < 4; ++kk) {
                    uint32_t vh[4], vl[4];
                    const int key = kk * 16 + ((lane >> 3) & 1) * 8 + (lane & 7);
                    const int nt = 2 * p + (lane >> 4);
                    const uint32_t off = (key << 7) + (((nt) ^ (key & 7)) << 4);
                    ldsm_x4_t(vh, sb + 16384 + off);
                    ldsm_x4_t(vl, sb + 24576 + off);
                    MMA_BF16(O[2 * p],     ph[kk], &vh[0]);
                    MMA_BF16(O[2 * p],     pl[kk], &vh[0]);
                    MMA_BF16(O[2 * p],     ph[kk], &vl[0]);
                    MMA_BF16(O[2 * p + 1], ph[kk], &vh[2]);
                    MMA_BF16(O[2 * p + 1], pl[kk], &vh[2]);
                    MMA_BF16(O[2 * p + 1], ph[kk], &vl[2]);
                }
            }
        }
        __syncthreads();
        if (kt + 2 < ktend) load_kv(s, kt + 2);
    }

    // ---- finalize: O/l, write ctx hi/lo bf16 straight into proj-A buffers
    const float inv0 = 1.f / l0, inv1 = 1.f / l1;
    const int b = bh >> 4, h = bh & 15;
    const int r0g = q0 + wid * 16 + rrow;
    const size_t mi0 = ((size_t)b * SEQ + r0g) * D_MODEL + h * 64;
    const size_t mi1 = ((size_t)b * SEQ + r0g + 8) * D_MODEL + h * 64;
#pragma unroll
    for (int jt = 0; jt < 8; ++jt) {
        const int c = jt * 8 + ccol;
        uint32_t hh, ll;
        split2(O[jt][0] * inv0, O[jt][1] * inv0, hh, ll);
        *(uint32_t*)(Ch + mi0 + c) = hh;
        *(uint32_t*)(Cl + mi0 + c) = ll;
        split2(O[jt][2] * inv1, O[jt][3] * inv1, hh, ll);
        *(uint32_t*)(Ch + mi1 + c) = hh;
        *(uint32_t*)(Cl + mi1 + c) = ll;
    }
}

// ---------------- launcher -------------------------------------------------
extern "C" void kernel_launch(void* const* d_in, const int* in_sizes, int n_in,
                              void* d_out, int out_size)
{
    const float* query = (const float*)d_in[0];
    const float* key_  = (const float*)d_in[1];
    const float* value = (const float*)d_in[2];
    const float* Wq = (const float*)d_in[4];
    const float* bq = (const float*)d_in[5];
    const float* Wk = (const float*)d_in[6];
    const float* bk = (const float*)d_in[7];
    const float* Wv = (const float*)d_in[8];
    const float* bv = (const float*)d_in[9];
    const float* Wo = (const float*)d_in[10];
    const float* bo = (const float*)d_in[11];
    float* out = (float*)d_out;

    __nv_bfloat16 *pQh, *pQl, *pKh, *pKl, *pVh, *pVl, *pXhi, *pXlo, *pWhi, *pWlo;
    cudaGetSymbolAddress((void**)&pQh, g_Qh);
    cudaGetSymbolAddress((void**)&pQl, g_Ql);
    cudaGetSymbolAddress((void**)&pKh, g_Kh);
    cudaGetSymbolAddress((void**)&pKl, g_Kl);
    cudaGetSymbolAddress((void**)&pVh, g_Vh);
    cudaGetSymbolAddress((void**)&pVl, g_Vl);
    cudaGetSymbolAddress((void**)&pXhi, g_Xhi);
    cudaGetSymbolAddress((void**)&pXlo, g_Xlo);
    cudaGetSymbolAddress((void**)&pWhi, g_Whi);
    cudaGetSymbolAddress((void**)&pWlo, g_Wlo);

    cudaFuncSetAttribute(mma_proj<0>, cudaFuncAttributeMaxDynamicSharedMemorySize, PROJ_SMEM);
    cudaFuncSetAttribute(mma_proj<1>, cudaFuncAttributeMaxDynamicSharedMemorySize, PROJ_SMEM);
    cudaFuncSetAttribute(attn_mma,    cudaFuncAttributeMaxDynamicSharedMemorySize, AT_SMEM);

    const int NX4 = (M_TOT * D_MODEL) / 4;
    const int NW4 = (D_MODEL * D_MODEL) / 4;
    dim3 gp(D_MODEL / 128, M_TOT / 128);   // (8, 64)
    dim3 ga(SEQ / 128, BATCH * NHEAD);     // (16, 64)
    const float qscale = 0.125f * 1.4426950408889634f;  // 1/sqrt(64) * log2(e)

    // Q projection
    cvt_kernel<<<2048, 512>>>(query, pXhi, pXlo, NX4);
    cvt_kernel<<<512, 512>>>(Wq, pWhi, pWlo, NW4);
    mma_proj<1><<<gp, 256, PROJ_SMEM>>>(pXhi, pXlo, pWhi, pWlo, bq, nullptr, pQh, pQl, qscale);
    // K projection
    cvt_kernel<<<2048, 512>>>(key_, pXhi, pXlo, NX4);
    cvt_kernel<<<512, 512>>>(Wk, pWhi, pWlo, NW4);
    mma_proj<1><<<gp, 256, PROJ_SMEM>>>(pXhi, pXlo, pWhi, pWlo, bk, nullptr, pKh, pKl, 1.0f);
    // V projection
    cvt_kernel<<<2048, 512>>>(value, pXhi, pXlo, NX4);
    cvt_kernel<<<512, 512>>>(Wv, pWhi, pWlo, NW4);
    mma_proj<1><<<gp, 256, PROJ_SMEM>>>(pXhi, pXlo, pWhi, pWlo, bv, nullptr, pVh, pVl, 1.0f);
    // attention -> ctx hi/lo (directly into out-proj A buffers)
    attn_mma<<<ga, 256, AT_SMEM>>>(pQh, pQl, pKh, pKl, pVh, pVl, pXhi, pXlo);
    // output projection
    cvt_kernel<<<512, 512>>>(Wo, pWhi, pWlo, NW4);
    mma_proj<0><<<gp, 256, PROJ_SMEM>>>(pXhi, pXlo, pWhi, pWlo, bo, out, nullptr, nullptr, 1.0f);
}

// round 7
// speedup vs baseline: 3.5566x; 1.1298x over previous
#include <cuda_runtime.h>
#include <cuda.h>
#include <cuda_bf16.h>
#include <cstdint>

#define D_MODEL 1024
#define NHEAD   16
#define HEAD_DIM 64
#define BATCH   4
#define SEQ     2048
#define M_TOT   (BATCH * SEQ)

// ---------------- scratch (static device memory; no allocations) ----------
__device__ __nv_bfloat16 g_Qh[BATCH * NHEAD * SEQ * HEAD_DIM];
__device__ __nv_bfloat16 g_Ql[BATCH * NHEAD * SEQ * HEAD_DIM];
__device__ __nv_bfloat16 g_Kh[BATCH * NHEAD * SEQ * HEAD_DIM];
__device__ __nv_bfloat16 g_Kl[BATCH * NHEAD * SEQ * HEAD_DIM];
__device__ __nv_bfloat16 g_Vh[BATCH * NHEAD * SEQ * HEAD_DIM];
__device__ __nv_bfloat16 g_Vl[BATCH * NHEAD * SEQ * HEAD_DIM];
__device__ __nv_bfloat16 g_Xhi[M_TOT * D_MODEL];
__device__ __nv_bfloat16 g_Xlo[M_TOT * D_MODEL];
__device__ __nv_bfloat16 g_Whi[D_MODEL * D_MODEL];
__device__ __nv_bfloat16 g_Wlo[D_MODEL * D_MODEL];

typedef unsigned long long ull;

// ---------------- PTX helpers ---------------------------------------------
__device__ __forceinline__ uint32_t smem_u32(const void* p) {
    uint32_t a;
    asm("{ .reg .u64 t; cvta.to.shared.u64 t, %1; cvt.u32.u64 %0, t; }"
        : "=r"(a) : "l"(p));
    return a;
}
__device__ __forceinline__ void ldsm_x4(uint32_t* r, uint32_t a) {
    asm volatile("ldmatrix.sync.aligned.m8n8.x4.shared.b16 {%0,%1,%2,%3}, [%4];"
                 : "=r"(r[0]), "=r"(r[1]), "=r"(r[2]), "=r"(r[3]) : "r"(a));
}
__device__ __forceinline__ void ldsm_x4_t(uint32_t* r, uint32_t a) {
    asm volatile("ldmatrix.sync.aligned.m8n8.x4.trans.shared.b16 {%0,%1,%2,%3}, [%4];"
                 : "=r"(r[0]), "=r"(r[1]), "=r"(r[2]), "=r"(r[3]) : "r"(a));
}
#define MMA_BF16(acc, a, b) \
    asm volatile("mma.sync.aligned.m16n8k16.row.col.f32.bf16.bf16.f32 " \
        "{%0,%1,%2,%3}, {%4,%5,%6,%7}, {%8,%9}, {%0,%1,%2,%3};" \
        : "+f"((acc)[0]), "+f"((acc)[1]), "+f"((acc)[2]), "+f"((acc)[3]) \
        : "r"((a)[0]), "r"((a)[1]), "r"((a)[2]), "r"((a)[3]), \
          "r"((b)[0]), "r"((b)[1]))

#define MBARRIER_INIT(addr, cnt) \
    asm volatile("mbarrier.init.shared.b64 [%0], %1;" :: "r"(addr), "r"(cnt) : "memory")
#define MBARRIER_EXPECT_TX(addr, bytes) \
    asm volatile("mbarrier.arrive.expect_tx.shared.b64 _, [%0], %1;" \
                 :: "r"(addr), "r"(bytes) : "memory")
#define MBARRIER_WAIT_PARITY(addr, parity) do { \
    uint32_t _m = (uint32_t)(addr); uint32_t _p = (uint32_t)(parity); uint32_t _d; \
    asm volatile("{\n\t.reg .pred p;\n\t" \
        "mbarrier.try_wait.parity.acquire.cta.shared::cta.b64 p, [%1], %2;\n\t" \
        "selp.b32 %0, 1, 0, p;\n\t}" : "=r"(_d) : "r"(_m), "r"(_p) : "memory"); \
    if (!_d) { \
        asm volatile("{\n\t.reg .pred P1;\n\t" \
            "WL_%=:\n\t" \
            "mbarrier.try_wait.parity.acquire.cta.shared::cta.b64 P1, [%0], %1, 0x989680;\n\t" \
            "@P1 bra.uni WD_%=;\n\t" \
            "bra.uni WL_%=;\n\t" \
            "WD_%=:\n\t}" :: "r"(_m), "r"(_p) : "memory"); \
    } } while (0)

#define TMA_LOAD_2D(smem_addr, tmap_ptr, cx, cy, mbar) \
    asm volatile("cp.async.bulk.tensor.2d.shared::cta.global.tile.mbarrier::complete_tx::bytes " \
        "[%0], [%1, {%2, %3}], [%4];" \
        :: "r"((uint32_t)(smem_addr)), "l"(tmap_ptr), "r"((int32_t)(cx)), "r"((int32_t)(cy)), \
           "r"((uint32_t)(mbar)) : "memory")

__device__ __forceinline__ uint32_t pkbf(float lo, float hi) {
    uint32_t r; asm("cvt.rn.bf16x2.f32 %0, %1, %2;" : "=r"(r) : "f"(hi), "f"(lo)); return r;
}
__device__ __forceinline__ void split2(float x, float y, uint32_t& h, uint32_t& l) {
    h = pkbf(x, y);
    float fx = __int_as_float(h << 16);
    float fy = __int_as_float(h & 0xffff0000u);
    l = pkbf(x - fx, y - fy);
}
__device__ __forceinline__ float ex2(float x) {
    float y; asm("ex2.approx.ftz.f32 %0, %1;" : "=f"(y) : "f"(x)); return y;
}

// ---------------- fp32 -> bf16 hi/lo conversion ---------------------------
__global__ void __launch_bounds__(512)
cvt_kernel(const float* __restrict__ x, __nv_bfloat16* __restrict__ hi,
           __nv_bfloat16* __restrict__ lo, int n4)
{
    int i = blockIdx.x * blockDim.x + threadIdx.x;
    int stride = gridDim.x * blockDim.x;
    for (; i < n4; i += stride) {
        float4 v = ((const float4*)x)[i];
        uint32_t h0, l0, h1, l1;
        split2(v.x, v.y, h0, l0);
        split2(v.z, v.w, h1, l1);
        ((uint32_t*)hi)[2 * i] = h0;  ((uint32_t*)hi)[2 * i + 1] = h1;
        ((uint32_t*)lo)[2 * i] = l0;  ((uint32_t*)lo)[2 * i + 1] = l1;
    }
}

// ---------------- TMA projection GEMM (split-bf16 3-MMA) ------------------
// out = (X @ W^T + bias) * scale.
// MODE 0: fp32 out [m][1024]. MODE 1: bf16 hi/lo, head layout [b,h,s,dh].
#define KC          64
#define NCHUNKS     (D_MODEL / KC)
#define PSTAGES     3
#define RA_H        0
#define RA_L        16384
#define RB_H        32768
#define RB_L        49152
#define STAGE_BYTES 65536
#define PROJ_SMEM   (PSTAGES * STAGE_BYTES)

template <int MODE>
__global__ void __launch_bounds__(256)
mma_proj(const __grid_constant__ CUtensorMap tmAh,
         const __grid_constant__ CUtensorMap tmAl,
         const __grid_constant__ CUtensorMap tmBh,
         const __grid_constant__ CUtensorMap tmBl,
         const float* __restrict__ bias, float* __restrict__ out,
         __nv_bfloat16* __restrict__ oh, __nv_bfloat16* __restrict__ ol, float scale)
{
    extern __shared__ __align__(1024) char smem[];
    __shared__ __align__(8) ull s_bar[PSTAGES];
    const uint32_t dyn0 = smem_u32(smem);
    const uint32_t bar0 = smem_u32(s_bar);

    const int tid = threadIdx.x;
    const int wid = tid >> 5, lane = tid & 31;
    const int m0 = blockIdx.y << 7, n0 = blockIdx.x << 7;
    const int wm = (wid & 1) << 6, wn = (wid >> 1) << 5;

    if (tid == 0) {
        for (int s = 0; s < PSTAGES; ++s) MBARRIER_INIT(bar0 + s * 8, 1);
    }
    __syncthreads();

    auto issue = [&](int s, int kc) {
        const uint32_t sb = dyn0 + s * STAGE_BYTES;
        const uint32_t fb = bar0 + s * 8;
        MBARRIER_EXPECT_TX(fb, STAGE_BYTES);
        TMA_LOAD_2D(sb + RA_H, &tmAh, kc * KC, m0, fb);
        TMA_LOAD_2D(sb + RA_L, &tmAl, kc * KC, m0, fb);
        TMA_LOAD_2D(sb + RB_H, &tmBh, kc * KC, n0, fb);
        TMA_LOAD_2D(sb + RB_L, &tmBl, kc * KC, n0, fb);
    };
    if (tid == 0) {
        for (int c = 0; c < PSTAGES; ++c) issue(c, c);
    }

    float acc[4][4][4];
#pragma unroll
    for (int i = 0; i < 4; ++i)
#pragma unroll
        for (int j = 0; j < 4; ++j)
#pragma unroll
            for (int q = 0; q < 4; ++q) acc[i][j][q] = 0.f;

    for (int kc = 0; kc < NCHUNKS; ++kc) {
        const int s = kc % PSTAGES;
        const int ph = (kc / PSTAGES) & 1;
        MBARRIER_WAIT_PARITY(bar0 + s * 8, ph);
        const uint32_t sb = dyn0 + s * STAGE_BYTES;

#pragma unroll
        for (int k16 = 0; k16 < 4; ++k16) {
            uint32_t ah[4][4], al[4][4], bh[2][4], bl[2][4];
#pragma unroll
            for (int am = 0; am < 4; ++am) {
                const int rowA = wm + am * 16 + (lane & 15);
                const int g = k16 * 2 + (lane >> 4);
                const uint32_t off = (rowA << 7) + ((g ^ (rowA & 7)) << 4);
                ldsm_x4(ah[am], sb + RA_H + off);
                ldsm_x4(al[am], sb + RA_L + off);
            }
#pragma unroll
            for (int p = 0; p < 2; ++p) {
                const int rowB = wn + p * 16 + ((lane >> 4) << 3) + (lane & 7);
                const int g = k16 * 2 + ((lane >> 3) & 1);
                const uint32_t off = (rowB << 7) + ((g ^ (rowB & 7)) << 4);
                ldsm_x4(bh[p], sb + RB_H + off);
                ldsm_x4(bl[p], sb + RB_L + off);
            }
#pragma unroll
            for (int am = 0; am < 4; ++am)
#pragma unroll
                for (int an = 0; an < 4; ++an) {
                    uint32_t* B0 = &bh[an >> 1][(an & 1) * 2];
                    uint32_t* BL = &bl[an >> 1][(an & 1) * 2];
                    MMA_BF16(acc[am][an], ah[am], B0);
                    MMA_BF16(acc[am][an], ah[am], BL);
                    MMA_BF16(acc[am][an], al[am], B0);
                }
        }
        __syncthreads();
        if (tid == 0 && kc + PSTAGES < NCHUNKS) issue(s, kc + PSTAGES);
    }

#pragma unroll
    for (int am = 0; am < 4; ++am) {
#pragma unroll
        for (int an = 0; an < 4; ++an) {
            const int m = m0 + wm + am * 16 + (lane >> 2);
            const int c = n0 + wn + an * 8 + ((lane & 3) << 1);
            const float2 bv = *(const float2*)&bias[c];
#pragma unroll
            for (int h2 = 0; h2 < 2; ++h2) {
                const int row = m + h2 * 8;
                float ox = (acc[am][an][2 * h2]     + bv.x) * scale;
                float oy = (acc[am][an][2 * h2 + 1] + bv.y) * scale;
                if (MODE == 1) {
                    const int b = row >> 11, srow = row & (SEQ - 1);
                    const int hh = c >> 6, dh = c & 63;
                    const size_t idx = (((size_t)(b * NHEAD + hh) * SEQ + srow) * HEAD_DIM + dh);
                    uint32_t h, l;
                    split2(ox, oy, h, l);
                    *(uint32_t*)(oh + idx) = h;
                    *(uint32_t*)(ol + idx) = l;
                } else {
                    *(float2*)(out + (size_t)row * D_MODEL + c) = make_float2(ox, oy);
                }
            }
        }
    }
}

// ---------------- TMA causal flash attention ------------------------------
// Q/K/V bf16 hi/lo [bh*S][64] (Q pre-scaled by log2(e)/8). Out: ctx hi/lo bf16
// [B*S][1024] (head-interleaved columns), feeding the output projection.
// smem: Q region 32KB (Qh 0, Ql 16384), then 3 KV stages x 32KB.
#define KVSTAGES 3
#define KV0      32768
#define AT_SMEM  (KV0 + KVSTAGES * 32768)

__global__ void __launch_bounds__(256)
attn_mma(const __grid_constant__ CUtensorMap tmQh, const __grid_constant__ CUtensorMap tmQl,
         const __grid_constant__ CUtensorMap tmKh, const __grid_constant__ CUtensorMap tmKl,
         const __grid_constant__ CUtensorMap tmVh, const __grid_constant__ CUtensorMap tmVl,
         __nv_bfloat16* __restrict__ Ch, __nv_bfloat16* __restrict__ Cl)
{
    extern __shared__ __align__(1024) char smem[];
    __shared__ __align__(8) ull s_bar[1 + KVSTAGES];
    const uint32_t dyn0 = smem_u32(smem);
    const uint32_t barq = smem_u32(s_bar);
    const uint32_t bark = barq + 8;

    const int tid = threadIdx.x, wid = tid >> 5, lane = tid & 31;
    const int bx = (int)gridDim.x - 1 - (int)blockIdx.x;   // big tiles first
    const int bh = blockIdx.y;
    const int q0 = bx << 7;
    const int yb = bh * SEQ;
    const int ktend = 2 * bx + 2;

    if (tid == 0) {
        MBARRIER_INIT(barq, 1);
        for (int s = 0; s < KVSTAGES; ++s) MBARRIER_INIT(bark + s * 8, 1);
    }
    __syncthreads();

    auto issue_kv = [&](int s, int kt) {
        const uint32_t sb = dyn0 + KV0 + s * 32768;
        const uint32_t fb = bark + s * 8;
        const int y = yb + kt * 64;
        MBARRIER_EXPECT_TX(fb, 32768);
        TMA_LOAD_2D(sb,         &tmKh, 0, y, fb);
        TMA_LOAD_2D(sb +  8192, &tmKl, 0, y, fb);
        TMA_LOAD_2D(sb + 16384, &tmVh, 0, y, fb);
        TMA_LOAD_2D(sb + 24576, &tmVl, 0, y, fb);
    };
    if (tid == 0) {
        MBARRIER_EXPECT_TX(barq, 32768);
        TMA_LOAD_2D(dyn0,         &tmQh, 0, yb + q0, barq);
        TMA_LOAD_2D(dyn0 + 16384, &tmQl, 0, yb + q0, barq);
        const int np = ktend < KVSTAGES ? ktend : KVSTAGES;
        for (int p = 0; p < np; ++p) issue_kv(p, p);
    }

    // ---- Q fragments (region never reused; no extra sync needed)
    MBARRIER_WAIT_PARITY(barq, 0);
    uint32_t qh[4][4], ql[4][4];
#pragma unroll
    for (int k16 = 0; k16 < 4; ++k16) {
        const int rowA = wid * 16 + (lane & 15);
        const int g = k16 * 2 + (lane >> 4);
        const uint32_t off = (rowA << 7) + ((g ^ (rowA & 7)) << 4);
        ldsm_x4(qh[k16], dyn0 + off);
        ldsm_x4(ql[k16], dyn0 + 16384 + off);
    }

    float O[8][4];
#pragma unroll
    for (int j = 0; j < 8; ++j)
#pragma unroll
        for (int q = 0; q < 4; ++q) O[j][q] = 0.f;
    float m0 = -1e30f, m1 = -1e30f, l0 = 0.f, l1 = 0.f;

    const int rrow = lane >> 2;
    const int ccol = (lane & 3) << 1;

    for (int kt = 0; kt < ktend; ++kt) {
        const int s = kt % KVSTAGES;
        const int ph = (kt / KVSTAGES) & 1;
        MBARRIER_WAIT_PARITY(bark + s * 8, ph);
        const uint32_t sb = dyn0 + KV0 + s * 32768;

        const bool active = (kt * 64 <= q0 + wid * 16 + 15);
        if (active) {
            // ---- S = Q K^T (3-MMA split)
            float S[8][4];
#pragma unroll
            for (int j = 0; j < 8; ++j)
#pragma unroll
                for (int q = 0; q < 4; ++q) S[j][q] = 0.f;
#pragma unroll
            for (int p = 0; p < 4; ++p) {
#pragma unroll
                for (int k16 = 0; k16 < 4; ++k16) {
                    uint32_t bkh[4], bkl[4];
                    const int rowB = p * 16 + ((lane >> 4) << 3) + (lane & 7);
                    const int g = k16 * 2 + ((lane >> 3) & 1);
                    const uint32_t off = (rowB << 7) + ((g ^ (rowB & 7)) << 4);
                    ldsm_x4(bkh, sb + off);
                    ldsm_x4(bkl, sb + 8192 + off);
                    MMA_BF16(S[2 * p],     qh[k16], &bkh[0]);
                    MMA_BF16(S[2 * p],     qh[k16], &bkl[0]);
                    MMA_BF16(S[2 * p],     ql[k16], &bkh[0]);
                    MMA_BF16(S[2 * p + 1], qh[k16], &bkh[2]);
                    MMA_BF16(S[2 * p + 1], qh[k16], &bkl[2]);
                    MMA_BF16(S[2 * p + 1], ql[k16], &bkh[2]);
                }
            }

            // ---- causal mask (only the 2 diagonal chunks)
            if (kt >= 2 * bx) {
                const int r0g = q0 + wid * 16 + rrow;
#pragma unroll
                for (int jt = 0; jt < 8; ++jt) {
                    const int cg = kt * 64 + jt * 8 + ccol;
                    if (cg     > r0g)     S[jt][0] = -1e30f;
                    if (cg + 1 > r0g)     S[jt][1] = -1e30f;
                    if (cg     > r0g + 8) S[jt][2] = -1e30f;
                    if (cg + 1 > r0g + 8) S[jt][3] = -1e30f;
                }
            }

            // ---- online softmax (base-2; log2e folded into Q scale)
            float mx0 = -1e30f, mx1 = -1e30f;
#pragma unroll
            for (int jt = 0; jt < 8; ++jt) {
                mx0 = fmaxf(mx0, fmaxf(S[jt][0], S[jt][1]));
                mx1 = fmaxf(mx1, fmaxf(S[jt][2], S[jt][3]));
            }
            mx0 = fmaxf(mx0, __shfl_xor_sync(0xffffffffu, mx0, 1));
            mx0 = fmaxf(mx0, __shfl_xor_sync(0xffffffffu, mx0, 2));
            mx1 = fmaxf(mx1, __shfl_xor_sync(0xffffffffu, mx1, 1));
            mx1 = fmaxf(mx1, __shfl_xor_sync(0xffffffffu, mx1, 2));
            const float nm0 = fmaxf(m0, mx0), nm1 = fmaxf(m1, mx1);
            const float a0 = ex2(m0 - nm0), a1 = ex2(m1 - nm1);
            m0 = nm0; m1 = nm1;
            float s0 = 0.f, s1 = 0.f;
#pragma unroll
            for (int jt = 0; jt < 8; ++jt) {
                S[jt][0] = ex2(S[jt][0] - m0);
                S[jt][1] = ex2(S[jt][1] - m0);
                S[jt][2] = ex2(S[jt][2] - m1);
                S[jt][3] = ex2(S[jt][3] - m1);
                s0 += S[jt][0] + S[jt][1];
                s1 += S[jt][2] + S[jt][3];
            }
            s0 += __shfl_xor_sync(0xffffffffu, s0, 1);
            s0 += __shfl_xor_sync(0xffffffffu, s0, 2);
            s1 += __shfl_xor_sync(0xffffffffu, s1, 1);
            s1 += __shfl_xor_sync(0xffffffffu, s1, 2);
            l0 = l0 * a0 + s0;
            l1 = l1 * a1 + s1;
#pragma unroll
            for (int jt = 0; jt < 8; ++jt) {
                O[jt][0] *= a0; O[jt][1] *= a0;
                O[jt][2] *= a1; O[jt][3] *= a1;
            }

            // ---- pack P into bf16 hi/lo A fragments
            uint32_t pfh[4][4], pfl[4][4];
#pragma unroll
            for (int kk = 0; kk < 4; ++kk) {
                split2(S[2 * kk][0],     S[2 * kk][1],     pfh[kk][0], pfl[kk][0]);
                split2(S[2 * kk][2],     S[2 * kk][3],     pfh[kk][1], pfl[kk][1]);
                split2(S[2 * kk + 1][0], S[2 * kk + 1][1], pfh[kk][2], pfl[kk][2]);
                split2(S[2 * kk + 1][2], S[2 * kk + 1][3], pfh[kk][3], pfl[kk][3]);
            }

            // ---- O += P V (3-MMA split, V^T via ldmatrix.trans)
#pragma unroll
            for (int p = 0; p < 4; ++p) {
#pragma unroll
                for (int kk = 0; kk < 4; ++kk) {
                    uint32_t vh[4], vl[4];
                    const int key = kk * 16 + ((lane >> 3) & 1) * 8 + (lane & 7);
                    const int nt = 2 * p + (lane >> 4);
                    const uint32_t off = (key << 7) + (((nt) ^ (key & 7)) << 4);
                    ldsm_x4_t(vh, sb + 16384 + off);
                    ldsm_x4_t(vl, sb + 24576 + off);
                    MMA_BF16(O[2 * p],     pfh[kk], &vh[0]);
                    MMA_BF16(O[2 * p],     pfl[kk], &vh[0]);
                    MMA_BF16(O[2 * p],     pfh[kk], &vl[0]);
                    MMA_BF16(O[2 * p + 1], pfh[kk], &vh[2]);
                    MMA_BF16(O[2 * p + 1], pfl[kk], &vh[2]);
                    MMA_BF16(O[2 * p + 1], pfh[kk], &vl[2]);
                }
            }
        }
        __syncthreads();
        if (tid == 0 && kt + KVSTAGES < ktend) issue_kv(s, kt + KVSTAGES);
    }

    // ---- finalize: O/l, write ctx hi/lo bf16 straight into proj-A buffers
    const float inv0 = 1.f / l0, inv1 = 1.f / l1;
    const int b = bh >> 4, h = bh & 15;
    const int r0g = q0 + wid * 16 + rrow;
    const size_t mi0 = ((size_t)b * SEQ + r0g) * D_MODEL + h * 64;
    const size_t mi1 = ((size_t)b * SEQ + r0g + 8) * D_MODEL + h * 64;
#pragma unroll
    for (int jt = 0; jt < 8; ++jt) {
        const int c = jt * 8 + ccol;
        uint32_t hh, ll;
        split2(O[jt][0] * inv0, O[jt][1] * inv0, hh, ll);
        *(uint32_t*)(Ch + mi0 + c) = hh;
        *(uint32_t*)(Cl + mi0 + c) = ll;
        split2(O[jt][2] * inv1, O[jt][3] * inv1, hh, ll);
        *(uint32_t*)(Ch + mi1 + c) = hh;
        *(uint32_t*)(Cl + mi1 + c) = ll;
    }
}

// ---------------- host-side tensor maps -----------------------------------
typedef CUresult (*EncodeFn)(CUtensorMap*, CUtensorMapDataType, cuuint32_t, void*,
                             const cuuint64_t*, const cuuint64_t*, const cuuint32_t*,
                             const cuuint32_t*, CUtensorMapInterleave, CUtensorMapSwizzle,
                             CUtensorMapL2promotion, CUtensorMapFloatOOBfill);

static void make_map(EncodeFn enc, CUtensorMap* m, void* base,
                     uint64_t d0, uint64_t d1, uint32_t box_rows)
{
    cuuint64_t dims[2] = {d0, d1};
    cuuint64_t strides[1] = {d0 * 2};       // bytes per row
    cuuint32_t box[2] = {64u, box_rows};    // 64 bf16 = 128B (SW128)
    cuuint32_t es[2] = {1u, 1u};
    enc(m, CU_TENSOR_MAP_DATA_TYPE_BFLOAT16, 2, base, dims, strides, box, es,
        CU_TENSOR_MAP_INTERLEAVE_NONE, CU_TENSOR_MAP_SWIZZLE_128B,
        CU_TENSOR_MAP_L2_PROMOTION_L2_128B, CU_TENSOR_MAP_FLOAT_OOB_FILL_NONE);
}

// ---------------- launcher -------------------------------------------------
extern "C" void kernel_launch(void* const* d_in, const int* in_sizes, int n_in,
                              void* d_out, int out_size)
{
    const float* query = (const float*)d_in[0];
    const float* key_  = (const float*)d_in[1];
    const float* value = (const float*)d_in[2];
    const float* Wq = (const float*)d_in[4];
    const float* bq = (const float*)d_in[5];
    const float* Wk = (const float*)d_in[6];
    const float* bk = (const float*)d_in[7];
    const float* Wv = (const float*)d_in[8];
    const float* bv = (const float*)d_in[9];
    const float* Wo = (const float*)d_in[10];
    const float* bo = (const float*)d_in[11];
    float* out = (float*)d_out;

    __nv_bfloat16 *pQh, *pQl, *pKh, *pKl, *pVh, *pVl, *pXhi, *pXlo, *pWhi, *pWlo;
    cudaGetSymbolAddress((void**)&pQh, g_Qh);
    cudaGetSymbolAddress((void**)&pQl, g_Ql);
    cudaGetSymbolAddress((void**)&pKh, g_Kh);
    cudaGetSymbolAddress((void**)&pKl, g_Kl);
    cudaGetSymbolAddress((void**)&pVh, g_Vh);
    cudaGetSymbolAddress((void**)&pVl, g_Vl);
    cudaGetSymbolAddress((void**)&pXhi, g_Xhi);
    cudaGetSymbolAddress((void**)&pXlo, g_Xlo);
    cudaGetSymbolAddress((void**)&pWhi, g_Whi);
    cudaGetSymbolAddress((void**)&pWlo, g_Wlo);

    void* encp = nullptr;
    cudaDriverEntryPointQueryResult qr;
    cudaGetDriverEntryPointByVersion("cuTensorMapEncodeTiled", &encp, 12000,
                                     cudaEnableDefault, &qr);
    EncodeFn enc = (EncodeFn)encp;

    const uint64_t NR = (uint64_t)BATCH * NHEAD * SEQ;   // 131072 head rows
    CUtensorMap tmXhi, tmXlo, tmWhi, tmWlo, tmQh, tmQl, tmKh, tmKl, tmVh, tmVl;
    make_map(enc, &tmXhi, pXhi, D_MODEL, M_TOT, 128);
    make_map(enc, &tmXlo, pXlo, D_MODEL, M_TOT, 128);
    make_map(enc, &tmWhi, pWhi, D_MODEL, D_MODEL, 128);
    make_map(enc, &tmWlo, pWlo, D_MODEL, D_MODEL, 128);
    make_map(enc, &tmQh, pQh, HEAD_DIM, NR, 128);
    make_map(enc, &tmQl, pQl, HEAD_DIM, NR, 128);
    make_map(enc, &tmKh, pKh, HEAD_DIM, NR, 64);
    make_map(enc, &tmKl, pKl, HEAD_DIM, NR, 64);
    make_map(enc, &tmVh, pVh, HEAD_DIM, NR, 64);
    make_map(enc, &tmVl, pVl, HEAD_DIM, NR, 64);

    cudaFuncSetAttribute(mma_proj<0>, cudaFuncAttributeMaxDynamicSharedMemorySize, PROJ_SMEM);
    cudaFuncSetAttribute(mma_proj<1>, cudaFuncAttributeMaxDynamicSharedMemorySize, PROJ_SMEM);
    cudaFuncSetAttribute(attn_mma,    cudaFuncAttributeMaxDynamicSharedMemorySize, AT_SMEM);

    const int NX4 = (M_TOT * D_MODEL) / 4;
    const int NW4 = (D_MODEL * D_MODEL) / 4;
    dim3 gp(D_MODEL / 128, M_TOT / 128);   // (8, 64)
    dim3 ga(SEQ / 128, BATCH * NHEAD);     // (16, 64)
    const float qscale = 0.125f * 1.4426950408889634f;  // 1/sqrt(64) * log2(e)

    // Q projection
    cvt_kernel<<<2048, 512>>>(query, pXhi, pXlo, NX4);
    cvt_kernel<<<512, 512>>>(Wq, pWhi, pWlo, NW4);
    mma_proj<1><<<gp, 256, PROJ_SMEM>>>(tmXhi, tmXlo, tmWhi, tmWlo, bq, nullptr, pQh, pQl, qscale);
    // K projection
    cvt_kernel<<<2048, 512>>>(key_, pXhi, pXlo, NX4);
    cvt_kernel<<<512, 512>>>(Wk, pWhi, pWlo, NW4);
    mma_proj<1><<<gp, 256, PROJ_SMEM>>>(tmXhi, tmXlo, tmWhi, tmWlo, bk, nullptr, pKh, pKl, 1.0f);
    // V projection
    cvt_kernel<<<2048, 512>>>(value, pXhi, pXlo, NX4);
    cvt_kernel<<<512, 512>>>(Wv, pWhi, pWlo, NW4);
    mma_proj<1><<<gp, 256, PROJ_SMEM>>>(tmXhi, tmXlo, tmWhi, tmWlo, bv, nullptr, pVh, pVl, 1.0f);
    // attention -> ctx hi/lo (directly into out-proj A buffers)
    attn_mma<<<ga, 256, AT_SMEM>>>(tmQh, tmQl, tmKh, tmKl, tmVh, tmVl, pXhi, pXlo);
    // output projection
    cvt_kernel<<<512, 512>>>(Wo, pWhi, pWlo, NW4);
    mma_proj<0><<<gp, 256, PROJ_SMEM>>>(tmXhi, tmXlo, tmWhi, tmWlo, bo, out, nullptr, nullptr, 1.0f);
}

// round 8
// speedup vs baseline: 4.4666x; 1.2559x over previous
#include <cuda_runtime.h>
#include <cuda.h>
#include <cuda_fp16.h>
#include <cstdint>

#define D_MODEL 1024
#define NHEAD   16
#define HEAD_DIM 64
#define BATCH   4
#define SEQ     2048
#define M_TOT   (BATCH * SEQ)

// ---------------- scratch (static device memory; no allocations) ----------
__device__ __half g_Qh[BATCH * NHEAD * SEQ * HEAD_DIM];
__device__ __half g_Ql[BATCH * NHEAD * SEQ * HEAD_DIM];
__device__ __half g_K [BATCH * NHEAD * SEQ * HEAD_DIM];
__device__ __half g_V [BATCH * NHEAD * SEQ * HEAD_DIM];
__device__ __half g_Xhi[M_TOT * D_MODEL];
__device__ __half g_Xlo[M_TOT * D_MODEL];
__device__ __half g_W  [D_MODEL * D_MODEL];

typedef unsigned long long ull;

// ---------------- PTX helpers ---------------------------------------------
__device__ __forceinline__ uint32_t smem_u32(const void* p) {
    uint32_t a;
    asm("{ .reg .u64 t; cvta.to.shared.u64 t, %1; cvt.u32.u64 %0, t; }"
        : "=r"(a) : "l"(p));
    return a;
}
__device__ __forceinline__ void ldsm_x4(uint32_t* r, uint32_t a) {
    asm volatile("ldmatrix.sync.aligned.m8n8.x4.shared.b16 {%0,%1,%2,%3}, [%4];"
                 : "=r"(r[0]), "=r"(r[1]), "=r"(r[2]), "=r"(r[3]) : "r"(a));
}
__device__ __forceinline__ void ldsm_x4_t(uint32_t* r, uint32_t a) {
    asm volatile("ldmatrix.sync.aligned.m8n8.x4.trans.shared.b16 {%0,%1,%2,%3}, [%4];"
                 : "=r"(r[0]), "=r"(r[1]), "=r"(r[2]), "=r"(r[3]) : "r"(a));
}
#define MMA_F16(acc, a, b) \
    asm volatile("mma.sync.aligned.m16n8k16.row.col.f32.f16.f16.f32 " \
        "{%0,%1,%2,%3}, {%4,%5,%6,%7}, {%8,%9}, {%0,%1,%2,%3};" \
        : "+f"((acc)[0]), "+f"((acc)[1]), "+f"((acc)[2]), "+f"((acc)[3]) \
        : "r"((a)[0]), "r"((a)[1]), "r"((a)[2]), "r"((a)[3]), \
          "r"((b)[0]), "r"((b)[1]))

#define MBARRIER_INIT(addr, cnt) \
    asm volatile("mbarrier.init.shared.b64 [%0], %1;" :: "r"(addr), "r"(cnt) : "memory")
#define MBARRIER_EXPECT_TX(addr, bytes) \
    asm volatile("mbarrier.arrive.expect_tx.shared.b64 _, [%0], %1;" \
                 :: "r"(addr), "r"(bytes) : "memory")
#define MBARRIER_WAIT_PARITY(addr, parity) do { \
    uint32_t _m = (uint32_t)(addr); uint32_t _p = (uint32_t)(parity); uint32_t _d; \
    asm volatile("{\n\t.reg .pred p;\n\t" \
        "mbarrier.try_wait.parity.acquire.cta.shared::cta.b64 p, [%1], %2;\n\t" \
        "selp.b32 %0, 1, 0, p;\n\t}" : "=r"(_d) : "r"(_m), "r"(_p) : "memory"); \
    if (!_d) { \
        asm volatile("{\n\t.reg .pred P1;\n\t" \
            "WL_%=:\n\t" \
            "mbarrier.try_wait.parity.acquire.cta.shared::cta.b64 P1, [%0], %1, 0x989680;\n\t" \
            "@P1 bra.uni WD_%=;\n\t" \
            "bra.uni WL_%=;\n\t" \
            "WD_%=:\n\t}" :: "r"(_m), "r"(_p) : "memory"); \
    } } while (0)

#define TMA_LOAD_2D(smem_addr, tmap_ptr, cx, cy, mbar) \
    asm volatile("cp.async.bulk.tensor.2d.shared::cta.global.tile.mbarrier::complete_tx::bytes " \
        "[%0], [%1, {%2, %3}], [%4];" \
        :: "r"((uint32_t)(smem_addr)), "l"(tmap_ptr), "r"((int32_t)(cx)), "r"((int32_t)(cy)), \
           "r"((uint32_t)(mbar)) : "memory")

__device__ __forceinline__ uint32_t pkh(float x, float y) {
    __half2 hh = __floats2half2_rn(x, y);
    return *(uint32_t*)&hh;
}
__device__ __forceinline__ void split2h(float x, float y, uint32_t& h, uint32_t& l) {
    __half2 hh = __floats2half2_rn(x, y);
    float fx = __low2float(hh), fy = __high2float(hh);
    __half2 ll = __floats2half2_rn(x - fx, y - fy);
    h = *(uint32_t*)&hh;
    l = *(uint32_t*)&ll;
}
__device__ __forceinline__ float ex2(float x) {
    float y; asm("ex2.approx.ftz.f32 %0, %1;" : "=f"(y) : "f"(x)); return y;
}

// ---------------- fp32 -> fp16 conversions --------------------------------
__global__ void __launch_bounds__(512)
cvt_split(const float* __restrict__ x, __half* __restrict__ hi,
          __half* __restrict__ lo, int n4)
{
    int i = blockIdx.x * blockDim.x + threadIdx.x;
    int stride = gridDim.x * blockDim.x;
    for (; i < n4; i += stride) {
        float4 v = ((const float4*)x)[i];
        uint32_t h0, l0, h1, l1;
        split2h(v.x, v.y, h0, l0);
        split2h(v.z, v.w, h1, l1);
        ((uint32_t*)hi)[2 * i] = h0;  ((uint32_t*)hi)[2 * i + 1] = h1;
        ((uint32_t*)lo)[2 * i] = l0;  ((uint32_t*)lo)[2 * i + 1] = l1;
    }
}
__global__ void __launch_bounds__(512)
cvt_single(const float* __restrict__ x, __half* __restrict__ w, int n4)
{
    int i = blockIdx.x * blockDim.x + threadIdx.x;
    int stride = gridDim.x * blockDim.x;
    for (; i < n4; i += stride) {
        float4 v = ((const float4*)x)[i];
        ((uint32_t*)w)[2 * i]     = pkh(v.x, v.y);
        ((uint32_t*)w)[2 * i + 1] = pkh(v.z, v.w);
    }
}

// ---------------- TMA projection GEMM (fp16 2-MMA: A split, B single) -----
// out = (X @ W^T + bias) * scale.
// MODE 0: fp32 out [m][1024]. MODE 1: fp16 hi/lo head layout. MODE 2: fp16 single head layout.
#define KC          64
#define NCHUNKS     (D_MODEL / KC)
#define PSTAGES     3
#define RA_H        0
#define RA_L        16384
#define RB          32768
#define STAGE_BYTES 49152
#define PROJ_SMEM   (PSTAGES * STAGE_BYTES)

template <int MODE>
__global__ void __launch_bounds__(256)
mma_proj(const __grid_constant__ CUtensorMap tmAh,
         const __grid_constant__ CUtensorMap tmAl,
         const __grid_constant__ CUtensorMap tmB,
         const float* __restrict__ bias, float* __restrict__ out,
         __half* __restrict__ oh, __half* __restrict__ ol, float scale)
{
    extern __shared__ __align__(1024) char smem[];
    __shared__ __align__(8) ull s_bar[PSTAGES];
    const uint32_t dyn0 = smem_u32(smem);
    const uint32_t bar0 = smem_u32(s_bar);

    const int tid = threadIdx.x;
    const int wid = tid >> 5, lane = tid & 31;
    const int m0 = blockIdx.y << 7, n0 = blockIdx.x << 7;
    const int wm = (wid & 1) << 6, wn = (wid >> 1) << 5;

    if (tid == 0) {
        for (int s = 0; s < PSTAGES; ++s) MBARRIER_INIT(bar0 + s * 8, 1);
    }
    __syncthreads();

    auto issue = [&](int s, int kc) {
        const uint32_t sb = dyn0 + s * STAGE_BYTES;
        const uint32_t fb = bar0 + s * 8;
        MBARRIER_EXPECT_TX(fb, STAGE_BYTES);
        TMA_LOAD_2D(sb + RA_H, &tmAh, kc * KC, m0, fb);
        TMA_LOAD_2D(sb + RA_L, &tmAl, kc * KC, m0, fb);
        TMA_LOAD_2D(sb + RB,   &tmB,  kc * KC, n0, fb);
    };
    if (tid == 0) {
        for (int c = 0; c < PSTAGES; ++c) issue(c, c);
    }

    float acc[4][4][4];
#pragma unroll
    for (int i = 0; i < 4; ++i)
#pragma unroll
        for (int j = 0; j < 4; ++j)
#pragma unroll
            for (int q = 0; q < 4; ++q) acc[i][j][q] = 0.f;

    for (int kc = 0; kc < NCHUNKS; ++kc) {
        const int s = kc % PSTAGES;
        const int ph = (kc / PSTAGES) & 1;
        MBARRIER_WAIT_PARITY(bar0 + s * 8, ph);
        const uint32_t sb = dyn0 + s * STAGE_BYTES;

#pragma unroll
        for (int k16 = 0; k16 < 4; ++k16) {
            uint32_t ah[4][4], al[4][4], bh[2][4];
#pragma unroll
            for (int am = 0; am < 4; ++am) {
                const int rowA = wm + am * 16 + (lane & 15);
                const int g = k16 * 2 + (lane >> 4);
                const uint32_t off = (rowA << 7) + ((g ^ (rowA & 7)) << 4);
                ldsm_x4(ah[am], sb + RA_H + off);
                ldsm_x4(al[am], sb + RA_L + off);
            }
#pragma unroll
            for (int p = 0; p < 2; ++p) {
                const int rowB = wn + p * 16 + ((lane >> 4) << 3) + (lane & 7);
                const int g = k16 * 2 + ((lane >> 3) & 1);
                const uint32_t off = (rowB << 7) + ((g ^ (rowB & 7)) << 4);
                ldsm_x4(bh[p], sb + RB + off);
            }
#pragma unroll
            for (int am = 0; am < 4; ++am)
#pragma unroll
                for (int an = 0; an < 4; ++an) {
                    uint32_t* B0 = &bh[an >> 1][(an & 1) * 2];
                    MMA_F16(acc[am][an], ah[am], B0);
                    MMA_F16(acc[am][an], al[am], B0);
                }
        }
        __syncthreads();
        if (tid == 0 && kc + PSTAGES < NCHUNKS) issue(s, kc + PSTAGES);
    }

#pragma unroll
    for (int am = 0; am < 4; ++am) {
#pragma unroll
        for (int an = 0; an < 4; ++an) {
            const int m = m0 + wm + am * 16 + (lane >> 2);
            const int c = n0 + wn + an * 8 + ((lane & 3) << 1);
            const float2 bv = *(const float2*)&bias[c];
#pragma unroll
            for (int h2 = 0; h2 < 2; ++h2) {
                const int row = m + h2 * 8;
                float ox = (acc[am][an][2 * h2]     + bv.x) * scale;
                float oy = (acc[am][an][2 * h2 + 1] + bv.y) * scale;
                if (MODE == 0) {
                    *(float2*)(out + (size_t)row * D_MODEL + c) = make_float2(ox, oy);
                } else {
                    const int b = row >> 11, srow = row & (SEQ - 1);
                    const int hh = c >> 6, dh = c & 63;
                    const size_t idx = (((size_t)(b * NHEAD + hh) * SEQ + srow) * HEAD_DIM + dh);
                    if (MODE == 1) {
                        uint32_t h, l;
                        split2h(ox, oy, h, l);
                        *(uint32_t*)(oh + idx) = h;
                        *(uint32_t*)(ol + idx) = l;
                    } else {
                        *(uint32_t*)(oh + idx) = pkh(ox, oy);
                    }
                }
            }
        }
    }
}

// ---------------- TMA causal flash attention (fp16 2-MMA) -----------------
// Q hi/lo fp16 [bh*S][64] (pre-scaled by log2(e)/8); K, V single fp16.
// Out: ctx hi/lo fp16 [B*S][1024] head-interleaved, feeding out-projection.
// smem: Q 32KB (Qh 0, Ql 16384), then 4 KV stages x 16KB (K 0, V 8192).
#define KVSTAGES 4
#define KV0      32768
#define KVSB     16384
#define AT_SMEM  (KV0 + KVSTAGES * KVSB)

__global__ void __launch_bounds__(256)
attn_mma(const __grid_constant__ CUtensorMap tmQh, const __grid_constant__ CUtensorMap tmQl,
         const __grid_constant__ CUtensorMap tmK,  const __grid_constant__ CUtensorMap tmV,
         __half* __restrict__ Ch, __half* __restrict__ Cl)
{
    extern __shared__ __align__(1024) char smem[];
    __shared__ __align__(8) ull s_bar[1 + KVSTAGES];
    const uint32_t dyn0 = smem_u32(smem);
    const uint32_t barq = smem_u32(s_bar);
    const uint32_t bark = barq + 8;

    const int tid = threadIdx.x, wid = tid >> 5, lane = tid & 31;
    const int bx = (int)gridDim.x - 1 - (int)blockIdx.x;   // big tiles first
    const int bh = blockIdx.y;
    const int q0 = bx << 7;
    const int yb = bh * SEQ;
    const int ktend = 2 * bx + 2;

    if (tid == 0) {
        MBARRIER_INIT(barq, 1);
        for (int s = 0; s < KVSTAGES; ++s) MBARRIER_INIT(bark + s * 8, 1);
    }
    __syncthreads();

    auto issue_kv = [&](int s, int kt) {
        const uint32_t sb = dyn0 + KV0 + s * KVSB;
        const uint32_t fb = bark + s * 8;
        const int y = yb + kt * 64;
        MBARRIER_EXPECT_TX(fb, KVSB);
        TMA_LOAD_2D(sb,        &tmK, 0, y, fb);
        TMA_LOAD_2D(sb + 8192, &tmV, 0, y, fb);
    };
    if (tid == 0) {
        MBARRIER_EXPECT_TX(barq, 32768);
        TMA_LOAD_2D(dyn0,         &tmQh, 0, yb + q0, barq);
        TMA_LOAD_2D(dyn0 + 16384, &tmQl, 0, yb + q0, barq);
        const int np = ktend < KVSTAGES ? ktend : KVSTAGES;
        for (int p = 0; p < np; ++p) issue_kv(p, p);
    }

    // ---- Q fragments (region never reused)
    MBARRIER_WAIT_PARITY(barq, 0);
    uint32_t qh[4][4], ql[4][4];
#pragma unroll
    for (int k16 = 0; k16 < 4; ++k16) {
        const int rowA = wid * 16 + (lane & 15);
        const int g = k16 * 2 + (lane >> 4);
        const uint32_t off = (rowA << 7) + ((g ^ (rowA & 7)) << 4);
        ldsm_x4(qh[k16], dyn0 + off);
        ldsm_x4(ql[k16], dyn0 + 16384 + off);
    }

    float O[8][4];
#pragma unroll
    for (int j = 0; j < 8; ++j)
#pragma unroll
        for (int q = 0; q < 4; ++q) O[j][q] = 0.f;
    float m0 = -1e30f, m1 = -1e30f, l0 = 0.f, l1 = 0.f;

    const int rrow = lane >> 2;
    const int ccol = (lane & 3) << 1;

    for (int kt = 0; kt < ktend; ++kt) {
        const int s = kt % KVSTAGES;
        const int ph = (kt / KVSTAGES) & 1;
        MBARRIER_WAIT_PARITY(bark + s * 8, ph);
        const uint32_t sb = dyn0 + KV0 + s * KVSB;

        const bool active = (kt * 64 <= q0 + wid * 16 + 15);
        if (active) {
            // ---- S = Q K^T (2-MMA: Q split, K single)
            float S[8][4];
#pragma unroll
            for (int j = 0; j < 8; ++j)
#pragma unroll
                for (int q = 0; q < 4; ++q) S[j][q] = 0.f;
#pragma unroll
            for (int p = 0; p < 4; ++p) {
#pragma unroll
                for (int k16 = 0; k16 < 4; ++k16) {
                    uint32_t bkh[4];
                    const int rowB = p * 16 + ((lane >> 4) << 3) + (lane & 7);
                    const int g = k16 * 2 + ((lane >> 3) & 1);
                    const uint32_t off = (rowB << 7) + ((g ^ (rowB & 7)) << 4);
                    ldsm_x4(bkh, sb + off);
                    MMA_F16(S[2 * p],     qh[k16], &bkh[0]);
                    MMA_F16(S[2 * p],     ql[k16], &bkh[0]);
                    MMA_F16(S[2 * p + 1], qh[k16], &bkh[2]);
                    MMA_F16(S[2 * p + 1], ql[k16], &bkh[2]);
                }
            }

            // ---- causal mask (only the 2 diagonal chunks)
            if (kt >= 2 * bx) {
                const int r0g = q0 + wid * 16 + rrow;
#pragma unroll
                for (int jt = 0; jt < 8; ++jt) {
                    const int cg = kt * 64 + jt * 8 + ccol;
                    if (cg     > r0g)     S[jt][0] = -1e30f;
                    if (cg + 1 > r0g)     S[jt][1] = -1e30f;
                    if (cg     > r0g + 8) S[jt][2] = -1e30f;
                    if (cg + 1 > r0g + 8) S[jt][3] = -1e30f;
                }
            }

            // ---- online softmax (base-2; log2e folded into Q scale)
            float mx0 = -1e30f, mx1 = -1e30f;
#pragma unroll
            for (int jt = 0; jt < 8; ++jt) {
                mx0 = fmaxf(mx0, fmaxf(S[jt][0], S[jt][1]));
                mx1 = fmaxf(mx1, fmaxf(S[jt][2], S[jt][3]));
            }
            mx0 = fmaxf(mx0, __shfl_xor_sync(0xffffffffu, mx0, 1));
            mx0 = fmaxf(mx0, __shfl_xor_sync(0xffffffffu, mx0, 2));
            mx1 = fmaxf(mx1, __shfl_xor_sync(0xffffffffu, mx1, 1));
            mx1 = fmaxf(mx1, __shfl_xor_sync(0xffffffffu, mx1, 2));
            const float nm0 = fmaxf(m0, mx0), nm1 = fmaxf(m1, mx1);
            const float a0 = ex2(m0 - nm0), a1 = ex2(m1 - nm1);
            m0 = nm0; m1 = nm1;
            float s0 = 0.f, s1 = 0.f;
#pragma unroll
            for (int jt = 0; jt < 8; ++jt) {
                S[jt][0] = ex2(S[jt][0] - m0);
                S[jt][1] = ex2(S[jt][1] - m0);
                S[jt][2] = ex2(S[jt][2] - m1);
                S[jt][3] = ex2(S[jt][3] - m1);
                s0 += S[jt][0] + S[jt][1];
                s1 += S[jt][2] + S[jt][3];
            }
            s0 += __shfl_xor_sync(0xffffffffu, s0, 1);
            s0 += __shfl_xor_sync(0xffffffffu, s0, 2);
            s1 += __shfl_xor_sync(0xffffffffu, s1, 1);
            s1 += __shfl_xor_sync(0xffffffffu, s1, 2);
            l0 = l0 * a0 + s0;
            l1 = l1 * a1 + s1;
#pragma unroll
            for (int jt = 0; jt < 8; ++jt) {
                O[jt][0] *= a0; O[jt][1] *= a0;
                O[jt][2] *= a1; O[jt][3] *= a1;
            }

            // ---- pack P into fp16 hi/lo A fragments
            uint32_t pfh[4][4], pfl[4][4];
#pragma unroll
            for (int kk = 0; kk < 4; ++kk) {
                split2h(S[2 * kk][0],     S[2 * kk][1],     pfh[kk][0], pfl[kk][0]);
                split2h(S[2 * kk][2],     S[2 * kk][3],     pfh[kk][1], pfl[kk][1]);
                split2h(S[2 * kk + 1][0], S[2 * kk + 1][1], pfh[kk][2], pfl[kk][2]);
                split2h(S[2 * kk + 1][2], S[2 * kk + 1][3], pfh[kk][3], pfl[kk][3]);
            }

            // ---- O += P V (2-MMA: P split, V single; V^T via ldmatrix.trans)
#pragma unroll
            for (int p = 0; p < 4; ++p) {
#pragma unroll
                for (int kk = 0; kk < 4; ++kk) {
                    uint32_t vh[4];
                    const int key = kk * 16 + ((lane >> 3) & 1) * 8 + (lane & 7);
                    const int nt = 2 * p + (lane >> 4);
                    const uint32_t off = (key << 7) + (((nt) ^ (key & 7)) << 4);
                    ldsm_x4_t(vh, sb + 8192 + off);
                    MMA_F16(O[2 * p],     pfh[kk], &vh[0]);
                    MMA_F16(O[2 * p],     pfl[kk], &vh[0]);
                    MMA_F16(O[2 * p + 1], pfh[kk], &vh[2]);
                    MMA_F16(O[2 * p + 1], pfl[kk], &vh[2]);
                }
            }
        }
        __syncthreads();
        if (tid == 0 && kt + KVSTAGES < ktend) issue_kv(s, kt + KVSTAGES);
    }

    // ---- finalize: O/l, write ctx hi/lo fp16 straight into proj-A buffers
    const float inv0 = 1.f / l0, inv1 = 1.f / l1;
    const int b = bh >> 4, h = bh & 15;
    const int r0g = q0 + wid * 16 + rrow;
    const size_t mi0 = ((size_t)b * SEQ + r0g) * D_MODEL + h * 64;
    const size_t mi1 = ((size_t)b * SEQ + r0g + 8) * D_MODEL + h * 64;
#pragma unroll
    for (int jt = 0; jt < 8; ++jt) {
        const int c = jt * 8 + ccol;
        uint32_t hh, ll;
        split2h(O[jt][0] * inv0, O[jt][1] * inv0, hh, ll);
        *(uint32_t*)(Ch + mi0 + c) = hh;
        *(uint32_t*)(Cl + mi0 + c) = ll;
        split2h(O[jt][2] * inv1, O[jt][3] * inv1, hh, ll);
        *(uint32_t*)(Ch + mi1 + c) = hh;
        *(uint32_t*)(Cl + mi1 + c) = ll;
    }
}

// ---------------- host-side tensor maps -----------------------------------
typedef CUresult (*EncodeFn)(CUtensorMap*, CUtensorMapDataType, cuuint32_t, void*,
                             const cuuint64_t*, const cuuint64_t*, const cuuint32_t*,
                             const cuuint32_t*, CUtensorMapInterleave, CUtensorMapSwizzle,
                             CUtensorMapL2promotion, CUtensorMapFloatOOBfill);

static void make_map(EncodeFn enc, CUtensorMap* m, void* base,
                     uint64_t d0, uint64_t d1, uint32_t box_rows)
{
    cuuint64_t dims[2] = {d0, d1};
    cuuint64_t strides[1] = {d0 * 2};       // bytes per row
    cuuint32_t box[2] = {64u, box_rows};    // 64 f16 = 128B (SW128)
    cuuint32_t es[2] = {1u, 1u};
    enc(m, CU_TENSOR_MAP_DATA_TYPE_FLOAT16, 2, base, dims, strides, box, es,
        CU_TENSOR_MAP_INTERLEAVE_NONE, CU_TENSOR_MAP_SWIZZLE_128B,
        CU_TENSOR_MAP_L2_PROMOTION_L2_128B, CU_TENSOR_MAP_FLOAT_OOB_FILL_NONE);
}

// ---------------- launcher -------------------------------------------------
extern "C" void kernel_launch(void* const* d_in, const int* in_sizes, int n_in,
                              void* d_out, int out_size)
{
    const float* query = (const float*)d_in[0];
    const float* key_  = (const float*)d_in[1];
    const float* value = (const float*)d_in[2];
    const float* Wq = (const float*)d_in[4];
    const float* bq = (const float*)d_in[5];
    const float* Wk = (const float*)d_in[6];
    const float* bk = (const float*)d_in[7];
    const float* Wv = (const float*)d_in[8];
    const float* bv = (const float*)d_in[9];
    const float* Wo = (const float*)d_in[10];
    const float* bo = (const float*)d_in[11];
    float* out = (float*)d_out;

    __half *pQh, *pQl, *pK, *pV, *pXhi, *pXlo, *pW;
    cudaGetSymbolAddress((void**)&pQh, g_Qh);
    cudaGetSymbolAddress((void**)&pQl, g_Ql);
    cudaGetSymbolAddress((void**)&pK, g_K);
    cudaGetSymbolAddress((void**)&pV, g_V);
    cudaGetSymbolAddress((void**)&pXhi, g_Xhi);
    cudaGetSymbolAddress((void**)&pXlo, g_Xlo);
    cudaGetSymbolAddress((void**)&pW, g_W);

    void* encp = nullptr;
    cudaDriverEntryPointQueryResult qr;
    cudaGetDriverEntryPointByVersion("cuTensorMapEncodeTiled", &encp, 12000,
                                     cudaEnableDefault, &qr);
    EncodeFn enc = (EncodeFn)encp;

    const uint64_t NR = (uint64_t)BATCH * NHEAD * SEQ;   // 131072 head rows
    CUtensorMap tmXhi, tmXlo, tmW, tmQh, tmQl, tmK, tmV;
    make_map(enc, &tmXhi, pXhi, D_MODEL, M_TOT, 128);
    make_map(enc, &tmXlo, pXlo, D_MODEL, M_TOT, 128);
    make_map(enc, &tmW,   pW,   D_MODEL, D_MODEL, 128);
    make_map(enc, &tmQh, pQh, HEAD_DIM, NR, 128);
    make_map(enc, &tmQl, pQl, HEAD_DIM, NR, 128);
    make_map(enc, &tmK,  pK,  HEAD_DIM, NR, 64);
    make_map(enc, &tmV,  pV,  HEAD_DIM, NR, 64);

    cudaFuncSetAttribute(mma_proj<0>, cudaFuncAttributeMaxDynamicSharedMemorySize, PROJ_SMEM);
    cudaFuncSetAttribute(mma_proj<1>, cudaFuncAttributeMaxDynamicSharedMemorySize, PROJ_SMEM);
    cudaFuncSetAttribute(mma_proj<2>, cudaFuncAttributeMaxDynamicSharedMemorySize, PROJ_SMEM);
    cudaFuncSetAttribute(attn_mma,    cudaFuncAttributeMaxDynamicSharedMemorySize, AT_SMEM);

    const int NX4 = (M_TOT * D_MODEL) / 4;
    const int NW4 = (D_MODEL * D_MODEL) / 4;
    dim3 gp(D_MODEL / 128, M_TOT / 128);   // (8, 64)
    dim3 ga(SEQ / 128, BATCH * NHEAD);     // (16, 64)
    const float qscale = 0.125f * 1.4426950408889634f;  // 1/sqrt(64) * log2(e)

    // Q projection (split output)
    cvt_split<<<2048, 512>>>(query, pXhi, pXlo, NX4);
    cvt_single<<<512, 512>>>(Wq, pW, NW4);
    mma_proj<1><<<gp, 256, PROJ_SMEM>>>(tmXhi, tmXlo, tmW, bq, nullptr, pQh, pQl, qscale);
    // K projection (single output)
    cvt_split<<<2048, 512>>>(key_, pXhi, pXlo, NX4);
    cvt_single<<<512, 512>>>(Wk, pW, NW4);
    mma_proj<2><<<gp, 256, PROJ_SMEM>>>(tmXhi, tmXlo, tmW, bk, nullptr, pK, nullptr, 1.0f);
    // V projection (single output)
    cvt_split<<<2048, 512>>>(value, pXhi, pXlo, NX4);
    cvt_single<<<512, 512>>>(Wv, pW, NW4);
    mma_proj<2><<<gp, 256, PROJ_SMEM>>>(tmXhi, tmXlo, tmW, bv, nullptr, pV, nullptr, 1.0f);
    // attention -> ctx hi/lo (directly into out-proj A buffers)
    attn_mma<<<ga, 256, AT_SMEM>>>(tmQh, tmQl, tmK, tmV, pXhi, pXlo);
    // output projection
    cvt_single<<<512, 512>>>(Wo, pW, NW4);
    mma_proj<0><<<gp, 256, PROJ_SMEM>>>(tmXhi, tmXlo, tmW, bo, out, nullptr, nullptr, 1.0f);
}

// round 9
// speedup vs baseline: 4.6529x; 1.0417x over previous
#include <cuda_runtime.h>
#include <cuda.h>
#include <cuda_fp16.h>
#include <cstdint>

#define D_MODEL 1024
#define NHEAD   16
#define HEAD_DIM 64
#define BATCH   4
#define SEQ     2048
#define M_TOT   (BATCH * SEQ)

// ---------------- scratch (static device memory; no allocations) ----------
__device__ __half g_Qh[BATCH * NHEAD * SEQ * HEAD_DIM];
__device__ __half g_Ql[BATCH * NHEAD * SEQ * HEAD_DIM];
__device__ __half g_K [BATCH * NHEAD * SEQ * HEAD_DIM];
__device__ __half g_V [BATCH * NHEAD * SEQ * HEAD_DIM];
__device__ __half g_Xq_hi[M_TOT * D_MODEL];   // also ctx hi after attn
__device__ __half g_Xq_lo[M_TOT * D_MODEL];   // also ctx lo after attn
__device__ __half g_Xk_hi[M_TOT * D_MODEL];
__device__ __half g_Xk_lo[M_TOT * D_MODEL];
__device__ __half g_Xv_hi[M_TOT * D_MODEL];
__device__ __half g_Xv_lo[M_TOT * D_MODEL];
__device__ __half g_Wq[D_MODEL * D_MODEL];
__device__ __half g_Wk[D_MODEL * D_MODEL];
__device__ __half g_Wv[D_MODEL * D_MODEL];
__device__ __half g_Wo[D_MODEL * D_MODEL];

typedef unsigned long long ull;

// ---------------- PTX helpers ---------------------------------------------
__device__ __forceinline__ uint32_t smem_u32(const void* p) {
    uint32_t a;
    asm("{ .reg .u64 t; cvta.to.shared.u64 t, %1; cvt.u32.u64 %0, t; }"
        : "=r"(a) : "l"(p));
    return a;
}
__device__ __forceinline__ void ldsm_x4(uint32_t* r, uint32_t a) {
    asm volatile("ldmatrix.sync.aligned.m8n8.x4.shared.b16 {%0,%1,%2,%3}, [%4];"
                 : "=r"(r[0]), "=r"(r[1]), "=r"(r[2]), "=r"(r[3]) : "r"(a));
}
__device__ __forceinline__ void ldsm_x4_t(uint32_t* r, uint32_t a) {
    asm volatile("ldmatrix.sync.aligned.m8n8.x4.trans.shared.b16 {%0,%1,%2,%3}, [%4];"
                 : "=r"(r[0]), "=r"(r[1]), "=r"(r[2]), "=r"(r[3]) : "r"(a));
}
#define MMA_F16(acc, a, b) \
    asm volatile("mma.sync.aligned.m16n8k16.row.col.f32.f16.f16.f32 " \
        "{%0,%1,%2,%3}, {%4,%5,%6,%7}, {%8,%9}, {%0,%1,%2,%3};" \
        : "+f"((acc)[0]), "+f"((acc)[1]), "+f"((acc)[2]), "+f"((acc)[3]) \
        : "r"((a)[0]), "r"((a)[1]), "r"((a)[2]), "r"((a)[3]), \
          "r"((b)[0]), "r"((b)[1]))

#define MBARRIER_INIT(addr, cnt) \
    asm volatile("mbarrier.init.shared.b64 [%0], %1;" :: "r"(addr), "r"(cnt) : "memory")
#define MBARRIER_EXPECT_TX(addr, bytes) \
    asm volatile("mbarrier.arrive.expect_tx.shared.b64 _, [%0], %1;" \
                 :: "r"(addr), "r"(bytes) : "memory")
#define MBARRIER_WAIT_PARITY(addr, parity) do { \
    uint32_t _m = (uint32_t)(addr); uint32_t _p = (uint32_t)(parity); uint32_t _d; \
    asm volatile("{\n\t.reg .pred p;\n\t" \
        "mbarrier.try_wait.parity.acquire.cta.shared::cta.b64 p, [%1], %2;\n\t" \
        "selp.b32 %0, 1, 0, p;\n\t}" : "=r"(_d) : "r"(_m), "r"(_p) : "memory"); \
    if (!_d) { \
        asm volatile("{\n\t.reg .pred P1;\n\t" \
            "WL_%=:\n\t" \
            "mbarrier.try_wait.parity.acquire.cta.shared::cta.b64 P1, [%0], %1, 0x989680;\n\t" \
            "@P1 bra.uni WD_%=;\n\t" \
            "bra.uni WL_%=;\n\t" \
            "WD_%=:\n\t}" :: "r"(_m), "r"(_p) : "memory"); \
    } } while (0)

#define TMA_LOAD_2D(smem_addr, tmap_ptr, cx, cy, mbar) \
    asm volatile("cp.async.bulk.tensor.2d.shared::cta.global.tile.mbarrier::complete_tx::bytes " \
        "[%0], [%1, {%2, %3}], [%4];" \
        :: "r"((uint32_t)(smem_addr)), "l"(tmap_ptr), "r"((int32_t)(cx)), "r"((int32_t)(cy)), \
           "r"((uint32_t)(mbar)) : "memory")

__device__ __forceinline__ uint32_t pkh(float x, float y) {
    __half2 hh = __floats2half2_rn(x, y);
    return *(uint32_t*)&hh;
}
__device__ __forceinline__ void split2h(float x, float y, uint32_t& h, uint32_t& l) {
    __half2 hh = __floats2half2_rn(x, y);
    float fx = __low2float(hh), fy = __high2float(hh);
    __half2 ll = __floats2half2_rn(x - fx, y - fy);
    h = *(uint32_t*)&hh;
    l = *(uint32_t*)&ll;
}
__device__ __forceinline__ float ex2(float x) {
    float y; asm("ex2.approx.ftz.f32 %0, %1;" : "=f"(y) : "f"(x)); return y;
}

// ---------------- batched fp32 -> fp16 conversions ------------------------
__global__ void __launch_bounds__(512)
cvt_split3(const float* __restrict__ x0, const float* __restrict__ x1,
           const float* __restrict__ x2,
           __half* __restrict__ h0, __half* __restrict__ l0_,
           __half* __restrict__ h1, __half* __restrict__ l1_,
           __half* __restrict__ h2, __half* __restrict__ l2_, int n4)
{
    const int seg = blockIdx.y;
    const float* x = seg == 0 ? x0 : (seg == 1 ? x1 : x2);
    __half* hi = seg == 0 ? h0 : (seg == 1 ? h1 : h2);
    __half* lo = seg == 0 ? l0_ : (seg == 1 ? l1_ : l2_);
    int i = blockIdx.x * blockDim.x + threadIdx.x;
    int stride = gridDim.x * blockDim.x;
    for (; i < n4; i += stride) {
        float4 v = ((const float4*)x)[i];
        uint32_t a0, b0, a1, b1;
        split2h(v.x, v.y, a0, b0);
        split2h(v.z, v.w, a1, b1);
        ((uint32_t*)hi)[2 * i] = a0;  ((uint32_t*)hi)[2 * i + 1] = a1;
        ((uint32_t*)lo)[2 * i] = b0;  ((uint32_t*)lo)[2 * i + 1] = b1;
    }
}
__global__ void __launch_bounds__(512)
cvt_single4(const float* __restrict__ x0, const float* __restrict__ x1,
            const float* __restrict__ x2, const float* __restrict__ x3,
            __half* __restrict__ w0, __half* __restrict__ w1,
            __half* __restrict__ w2, __half* __restrict__ w3, int n4)
{
    const int seg = blockIdx.y;
    const float* x = seg == 0 ? x0 : (seg == 1 ? x1 : (seg == 2 ? x2 : x3));
    __half* w = seg == 0 ? w0 : (seg == 1 ? w1 : (seg == 2 ? w2 : w3));
    int i = blockIdx.x * blockDim.x + threadIdx.x;
    int stride = gridDim.x * blockDim.x;
    for (; i < n4; i += stride) {
        float4 v = ((const float4*)x)[i];
        ((uint32_t*)w)[2 * i]     = pkh(v.x, v.y);
        ((uint32_t*)w)[2 * i + 1] = pkh(v.z, v.w);
    }
}

// ---------------- TMA projection GEMM (fp16 2-MMA: A split, B single) -----
#define KC          64
#define NCHUNKS     (D_MODEL / KC)
#define PSTAGES     3
#define RA_H        0
#define RA_L        16384
#define RB          32768
#define STAGE_BYTES 49152
#define PROJ_SMEM   (PSTAGES * STAGE_BYTES)

// Core GEMM body shared by both kernels.
// mode: 0 fp32 row-major out; 1 fp16 hi/lo head layout; 2 fp16 single head layout.
__device__ __forceinline__ void proj_body(
    const CUtensorMap* pAh, const CUtensorMap* pAl, const CUtensorMap* pB,
    const float* bias, float* out, __half* oh, __half* ol, float scale,
    int mode, int m0, int n0, uint32_t dyn0, uint32_t bar0)
{
    const int tid = threadIdx.x;
    const int wid = tid >> 5, lane = tid & 31;
    const int wm = (wid & 1) << 6, wn = (wid >> 1) << 5;

    if (tid == 0) {
        for (int s = 0; s < PSTAGES; ++s) MBARRIER_INIT(bar0 + s * 8, 1);
    }
    __syncthreads();

    auto issue = [&](int s, int kc) {
        const uint32_t sb = dyn0 + s * STAGE_BYTES;
        const uint32_t fb = bar0 + s * 8;
        MBARRIER_EXPECT_TX(fb, STAGE_BYTES);
        TMA_LOAD_2D(sb + RA_H, pAh, kc * KC, m0, fb);
        TMA_LOAD_2D(sb + RA_L, pAl, kc * KC, m0, fb);
        TMA_LOAD_2D(sb + RB,   pB,  kc * KC, n0, fb);
    };
    if (tid == 0) {
        for (int c = 0; c < PSTAGES; ++c) issue(c, c);
    }

    float acc[4][4][4];
#pragma unroll
    for (int i = 0; i < 4; ++i)
#pragma unroll
        for (int j = 0; j < 4; ++j)
#pragma unroll
            for (int q = 0; q < 4; ++q) acc[i][j][q] = 0.f;

    for (int kc = 0; kc < NCHUNKS; ++kc) {
        const int s = kc % PSTAGES;
        const int ph = (kc / PSTAGES) & 1;
        MBARRIER_WAIT_PARITY(bar0 + s * 8, ph);
        const uint32_t sb = dyn0 + s * STAGE_BYTES;

#pragma unroll
        for (int k16 = 0; k16 < 4; ++k16) {
            uint32_t ah[4][4], al[4][4], bh[2][4];
#pragma unroll
            for (int am = 0; am < 4; ++am) {
                const int rowA = wm + am * 16 + (lane & 15);
                const int g = k16 * 2 + (lane >> 4);
                const uint32_t off = (rowA << 7) + ((g ^ (rowA & 7)) << 4);
                ldsm_x4(ah[am], sb + RA_H + off);
                ldsm_x4(al[am], sb + RA_L + off);
            }
#pragma unroll
            for (int p = 0; p < 2; ++p) {
                const int rowB = wn + p * 16 + ((lane >> 4) << 3) + (lane & 7);
                const int g = k16 * 2 + ((lane >> 3) & 1);
                const uint32_t off = (rowB << 7) + ((g ^ (rowB & 7)) << 4);
                ldsm_x4(bh[p], sb + RB + off);
            }
#pragma unroll
            for (int am = 0; am < 4; ++am)
#pragma unroll
                for (int an = 0; an < 4; ++an) {
                    uint32_t* B0 = &bh[an >> 1][(an & 1) * 2];
                    MMA_F16(acc[am][an], ah[am], B0);
                    MMA_F16(acc[am][an], al[am], B0);
                }
        }
        __syncthreads();
        if (tid == 0 && kc + PSTAGES < NCHUNKS) issue(s, kc + PSTAGES);
    }

#pragma unroll
    for (int am = 0; am < 4; ++am) {
#pragma unroll
        for (int an = 0; an < 4; ++an) {
            const int m = m0 + wm + am * 16 + (lane >> 2);
            const int c = n0 + wn + an * 8 + ((lane & 3) << 1);
            const float2 bv = *(const float2*)&bias[c];
#pragma unroll
            for (int h2 = 0; h2 < 2; ++h2) {
                const int row = m + h2 * 8;
                float ox = (acc[am][an][2 * h2]     + bv.x) * scale;
                float oy = (acc[am][an][2 * h2 + 1] + bv.y) * scale;
                if (mode == 0) {
                    *(float2*)(out + (size_t)row * D_MODEL + c) = make_float2(ox, oy);
                } else {
                    const int b = row >> 11, srow = row & (SEQ - 1);
                    const int hh = c >> 6, dh = c & 63;
                    const size_t idx = (((size_t)(b * NHEAD + hh) * SEQ + srow) * HEAD_DIM + dh);
                    if (mode == 1) {
                        uint32_t h, l;
                        split2h(ox, oy, h, l);
                        *(uint32_t*)(oh + idx) = h;
                        *(uint32_t*)(ol + idx) = l;
                    } else {
                        *(uint32_t*)(oh + idx) = pkh(ox, oy);
                    }
                }
            }
        }
    }
}

// Fused Q/K/V projection: z selects input/weight/bias/output/mode.
__global__ void __launch_bounds__(256)
qkv_proj(const __grid_constant__ CUtensorMap tmQxh, const __grid_constant__ CUtensorMap tmQxl,
         const __grid_constant__ CUtensorMap tmKxh, const __grid_constant__ CUtensorMap tmKxl,
         const __grid_constant__ CUtensorMap tmVxh, const __grid_constant__ CUtensorMap tmVxl,
         const __grid_constant__ CUtensorMap tmWq,  const __grid_constant__ CUtensorMap tmWk,
         const __grid_constant__ CUtensorMap tmWv,
         const float* __restrict__ bq, const float* __restrict__ bk,
         const float* __restrict__ bv,
         __half* __restrict__ oQh, __half* __restrict__ oQl,
         __half* __restrict__ oK,  __half* __restrict__ oV, float qscale)
{
    extern __shared__ __align__(1024) char smem[];
    __shared__ __align__(8) ull s_bar[PSTAGES];
    const uint32_t dyn0 = smem_u32(smem);
    const uint32_t bar0 = smem_u32(s_bar);
    const int m0 = blockIdx.y << 7, n0 = blockIdx.x << 7;
    const int z = blockIdx.z;

    const CUtensorMap* pAh = z == 0 ? &tmQxh : (z == 1 ? &tmKxh : &tmVxh);
    const CUtensorMap* pAl = z == 0 ? &tmQxl : (z == 1 ? &tmKxl : &tmVxl);
    const CUtensorMap* pB  = z == 0 ? &tmWq  : (z == 1 ? &tmWk  : &tmWv);
    const float* bias = z == 0 ? bq : (z == 1 ? bk : bv);
    __half* oh = z == 0 ? oQh : (z == 1 ? oK : oV);
    __half* ol = z == 0 ? oQl : nullptr;
    const float scale = z == 0 ? qscale : 1.0f;
    const int mode = z == 0 ? 1 : 2;

    proj_body(pAh, pAl, pB, bias, nullptr, oh, ol, scale, mode, m0, n0, dyn0, bar0);
}

// Output projection: fp32 out.
__global__ void __launch_bounds__(256)
out_proj(const __grid_constant__ CUtensorMap tmAh, const __grid_constant__ CUtensorMap tmAl,
         const __grid_constant__ CUtensorMap tmB,
         const float* __restrict__ bias, float* __restrict__ out)
{
    extern __shared__ __align__(1024) char smem[];
    __shared__ __align__(8) ull s_bar[PSTAGES];
    proj_body(&tmAh, &tmAl, &tmB, bias, out, nullptr, nullptr, 1.0f, 0,
              blockIdx.y << 7, blockIdx.x << 7, smem_u32(smem), smem_u32(s_bar));
}

// ---------------- TMA causal flash attention (fp16 2-MMA) -----------------
#define KVSTAGES 4
#define KV0      32768
#define KVSB     16384
#define AT_SMEM  (KV0 + KVSTAGES * KVSB)

__global__ void __launch_bounds__(256)
attn_mma(const __grid_constant__ CUtensorMap tmQh, const __grid_constant__ CUtensorMap tmQl,
         const __grid_constant__ CUtensorMap tmK,  const __grid_constant__ CUtensorMap tmV,
         __half* __restrict__ Ch, __half* __restrict__ Cl)
{
    extern __shared__ __align__(1024) char smem[];
    __shared__ __align__(8) ull s_bar[1 + KVSTAGES];
    const uint32_t dyn0 = smem_u32(smem);
    const uint32_t barq = smem_u32(s_bar);
    const uint32_t bark = barq + 8;

    const int tid = threadIdx.x, wid = tid >> 5, lane = tid & 31;
    const int bx = (int)gridDim.x - 1 - (int)blockIdx.x;   // big tiles first
    const int bh = blockIdx.y;
    const int q0 = bx << 7;
    const int yb = bh * SEQ;
    const int ktend = 2 * bx + 2;

    if (tid == 0) {
        MBARRIER_INIT(barq, 1);
        for (int s = 0; s < KVSTAGES; ++s) MBARRIER_INIT(bark + s * 8, 1);
    }
    __syncthreads();

    auto issue_kv = [&](int s, int kt) {
        const uint32_t sb = dyn0 + KV0 + s * KVSB;
        const uint32_t fb = bark + s * 8;
        const int y = yb + kt * 64;
        MBARRIER_EXPECT_TX(fb, KVSB);
        TMA_LOAD_2D(sb,        &tmK, 0, y, fb);
        TMA_LOAD_2D(sb + 8192, &tmV, 0, y, fb);
    };
    if (tid == 0) {
        MBARRIER_EXPECT_TX(barq, 32768);
        TMA_LOAD_2D(dyn0,         &tmQh, 0, yb + q0, barq);
        TMA_LOAD_2D(dyn0 + 16384, &tmQl, 0, yb + q0, barq);
        const int np = ktend < KVSTAGES ? ktend : KVSTAGES;
        for (int p = 0; p < np; ++p) issue_kv(p, p);
    }

    MBARRIER_WAIT_PARITY(barq, 0);
    uint32_t qh[4][4], ql[4][4];
#pragma unroll
    for (int k16 = 0; k16 < 4; ++k16) {
        const int rowA = wid * 16 + (lane & 15);
        const int g = k16 * 2 + (lane >> 4);
        const uint32_t off = (rowA << 7) + ((g ^ (rowA & 7)) << 4);
        ldsm_x4(qh[k16], dyn0 + off);
        ldsm_x4(ql[k16], dyn0 + 16384 + off);
    }

    float O[8][4];
#pragma unroll
    for (int j = 0; j < 8; ++j)
#pragma unroll
        for (int q = 0; q < 4; ++q) O[j][q] = 0.f;
    float m0 = -1e30f, m1 = -1e30f, l0 = 0.f, l1 = 0.f;

    const int rrow = lane >> 2;
    const int ccol = (lane & 3) << 1;

    for (int kt = 0; kt < ktend; ++kt) {
        const int s = kt % KVSTAGES;
        const int ph = (kt / KVSTAGES) & 1;
        MBARRIER_WAIT_PARITY(bark + s * 8, ph);
        const uint32_t sb = dyn0 + KV0 + s * KVSB;

        const bool active = (kt * 64 <= q0 + wid * 16 + 15);
        if (active) {
            float S[8][4];
#pragma unroll
            for (int j = 0; j < 8; ++j)
#pragma unroll
                for (int q = 0; q < 4; ++q) S[j][q] = 0.f;
#pragma unroll
            for (int p = 0; p < 4; ++p) {
#pragma unroll
                for (int k16 = 0; k16 < 4; ++k16) {
                    uint32_t bkh[4];
                    const int rowB = p * 16 + ((lane >> 4) << 3) + (lane & 7);
                    const int g = k16 * 2 + ((lane >> 3) & 1);
                    const uint32_t off = (rowB << 7) + ((g ^ (rowB & 7)) << 4);
                    ldsm_x4(bkh, sb + off);
                    MMA_F16(S[2 * p],     qh[k16], &bkh[0]);
                    MMA_F16(S[2 * p],     ql[k16], &bkh[0]);
                    MMA_F16(S[2 * p + 1], qh[k16], &bkh[2]);
                    MMA_F16(S[2 * p + 1], ql[k16], &bkh[2]);
                }
            }

            if (kt >= 2 * bx) {
                const int r0g = q0 + wid * 16 + rrow;
#pragma unroll
                for (int jt = 0; jt < 8; ++jt) {
                    const int cg = kt * 64 + jt * 8 + ccol;
                    if (cg     > r0g)     S[jt][0] = -1e30f;
                    if (cg + 1 > r0g)     S[jt][1] = -1e30f;
                    if (cg     > r0g + 8) S[jt][2] = -1e30f;
                    if (cg + 1 > r0g + 8) S[jt][3] = -1e30f;
                }
            }

            float mx0 = -1e30f, mx1 = -1e30f;
#pragma unroll
            for (int jt = 0; jt < 8; ++jt) {
                mx0 = fmaxf(mx0, fmaxf(S[jt][0], S[jt][1]));
                mx1 = fmaxf(mx1, fmaxf(S[jt][2], S[jt][3]));
            }
            mx0 = fmaxf(mx0, __shfl_xor_sync(0xffffffffu, mx0, 1));
            mx0 = fmaxf(mx0, __shfl_xor_sync(0xffffffffu, mx0, 2));
            mx1 = fmaxf(mx1, __shfl_xor_sync(0xffffffffu, mx1, 1));
            mx1 = fmaxf(mx1, __shfl_xor_sync(0xffffffffu, mx1, 2));
            const float nm0 = fmaxf(m0, mx0), nm1 = fmaxf(m1, mx1);
            const float a0 = ex2(m0 - nm0), a1 = ex2(m1 - nm1);
            m0 = nm0; m1 = nm1;
            float s0 = 0.f, s1 = 0.f;
#pragma unroll
            for (int jt = 0; jt < 8; ++jt) {
                S[jt][0] = ex2(S[jt][0] - m0);
                S[jt][1] = ex2(S[jt][1] - m0);
                S[jt][2] = ex2(S[jt][2] - m1);
                S[jt][3] = ex2(S[jt][3] - m1);
                s0 += S[jt][0] + S[jt][1];
                s1 += S[jt][2] + S[jt][3];
            }
            s0 += __shfl_xor_sync(0xffffffffu, s0, 1);
            s0 += __shfl_xor_sync(0xffffffffu, s0, 2);
            s1 += __shfl_xor_sync(0xffffffffu, s1, 1);
            s1 += __shfl_xor_sync(0xffffffffu, s1, 2);
            l0 = l0 * a0 + s0;
            l1 = l1 * a1 + s1;
#pragma unroll
            for (int jt = 0; jt < 8; ++jt) {
                O[jt][0] *= a0; O[jt][1] *= a0;
                O[jt][2] *= a1; O[jt][3] *= a1;
            }

            uint32_t pfh[4][4], pfl[4][4];
#pragma unroll
            for (int kk = 0; kk < 4; ++kk) {
                split2h(S[2 * kk][0],     S[2 * kk][1],     pfh[kk][0], pfl[kk][0]);
                split2h(S[2 * kk][2],     S[2 * kk][3],     pfh[kk][1], pfl[kk][1]);
                split2h(S[2 * kk + 1][0], S[2 * kk + 1][1], pfh[kk][2], pfl[kk][2]);
                split2h(S[2 * kk + 1][2], S[2 * kk + 1][3], pfh[kk][3], pfl[kk][3]);
            }

#pragma unroll
            for (int p = 0; p < 4; ++p) {
#pragma unroll
                for (int kk = 0; kk < 4; ++kk) {
                    uint32_t vh[4];
                    const int key = kk * 16 + ((lane >> 3) & 1) * 8 + (lane & 7);
                    const int nt = 2 * p + (lane >> 4);
                    const uint32_t off = (key << 7) + (((nt) ^ (key & 7)) << 4);
                    ldsm_x4_t(vh, sb + 8192 + off);
                    MMA_F16(O[2 * p],     pfh[kk], &vh[0]);
                    MMA_F16(O[2 * p],     pfl[kk], &vh[0]);
                    MMA_F16(O[2 * p + 1], pfh[kk], &vh[2]);
                    MMA_F16(O[2 * p + 1], pfl[kk], &vh[2]);
                }
            }
        }
        __syncthreads();
        if (tid == 0 && kt + KVSTAGES < ktend) issue_kv(s, kt + KVSTAGES);
    }

    const float inv0 = 1.f / l0, inv1 = 1.f / l1;
    const int b = bh >> 4, h = bh & 15;
    const int r0g = q0 + wid * 16 + rrow;
    const size_t mi0 = ((size_t)b * SEQ + r0g) * D_MODEL + h * 64;
    const size_t mi1 = ((size_t)b * SEQ + r0g + 8) * D_MODEL + h * 64;
#pragma unroll
    for (int jt = 0; jt < 8; ++jt) {
        const int c = jt * 8 + ccol;
        uint32_t hh, ll;
        split2h(O[jt][0] * inv0, O[jt][1] * inv0, hh, ll);
        *(uint32_t*)(Ch + mi0 + c) = hh;
        *(uint32_t*)(Cl + mi0 + c) = ll;
        split2h(O[jt][2] * inv1, O[jt][3] * inv1, hh, ll);
        *(uint32_t*)(Ch + mi1 + c) = hh;
        *(uint32_t*)(Cl + mi1 + c) = ll;
    }
}

// ---------------- host-side tensor maps -----------------------------------
typedef CUresult (*EncodeFn)(CUtensorMap*, CUtensorMapDataType, cuuint32_t, void*,
                             const cuuint64_t*, const cuuint64_t*, const cuuint32_t*,
                             const cuuint32_t*, CUtensorMapInterleave, CUtensorMapSwizzle,
                             CUtensorMapL2promotion, CUtensorMapFloatOOBfill);

static void make_map(EncodeFn enc, CUtensorMap* m, void* base,
                     uint64_t d0, uint64_t d1, uint32_t box_rows)
{
    cuuint64_t dims[2] = {d0, d1};
    cuuint64_t strides[1] = {d0 * 2};
    cuuint32_t box[2] = {64u, box_rows};
    cuuint32_t es[2] = {1u, 1u};
    enc(m, CU_TENSOR_MAP_DATA_TYPE_FLOAT16, 2, base, dims, strides, box, es,
        CU_TENSOR_MAP_INTERLEAVE_NONE, CU_TENSOR_MAP_SWIZZLE_128B,
        CU_TENSOR_MAP_L2_PROMOTION_L2_128B, CU_TENSOR_MAP_FLOAT_OOB_FILL_NONE);
}

// ---------------- launcher -------------------------------------------------
extern "C" void kernel_launch(void* const* d_in, const int* in_sizes, int n_in,
                              void* d_out, int out_size)
{
    const float* query = (const float*)d_in[0];
    const float* key_  = (const float*)d_in[1];
    const float* value = (const float*)d_in[2];
    const float* Wq = (const float*)d_in[4];
    const float* bq = (const float*)d_in[5];
    const float* Wk = (const float*)d_in[6];
    const float* bk = (const float*)d_in[7];
    const float* Wv = (const float*)d_in[8];
    const float* bv = (const float*)d_in[9];
    const float* Wo = (const float*)d_in[10];
    const float* bo = (const float*)d_in[11];
    float* out = (float*)d_out;

    __half *pQh, *pQl, *pK, *pV;
    __half *pXqh, *pXql, *pXkh, *pXkl, *pXvh, *pXvl;
    __half *pWq, *pWk, *pWv, *pWo;
    cudaGetSymbolAddress((void**)&pQh, g_Qh);
    cudaGetSymbolAddress((void**)&pQl, g_Ql);
    cudaGetSymbolAddress((void**)&pK, g_K);
    cudaGetSymbolAddress((void**)&pV, g_V);
    cudaGetSymbolAddress((void**)&pXqh, g_Xq_hi);
    cudaGetSymbolAddress((void**)&pXql, g_Xq_lo);
    cudaGetSymbolAddress((void**)&pXkh, g_Xk_hi);
    cudaGetSymbolAddress((void**)&pXkl, g_Xk_lo);
    cudaGetSymbolAddress((void**)&pXvh, g_Xv_hi);
    cudaGetSymbolAddress((void**)&pXvl, g_Xv_lo);
    cudaGetSymbolAddress((void**)&pWq, g_Wq);
    cudaGetSymbolAddress((void**)&pWk, g_Wk);
    cudaGetSymbolAddress((void**)&pWv, g_Wv);
    cudaGetSymbolAddress((void**)&pWo, g_Wo);

    void* encp = nullptr;
    cudaDriverEntryPointQueryResult qr;
    cudaGetDriverEntryPointByVersion("cuTensorMapEncodeTiled", &encp, 12000,
                                     cudaEnableDefault, &qr);
    EncodeFn enc = (EncodeFn)encp;

    const uint64_t NR = (uint64_t)BATCH * NHEAD * SEQ;
    CUtensorMap tmXqh, tmXql, tmXkh, tmXkl, tmXvh, tmXvl;
    CUtensorMap tmWq, tmWk, tmWv, tmWo, tmQh, tmQl, tmK, tmV;
    make_map(enc, &tmXqh, pXqh, D_MODEL, M_TOT, 128);
    make_map(enc, &tmXql, pXql, D_MODEL, M_TOT, 128);
    make_map(enc, &tmXkh, pXkh, D_MODEL, M_TOT, 128);
    make_map(enc, &tmXkl, pXkl, D_MODEL, M_TOT, 128);
    make_map(enc, &tmXvh, pXvh, D_MODEL, M_TOT, 128);
    make_map(enc, &tmXvl, pXvl, D_MODEL, M_TOT, 128);
    make_map(enc, &tmWq, pWq, D_MODEL, D_MODEL, 128);
    make_map(enc, &tmWk, pWk, D_MODEL, D_MODEL, 128);
    make_map(enc, &tmWv, pWv, D_MODEL, D_MODEL, 128);
    make_map(enc, &tmWo, pWo, D_MODEL, D_MODEL, 128);
    make_map(enc, &tmQh, pQh, HEAD_DIM, NR, 128);
    make_map(enc, &tmQl, pQl, HEAD_DIM, NR, 128);
    make_map(enc, &tmK,  pK,  HEAD_DIM, NR, 64);
    make_map(enc, &tmV,  pV,  HEAD_DIM, NR, 64);

    cudaFuncSetAttribute(qkv_proj, cudaFuncAttributeMaxDynamicSharedMemorySize, PROJ_SMEM);
    cudaFuncSetAttribute(out_proj, cudaFuncAttributeMaxDynamicSharedMemorySize, PROJ_SMEM);
    cudaFuncSetAttribute(attn_mma, cudaFuncAttributeMaxDynamicSharedMemorySize, AT_SMEM);

    const int NX4 = (M_TOT * D_MODEL) / 4;
    const int NW4 = (D_MODEL * D_MODEL) / 4;
    dim3 gcs(1024, 3);                         // cvt_split3
    dim3 gcw(512, 4);                          // cvt_single4
    dim3 gp3(D_MODEL / 128, M_TOT / 128, 3);   // (8, 64, 3)
    dim3 gp(D_MODEL / 128, M_TOT / 128);       // (8, 64)
    dim3 ga(SEQ / 128, BATCH * NHEAD);         // (16, 64)
    const float qscale = 0.125f * 1.4426950408889634f;  // 1/sqrt(64) * log2(e)

    cvt_split3<<<gcs, 512>>>(query, key_, value, pXqh, pXql, pXkh, pXkl, pXvh, pXvl, NX4);
    cvt_single4<<<gcw, 512>>>(Wq, Wk, Wv, Wo, pWq, pWk, pWv, pWo, NW4);
    qkv_proj<<<gp3, 256, PROJ_SMEM>>>(tmXqh, tmXql, tmXkh, tmXkl, tmXvh, tmXvl,
                                      tmWq, tmWk, tmWv, bq, bk, bv,
                                      pQh, pQl, pK, pV, qscale);
    attn_mma<<<ga, 256, AT_SMEM>>>(tmQh, tmQl, tmK, tmV, pXqh, pXql);
    out_proj<<<gp, 256, PROJ_SMEM>>>(tmXqh, tmXql, tmWo, bo, out);
}

// round 10
// speedup vs baseline: 4.9097x; 1.0552x over previous
#include <cuda_runtime.h>
#include <cuda.h>
#include <cuda_fp16.h>
#include <cstdint>

#define D_MODEL 1024
#define NHEAD   16
#define HEAD_DIM 64
#define BATCH   4
#define SEQ     2048
#define M_TOT   (BATCH * SEQ)

// ---------------- scratch (static device memory; no allocations) ----------
__device__ __half g_Qh[BATCH * NHEAD * SEQ * HEAD_DIM];
__device__ __half g_Ql[BATCH * NHEAD * SEQ * HEAD_DIM];
__device__ __half g_K [BATCH * NHEAD * SEQ * HEAD_DIM];
__device__ __half g_V [BATCH * NHEAD * SEQ * HEAD_DIM];
__device__ __half g_Xq_hi[M_TOT * D_MODEL];   // also ctx hi after attn
__device__ __half g_Xq_lo[M_TOT * D_MODEL];   // also ctx lo after attn
__device__ __half g_Xk_hi[M_TOT * D_MODEL];
__device__ __half g_Xk_lo[M_TOT * D_MODEL];
__device__ __half g_Xv_hi[M_TOT * D_MODEL];
__device__ __half g_Xv_lo[M_TOT * D_MODEL];
__device__ __half g_Wq[D_MODEL * D_MODEL];
__device__ __half g_Wk[D_MODEL * D_MODEL];
__device__ __half g_Wv[D_MODEL * D_MODEL];
__device__ __half g_Wo[D_MODEL * D_MODEL];

typedef unsigned long long ull;

// ---------------- PTX helpers ---------------------------------------------
__device__ __forceinline__ uint32_t smem_u32(const void* p) {
    uint32_t a;
    asm("{ .reg .u64 t; cvta.to.shared.u64 t, %1; cvt.u32.u64 %0, t; }"
        : "=r"(a) : "l"(p));
    return a;
}
__device__ __forceinline__ void ldsm_x4(uint32_t* r, uint32_t a) {
    asm volatile("ldmatrix.sync.aligned.m8n8.x4.shared.b16 {%0,%1,%2,%3}, [%4];"
                 : "=r"(r[0]), "=r"(r[1]), "=r"(r[2]), "=r"(r[3]) : "r"(a));
}
__device__ __forceinline__ void ldsm_x4_t(uint32_t* r, uint32_t a) {
    asm volatile("ldmatrix.sync.aligned.m8n8.x4.trans.shared.b16 {%0,%1,%2,%3}, [%4];"
                 : "=r"(r[0]), "=r"(r[1]), "=r"(r[2]), "=r"(r[3]) : "r"(a));
}
#define MMA_F16(acc, a, b) \
    asm volatile("mma.sync.aligned.m16n8k16.row.col.f32.f16.f16.f32 " \
        "{%0,%1,%2,%3}, {%4,%5,%6,%7}, {%8,%9}, {%0,%1,%2,%3};" \
        : "+f"((acc)[0]), "+f"((acc)[1]), "+f"((acc)[2]), "+f"((acc)[3]) \
        : "r"((a)[0]), "r"((a)[1]), "r"((a)[2]), "r"((a)[3]), \
          "r"((b)[0]), "r"((b)[1]))

#define MBARRIER_INIT(addr, cnt) \
    asm volatile("mbarrier.init.shared.b64 [%0], %1;" :: "r"(addr), "r"(cnt) : "memory")
#define MBARRIER_EXPECT_TX(addr, bytes) \
    asm volatile("mbarrier.arrive.expect_tx.shared.b64 _, [%0], %1;" \
                 :: "r"(addr), "r"(bytes) : "memory")
#define MBARRIER_WAIT_PARITY(addr, parity) do { \
    uint32_t _m = (uint32_t)(addr); uint32_t _p = (uint32_t)(parity); uint32_t _d; \
    asm volatile("{\n\t.reg .pred p;\n\t" \
        "mbarrier.try_wait.parity.acquire.cta.shared::cta.b64 p, [%1], %2;\n\t" \
        "selp.b32 %0, 1, 0, p;\n\t}" : "=r"(_d) : "r"(_m), "r"(_p) : "memory"); \
    if (!_d) { \
        asm volatile("{\n\t.reg .pred P1;\n\t" \
            "WL_%=:\n\t" \
            "mbarrier.try_wait.parity.acquire.cta.shared::cta.b64 P1, [%0], %1, 0x989680;\n\t" \
            "@P1 bra.uni WD_%=;\n\t" \
            "bra.uni WL_%=;\n\t" \
            "WD_%=:\n\t}" :: "r"(_m), "r"(_p) : "memory"); \
    } } while (0)

#define TMA_LOAD_2D(smem_addr, tmap_ptr, cx, cy, mbar) \
    asm volatile("cp.async.bulk.tensor.2d.shared::cta.global.tile.mbarrier::complete_tx::bytes " \
        "[%0], [%1, {%2, %3}], [%4];" \
        :: "r"((uint32_t)(smem_addr)), "l"(tmap_ptr), "r"((int32_t)(cx)), "r"((int32_t)(cy)), \
           "r"((uint32_t)(mbar)) : "memory")

__device__ __forceinline__ uint32_t pkh(float x, float y) {
    __half2 hh = __floats2half2_rn(x, y);
    return *(uint32_t*)&hh;
}
__device__ __forceinline__ void split2h(float x, float y, uint32_t& h, uint32_t& l) {
    __half2 hh = __floats2half2_rn(x, y);
    float fx = __low2float(hh), fy = __high2float(hh);
    __half2 ll = __floats2half2_rn(x - fx, y - fy);
    h = *(uint32_t*)&hh;
    l = *(uint32_t*)&ll;
}
__device__ __forceinline__ float ex2(float x) {
    float y; asm("ex2.approx.ftz.f32 %0, %1;" : "=f"(y) : "f"(x)); return y;
}

// ---------------- batched fp32 -> fp16 conversions ------------------------
__global__ void __launch_bounds__(512)
cvt_split3(const float* __restrict__ x0, const float* __restrict__ x1,
           const float* __restrict__ x2,
           __half* __restrict__ h0, __half* __restrict__ l0_,
           __half* __restrict__ h1, __half* __restrict__ l1_,
           __half* __restrict__ h2, __half* __restrict__ l2_, int n4)
{
    const int seg = blockIdx.y;
    const float* x = seg == 0 ? x0 : (seg == 1 ? x1 : x2);
    __half* hi = seg == 0 ? h0 : (seg == 1 ? h1 : h2);
    __half* lo = seg == 0 ? l0_ : (seg == 1 ? l1_ : l2_);
    int i = blockIdx.x * blockDim.x + threadIdx.x;
    int stride = gridDim.x * blockDim.x;
    for (; i < n4; i += stride) {
        float4 v = ((const float4*)x)[i];
        uint32_t a0, b0, a1, b1;
        split2h(v.x, v.y, a0, b0);
        split2h(v.z, v.w, a1, b1);
        ((uint32_t*)hi)[2 * i] = a0;  ((uint32_t*)hi)[2 * i + 1] = a1;
        ((uint32_t*)lo)[2 * i] = b0;  ((uint32_t*)lo)[2 * i + 1] = b1;
    }
}
__global__ void __launch_bounds__(512)
cvt_single4(const float* __restrict__ x0, const float* __restrict__ x1,
            const float* __restrict__ x2, const float* __restrict__ x3,
            __half* __restrict__ w0, __half* __restrict__ w1,
            __half* __restrict__ w2, __half* __restrict__ w3, int n4)
{
    const int seg = blockIdx.y;
    const float* x = seg == 0 ? x0 : (seg == 1 ? x1 : (seg == 2 ? x2 : x3));
    __half* w = seg == 0 ? w0 : (seg == 1 ? w1 : (seg == 2 ? w2 : w3));
    int i = blockIdx.x * blockDim.x + threadIdx.x;
    int stride = gridDim.x * blockDim.x;
    for (; i < n4; i += stride) {
        float4 v = ((const float4*)x)[i];
        ((uint32_t*)w)[2 * i]     = pkh(v.x, v.y);
        ((uint32_t*)w)[2 * i + 1] = pkh(v.z, v.w);
    }
}

// ---------------- TMA projection GEMM (fp16 2-MMA: A split, B single) -----
#define KC          64
#define NCHUNKS     (D_MODEL / KC)
#define PSTAGES     3
#define RA_H        0
#define RA_L        16384
#define RB          32768
#define STAGE_BYTES 49152
#define PROJ_SMEM   (PSTAGES * STAGE_BYTES)

// mode: 0 fp32 row-major out; 1 fp16 hi/lo head layout; 2 fp16 single head layout.
__device__ __forceinline__ void proj_body(
    const CUtensorMap* pAh, const CUtensorMap* pAl, const CUtensorMap* pB,
    const float* bias, float* out, __half* oh, __half* ol, float scale,
    int mode, int m0, int n0, uint32_t dyn0, uint32_t bar0)
{
    const int tid = threadIdx.x;
    const int wid = tid >> 5, lane = tid & 31;
    const int wm = (wid & 1) << 6, wn = (wid >> 1) << 5;

    if (tid == 0) {
        for (int s = 0; s < PSTAGES; ++s) MBARRIER_INIT(bar0 + s * 8, 1);
    }
    __syncthreads();

    auto issue = [&](int s, int kc) {
        const uint32_t sb = dyn0 + s * STAGE_BYTES;
        const uint32_t fb = bar0 + s * 8;
        MBARRIER_EXPECT_TX(fb, STAGE_BYTES);
        TMA_LOAD_2D(sb + RA_H, pAh, kc * KC, m0, fb);
        TMA_LOAD_2D(sb + RA_L, pAl, kc * KC, m0, fb);
        TMA_LOAD_2D(sb + RB,   pB,  kc * KC, n0, fb);
    };
    if (tid == 0) {
        for (int c = 0; c < PSTAGES; ++c) issue(c, c);
    }

    float acc[4][4][4];
#pragma unroll
    for (int i = 0; i < 4; ++i)
#pragma unroll
        for (int j = 0; j < 4; ++j)
#pragma unroll
            for (int q = 0; q < 4; ++q) acc[i][j][q] = 0.f;

    for (int kc = 0; kc < NCHUNKS; ++kc) {
        const int s = kc % PSTAGES;
        const int ph = (kc / PSTAGES) & 1;
        MBARRIER_WAIT_PARITY(bar0 + s * 8, ph);
        const uint32_t sb = dyn0 + s * STAGE_BYTES;

#pragma unroll
        for (int k16 = 0; k16 < 4; ++k16) {
            uint32_t ah[4][4], al[4][4], bh[2][4];
#pragma unroll
            for (int am = 0; am < 4; ++am) {
                const int rowA = wm + am * 16 + (lane & 15);
                const int g = k16 * 2 + (lane >> 4);
                const uint32_t off = (rowA << 7) + ((g ^ (rowA & 7)) << 4);
                ldsm_x4(ah[am], sb + RA_H + off);
                ldsm_x4(al[am], sb + RA_L + off);
            }
#pragma unroll
            for (int p = 0; p < 2; ++p) {
                const int rowB = wn + p * 16 + ((lane >> 4) << 3) + (lane & 7);
                const int g = k16 * 2 + ((lane >> 3) & 1);
                const uint32_t off = (rowB << 7) + ((g ^ (rowB & 7)) << 4);
                ldsm_x4(bh[p], sb + RB + off);
            }
#pragma unroll
            for (int am = 0; am < 4; ++am)
#pragma unroll
                for (int an = 0; an < 4; ++an) {
                    uint32_t* B0 = &bh[an >> 1][(an & 1) * 2];
                    MMA_F16(acc[am][an], ah[am], B0);
                    MMA_F16(acc[am][an], al[am], B0);
                }
        }
        __syncthreads();
        if (tid == 0 && kc + PSTAGES < NCHUNKS) issue(s, kc + PSTAGES);
    }

#pragma unroll
    for (int am = 0; am < 4; ++am) {
#pragma unroll
        for (int an = 0; an < 4; ++an) {
            const int m = m0 + wm + am * 16 + (lane >> 2);
            const int c = n0 + wn + an * 8 + ((lane & 3) << 1);
            const float2 bv = *(const float2*)&bias[c];
#pragma unroll
            for (int h2 = 0; h2 < 2; ++h2) {
                const int row = m + h2 * 8;
                float ox = (acc[am][an][2 * h2]     + bv.x) * scale;
                float oy = (acc[am][an][2 * h2 + 1] + bv.y) * scale;
                if (mode == 0) {
                    *(float2*)(out + (size_t)row * D_MODEL + c) = make_float2(ox, oy);
                } else {
                    const int b = row >> 11, srow = row & (SEQ - 1);
                    const int hh = c >> 6, dh = c & 63;
                    const size_t idx = (((size_t)(b * NHEAD + hh) * SEQ + srow) * HEAD_DIM + dh);
                    if (mode == 1) {
                        uint32_t h, l;
                        split2h(ox, oy, h, l);
                        *(uint32_t*)(oh + idx) = h;
                        *(uint32_t*)(ol + idx) = l;
                    } else {
                        *(uint32_t*)(oh + idx) = pkh(ox, oy);
                    }
                }
            }
        }
    }
}

// Fused Q/K/V projection: z selects input/weight/bias/output/mode.
__global__ void __launch_bounds__(256)
qkv_proj(const __grid_constant__ CUtensorMap tmQxh, const __grid_constant__ CUtensorMap tmQxl,
         const __grid_constant__ CUtensorMap tmKxh, const __grid_constant__ CUtensorMap tmKxl,
         const __grid_constant__ CUtensorMap tmVxh, const __grid_constant__ CUtensorMap tmVxl,
         const __grid_constant__ CUtensorMap tmWq,  const __grid_constant__ CUtensorMap tmWk,
         const __grid_constant__ CUtensorMap tmWv,
         const float* __restrict__ bq, const float* __restrict__ bk,
         const float* __restrict__ bv,
         __half* __restrict__ oQh, __half* __restrict__ oQl,
         __half* __restrict__ oK,  __half* __restrict__ oV, float qscale)
{
    extern __shared__ __align__(1024) char smem[];
    __shared__ __align__(8) ull s_bar[PSTAGES];
    const uint32_t dyn0 = smem_u32(smem);
    const uint32_t bar0 = smem_u32(s_bar);
    const int m0 = blockIdx.y << 7, n0 = blockIdx.x << 7;
    const int z = blockIdx.z;

    const CUtensorMap* pAh = z == 0 ? &tmQxh : (z == 1 ? &tmKxh : &tmVxh);
    const CUtensorMap* pAl = z == 0 ? &tmQxl : (z == 1 ? &tmKxl : &tmVxl);
    const CUtensorMap* pB  = z == 0 ? &tmWq  : (z == 1 ? &tmWk  : &tmWv);
    const float* bias = z == 0 ? bq : (z == 1 ? bk : bv);
    __half* oh = z == 0 ? oQh : (z == 1 ? oK : oV);
    __half* ol = z == 0 ? oQl : nullptr;
    const float scale = z == 0 ? qscale : 1.0f;
    const int mode = z == 0 ? 1 : 2;

    proj_body(pAh, pAl, pB, bias, nullptr, oh, ol, scale, mode, m0, n0, dyn0, bar0);
}

// Output projection: fp32 out.
__global__ void __launch_bounds__(256)
out_proj(const __grid_constant__ CUtensorMap tmAh, const __grid_constant__ CUtensorMap tmAl,
         const __grid_constant__ CUtensorMap tmB,
         const float* __restrict__ bias, float* __restrict__ out)
{
    extern __shared__ __align__(1024) char smem[];
    __shared__ __align__(8) ull s_bar[PSTAGES];
    proj_body(&tmAh, &tmAl, &tmB, bias, out, nullptr, nullptr, 1.0f, 0,
              blockIdx.y << 7, blockIdx.x << 7, smem_u32(smem), smem_u32(s_bar));
}

// ---------------- TMA causal flash attention (fp16 2-MMA) -----------------
// 2 CTAs/SM: regs capped at 128, smem 64KB/CTA (Q 32KB + 2 KV stages x 16KB).
#define KVSTAGES 2
#define KV0      32768
#define KVSB     16384
#define AT_SMEM  (KV0 + KVSTAGES * KVSB)

__global__ void __launch_bounds__(256, 2)
attn_mma(const __grid_constant__ CUtensorMap tmQh, const __grid_constant__ CUtensorMap tmQl,
         const __grid_constant__ CUtensorMap tmK,  const __grid_constant__ CUtensorMap tmV,
         __half* __restrict__ Ch, __half* __restrict__ Cl)
{
    extern __shared__ __align__(1024) char smem[];
    __shared__ __align__(8) ull s_bar[1 + KVSTAGES];
    const uint32_t dyn0 = smem_u32(smem);
    const uint32_t barq = smem_u32(s_bar);
    const uint32_t bark = barq + 8;

    const int tid = threadIdx.x, wid = tid >> 5, lane = tid & 31;
    const int bx = (int)gridDim.x - 1 - (int)blockIdx.x;   // big tiles first
    const int bh = blockIdx.y;
    const int q0 = bx << 7;
    const int yb = bh * SEQ;
    const int ktend = 2 * bx + 2;

    if (tid == 0) {
        MBARRIER_INIT(barq, 1);
        for (int s = 0; s < KVSTAGES; ++s) MBARRIER_INIT(bark + s * 8, 1);
    }
    __syncthreads();

    auto issue_kv = [&](int s, int kt) {
        const uint32_t sb = dyn0 + KV0 + s * KVSB;
        const uint32_t fb = bark + s * 8;
        const int y = yb + kt * 64;
        MBARRIER_EXPECT_TX(fb, KVSB);
        TMA_LOAD_2D(sb,        &tmK, 0, y, fb);
        TMA_LOAD_2D(sb + 8192, &tmV, 0, y, fb);
    };
    if (tid == 0) {
        MBARRIER_EXPECT_TX(barq, 32768);
        TMA_LOAD_2D(dyn0,         &tmQh, 0, yb + q0, barq);
        TMA_LOAD_2D(dyn0 + 16384, &tmQl, 0, yb + q0, barq);
        const int np = ktend < KVSTAGES ? ktend : KVSTAGES;
        for (int p = 0; p < np; ++p) issue_kv(p, p);
    }

    MBARRIER_WAIT_PARITY(barq, 0);
    uint32_t qh[4][4], ql[4][4];
#pragma unroll
    for (int k16 = 0; k16 < 4; ++k16) {
        const int rowA = wid * 16 + (lane & 15);
        const int g = k16 * 2 + (lane >> 4);
        const uint32_t off = (rowA << 7) + ((g ^ (rowA & 7)) << 4);
        ldsm_x4(qh[k16], dyn0 + off);
        ldsm_x4(ql[k16], dyn0 + 16384 + off);
    }

    float O[8][4];
#pragma unroll
    for (int j = 0; j < 8; ++j)
#pragma unroll
        for (int q = 0; q < 4; ++q) O[j][q] = 0.f;
    float m0 = -1e30f, m1 = -1e30f, l0 = 0.f, l1 = 0.f;

    const int rrow = lane >> 2;
    const int ccol = (lane & 3) << 1;

    for (int kt = 0; kt < ktend; ++kt) {
        const int s = kt % KVSTAGES;
        const int ph = (kt / KVSTAGES) & 1;
        MBARRIER_WAIT_PARITY(bark + s * 8, ph);
        const uint32_t sb = dyn0 + KV0 + s * KVSB;

        const bool active = (kt * 64 <= q0 + wid * 16 + 15);
        if (active) {
            float S[8][4];
#pragma unroll
            for (int j = 0; j < 8; ++j)
#pragma unroll
                for (int q = 0; q < 4; ++q) S[j][q] = 0.f;
#pragma unroll
            for (int p = 0; p < 4; ++p) {
#pragma unroll
                for (int k16 = 0; k16 < 4; ++k16) {
                    uint32_t bkh[4];
                    const int rowB = p * 16 + ((lane >> 4) << 3) + (lane & 7);
                    const int g = k16 * 2 + ((lane >> 3) & 1);
                    const uint32_t off = (rowB << 7) + ((g ^ (rowB & 7)) << 4);
                    ldsm_x4(bkh, sb + off);
                    MMA_F16(S[2 * p],     qh[k16], &bkh[0]);
                    MMA_F16(S[2 * p],     ql[k16], &bkh[0]);
                    MMA_F16(S[2 * p + 1], qh[k16], &bkh[2]);
                    MMA_F16(S[2 * p + 1], ql[k16], &bkh[2]);
                }
            }

            if (kt >= 2 * bx) {
                const int r0g = q0 + wid * 16 + rrow;
#pragma unroll
                for (int jt = 0; jt < 8; ++jt) {
                    const int cg = kt * 64 + jt * 8 + ccol;
                    if (cg     > r0g)     S[jt][0] = -1e30f;
                    if (cg + 1 > r0g)     S[jt][1] = -1e30f;
                    if (cg     > r0g + 8) S[jt][2] = -1e30f;
                    if (cg + 1 > r0g + 8) S[jt][3] = -1e30f;
                }
            }

            float mx0 = -1e30f, mx1 = -1e30f;
#pragma unroll
            for (int jt = 0; jt < 8; ++jt) {
                mx0 = fmaxf(mx0, fmaxf(S[jt][0], S[jt][1]));
                mx1 = fmaxf(mx1, fmaxf(S[jt][2], S[jt][3]));
            }
            mx0 = fmaxf(mx0, __shfl_xor_sync(0xffffffffu, mx0, 1));
            mx0 = fmaxf(mx0, __shfl_xor_sync(0xffffffffu, mx0, 2));
            mx1 = fmaxf(mx1, __shfl_xor_sync(0xffffffffu, mx1, 1));
            mx1 = fmaxf(mx1, __shfl_xor_sync(0xffffffffu, mx1, 2));
            const float nm0 = fmaxf(m0, mx0), nm1 = fmaxf(m1, mx1);
            const float a0 = ex2(m0 - nm0), a1 = ex2(m1 - nm1);
            m0 = nm0; m1 = nm1;
            float s0 = 0.f, s1 = 0.f;
#pragma unroll
            for (int jt = 0; jt < 8; ++jt) {
                S[jt][0] = ex2(S[jt][0] - m0);
                S[jt][1] = ex2(S[jt][1] - m0);
                S[jt][2] = ex2(S[jt][2] - m1);
                S[jt][3] = ex2(S[jt][3] - m1);
                s0 += S[jt][0] + S[jt][1];
                s1 += S[jt][2] + S[jt][3];
            }
            s0 += __shfl_xor_sync(0xffffffffu, s0, 1);
            s0 += __shfl_xor_sync(0xffffffffu, s0, 2);
            s1 += __shfl_xor_sync(0xffffffffu, s1, 1);
            s1 += __shfl_xor_sync(0xffffffffu, s1, 2);
            l0 = l0 * a0 + s0;
            l1 = l1 * a1 + s1;
#pragma unroll
            for (int jt = 0; jt < 8; ++jt) {
                O[jt][0] *= a0; O[jt][1] *= a0;
                O[jt][2] *= a1; O[jt][3] *= a1;
            }

            uint32_t pfh[4][4], pfl[4][4];
#pragma unroll
            for (int kk = 0; kk < 4; ++kk) {
                split2h(S[2 * kk][0],     S[2 * kk][1],     pfh[kk][0], pfl[kk][0]);
                split2h(S[2 * kk][2],     S[2 * kk][3],     pfh[kk][1], pfl[kk][1]);
                split2h(S[2 * kk + 1][0], S[2 * kk + 1][1], pfh[kk][2], pfl[kk][2]);
                split2h(S[2 * kk + 1][2], S[2 * kk + 1][3], pfh[kk][3], pfl[kk][3]);
            }

#pragma unroll
            for (int p = 0; p < 4; ++p) {
#pragma unroll
                for (int kk = 0; kk < 4; ++kk) {
                    uint32_t vh[4];
                    const int key = kk * 16 + ((lane >> 3) & 1) * 8 + (lane & 7);
                    const int nt = 2 * p + (lane >> 4);
                    const uint32_t off = (key << 7) + (((nt) ^ (key & 7)) << 4);
                    ldsm_x4_t(vh, sb + 8192 + off);
                    MMA_F16(O[2 * p],     pfh[kk], &vh[0]);
                    MMA_F16(O[2 * p],     pfl[kk], &vh[0]);
                    MMA_F16(O[2 * p + 1], pfh[kk], &vh[2]);
                    MMA_F16(O[2 * p + 1], pfl[kk], &vh[2]);
                }
            }
        }
        __syncthreads();
        if (tid == 0 && kt + KVSTAGES < ktend) issue_kv(s, kt + KVSTAGES);
    }

    const float inv0 = 1.f / l0, inv1 = 1.f / l1;
    const int b = bh >> 4, h = bh & 15;
    const int r0g = q0 + wid * 16 + rrow;
    const size_t mi0 = ((size_t)b * SEQ + r0g) * D_MODEL + h * 64;
    const size_t mi1 = ((size_t)b * SEQ + r0g + 8) * D_MODEL + h * 64;
#pragma unroll
    for (int jt = 0; jt < 8; ++jt) {
        const int c = jt * 8 + ccol;
        uint32_t hh, ll;
        split2h(O[jt][0] * inv0, O[jt][1] * inv0, hh, ll);
        *(uint32_t*)(Ch + mi0 + c) = hh;
        *(uint32_t*)(Cl + mi0 + c) = ll;
        split2h(O[jt][2] * inv1, O[jt][3] * inv1, hh, ll);
        *(uint32_t*)(Ch + mi1 + c) = hh;
        *(uint32_t*)(Cl + mi1 + c) = ll;
    }
}

// ---------------- host-side tensor maps -----------------------------------
typedef CUresult (*EncodeFn)(CUtensorMap*, CUtensorMapDataType, cuuint32_t, void*,
                             const cuuint64_t*, const cuuint64_t*, const cuuint32_t*,
                             const cuuint32_t*, CUtensorMapInterleave, CUtensorMapSwizzle,
                             CUtensorMapL2promotion, CUtensorMapFloatOOBfill);

static void make_map(EncodeFn enc, CUtensorMap* m, void* base,
                     uint64_t d0, uint64_t d1, uint32_t box_rows)
{
    cuuint64_t dims[2] = {d0, d1};
    cuuint64_t strides[1] = {d0 * 2};
    cuuint32_t box[2] = {64u, box_rows};
    cuuint32_t es[2] = {1u, 1u};
    enc(m, CU_TENSOR_MAP_DATA_TYPE_FLOAT16, 2, base, dims, strides, box, es,
        CU_TENSOR_MAP_INTERLEAVE_NONE, CU_TENSOR_MAP_SWIZZLE_128B,
        CU_TENSOR_MAP_L2_PROMOTION_L2_128B, CU_TENSOR_MAP_FLOAT_OOB_FILL_NONE);
}

// ---------------- launcher -------------------------------------------------
extern "C" void kernel_launch(void* const* d_in, const int* in_sizes, int n_in,
                              void* d_out, int out_size)
{
    const float* query = (const float*)d_in[0];
    const float* key_  = (const float*)d_in[1];
    const float* value = (const float*)d_in[2];
    const float* Wq = (const float*)d_in[4];
    const float* bq = (const float*)d_in[5];
    const float* Wk = (const float*)d_in[6];
    const float* bk = (const float*)d_in[7];
    const float* Wv = (const float*)d_in[8];
    const float* bv = (const float*)d_in[9];
    const float* Wo = (const float*)d_in[10];
    const float* bo = (const float*)d_in[11];
    float* out = (float*)d_out;

    __half *pQh, *pQl, *pK, *pV;
    __half *pXqh, *pXql, *pXkh, *pXkl, *pXvh, *pXvl;
    __half *pWq, *pWk, *pWv, *pWo;
    cudaGetSymbolAddress((void**)&pQh, g_Qh);
    cudaGetSymbolAddress((void**)&pQl, g_Ql);
    cudaGetSymbolAddress((void**)&pK, g_K);
    cudaGetSymbolAddress((void**)&pV, g_V);
    cudaGetSymbolAddress((void**)&pXqh, g_Xq_hi);
    cudaGetSymbolAddress((void**)&pXql, g_Xq_lo);
    cudaGetSymbolAddress((void**)&pXkh, g_Xk_hi);
    cudaGetSymbolAddress((void**)&pXkl, g_Xk_lo);
    cudaGetSymbolAddress((void**)&pXvh, g_Xv_hi);
    cudaGetSymbolAddress((void**)&pXvl, g_Xv_lo);
    cudaGetSymbolAddress((void**)&pWq, g_Wq);
    cudaGetSymbolAddress((void**)&pWk, g_Wk);
    cudaGetSymbolAddress((void**)&pWv, g_Wv);
    cudaGetSymbolAddress((void**)&pWo, g_Wo);

    void* encp = nullptr;
    cudaDriverEntryPointQueryResult qr;
    cudaGetDriverEntryPointByVersion("cuTensorMapEncodeTiled", &encp, 12000,
                                     cudaEnableDefault, &qr);
    EncodeFn enc = (EncodeFn)encp;

    const uint64_t NR = (uint64_t)BATCH * NHEAD * SEQ;
    CUtensorMap tmXqh, tmXql, tmXkh, tmXkl, tmXvh, tmXvl;
    CUtensorMap tmWq, tmWk, tmWv, tmWo, tmQh, tmQl, tmK, tmV;
    make_map(enc, &tmXqh, pXqh, D_MODEL, M_TOT, 128);
    make_map(enc, &tmXql, pXql, D_MODEL, M_TOT, 128);
    make_map(enc, &tmXkh, pXkh, D_MODEL, M_TOT, 128);
    make_map(enc, &tmXkl, pXkl, D_MODEL, M_TOT, 128);
    make_map(enc, &tmXvh, pXvh, D_MODEL, M_TOT, 128);
    make_map(enc, &tmXvl, pXvl, D_MODEL, M_TOT, 128);
    make_map(enc, &tmWq, pWq, D_MODEL, D_MODEL, 128);
    make_map(enc, &tmWk, pWk, D_MODEL, D_MODEL, 128);
    make_map(enc, &tmWv, pWv, D_MODEL, D_MODEL, 128);
    make_map(enc, &tmWo, pWo, D_MODEL, D_MODEL, 128);
    make_map(enc, &tmQh, pQh, HEAD_DIM, NR, 128);
    make_map(enc, &tmQl, pQl, HEAD_DIM, NR, 128);
    make_map(enc, &tmK,  pK,  HEAD_DIM, NR, 64);
    make_map(enc, &tmV,  pV,  HEAD_DIM, NR, 64);

    cudaFuncSetAttribute(qkv_proj, cudaFuncAttributeMaxDynamicSharedMemorySize, PROJ_SMEM);
    cudaFuncSetAttribute(out_proj, cudaFuncAttributeMaxDynamicSharedMemorySize, PROJ_SMEM);
    cudaFuncSetAttribute(attn_mma, cudaFuncAttributeMaxDynamicSharedMemorySize, AT_SMEM);

    const int NX4 = (M_TOT * D_MODEL) / 4;
    const int NW4 = (D_MODEL * D_MODEL) / 4;
    dim3 gcs(1024, 3);
    dim3 gcw(512, 4);
    dim3 gp3(D_MODEL / 128, M_TOT / 128, 3);
    dim3 gp(D_MODEL / 128, M_TOT / 128);
    dim3 ga(SEQ / 128, BATCH * NHEAD);
    const float qscale = 0.125f * 1.4426950408889634f;  // 1/sqrt(64) * log2(e)

    cvt_split3<<<gcs, 512>>>(query, key_, value, pXqh, pXql, pXkh, pXkl, pXvh, pXvl, NX4);
    cvt_single4<<<gcw, 512>>>(Wq, Wk, Wv, Wo, pWq, pWk, pWv, pWo, NW4);
    qkv_proj<<<gp3, 256, PROJ_SMEM>>>(tmXqh, tmXql, tmXkh, tmXkl, tmXvh, tmXvl,
                                      tmWq, tmWk, tmWv, bq, bk, bv,
                                      pQh, pQl, pK, pV, qscale);
    attn_mma<<<ga, 256, AT_SMEM>>>(tmQh, tmQl, tmK, tmV, pXqh, pXql);
    out_proj<<<gp, 256, PROJ_SMEM>>>(tmXqh, tmXql, tmWo, bo, out);
}

// round 11
// speedup vs baseline: 5.3749x; 1.0947x over previous
#include <cuda_runtime.h>
#include <cuda.h>
#include <cuda_fp16.h>
#include <cstdint>

#define D_MODEL 1024
#define NHEAD   16
#define HEAD_DIM 64
#define BATCH   4
#define SEQ     2048
#define M_TOT   (BATCH * SEQ)

// ---------------- scratch (static device memory; no allocations) ----------
__device__ __half g_Qh[BATCH * NHEAD * SEQ * HEAD_DIM];
__device__ __half g_Ql[BATCH * NHEAD * SEQ * HEAD_DIM];
__device__ __half g_K [BATCH * NHEAD * SEQ * HEAD_DIM];
__device__ __half g_V [BATCH * NHEAD * SEQ * HEAD_DIM];
__device__ __half g_Xq_hi[M_TOT * D_MODEL];   // also ctx hi after attn
__device__ __half g_Xq_lo[M_TOT * D_MODEL];   // also ctx lo after attn
__device__ __half g_Xk_hi[M_TOT * D_MODEL];
__device__ __half g_Xk_lo[M_TOT * D_MODEL];
__device__ __half g_Xv_hi[M_TOT * D_MODEL];
__device__ __half g_Xv_lo[M_TOT * D_MODEL];
__device__ __half g_Wq[D_MODEL * D_MODEL];
__device__ __half g_Wk[D_MODEL * D_MODEL];
__device__ __half g_Wv[D_MODEL * D_MODEL];
__device__ __half g_Wo[D_MODEL * D_MODEL];

typedef unsigned long long ull;

// ---------------- PTX helpers ---------------------------------------------
__device__ __forceinline__ uint32_t smem_u32(const void* p) {
    uint32_t a;
    asm("{ .reg .u64 t; cvta.to.shared.u64 t, %1; cvt.u32.u64 %0, t; }"
        : "=r"(a) : "l"(p));
    return a;
}
__device__ __forceinline__ void ldsm_x4(uint32_t* r, uint32_t a) {
    asm volatile("ldmatrix.sync.aligned.m8n8.x4.shared.b16 {%0,%1,%2,%3}, [%4];"
                 : "=r"(r[0]), "=r"(r[1]), "=r"(r[2]), "=r"(r[3]) : "r"(a));
}
__device__ __forceinline__ void ldsm_x4_t(uint32_t* r, uint32_t a) {
    asm volatile("ldmatrix.sync.aligned.m8n8.x4.trans.shared.b16 {%0,%1,%2,%3}, [%4];"
                 : "=r"(r[0]), "=r"(r[1]), "=r"(r[2]), "=r"(r[3]) : "r"(a));
}
#define MMA_F16(acc, a, b) \
    asm volatile("mma.sync.aligned.m16n8k16.row.col.f32.f16.f16.f32 " \
        "{%0,%1,%2,%3}, {%4,%5,%6,%7}, {%8,%9}, {%0,%1,%2,%3};" \
        : "+f"((acc)[0]), "+f"((acc)[1]), "+f"((acc)[2]), "+f"((acc)[3]) \
        : "r"((a)[0]), "r"((a)[1]), "r"((a)[2]), "r"((a)[3]), \
          "r"((b)[0]), "r"((b)[1]))

#define MBARRIER_INIT(addr, cnt) \
    asm volatile("mbarrier.init.shared.b64 [%0], %1;" :: "r"(addr), "r"(cnt) : "memory")
#define MBARRIER_EXPECT_TX(addr, bytes) \
    asm volatile("mbarrier.arrive.expect_tx.shared.b64 _, [%0], %1;" \
                 :: "r"(addr), "r"(bytes) : "memory")
#define MBARRIER_WAIT_PARITY(addr, parity) do { \
    uint32_t _m = (uint32_t)(addr); uint32_t _p = (uint32_t)(parity); uint32_t _d; \
    asm volatile("{\n\t.reg .pred p;\n\t" \
        "mbarrier.try_wait.parity.acquire.cta.shared::cta.b64 p, [%1], %2;\n\t" \
        "selp.b32 %0, 1, 0, p;\n\t}" : "=r"(_d) : "r"(_m), "r"(_p) : "memory"); \
    if (!_d) { \
        asm volatile("{\n\t.reg .pred P1;\n\t" \
            "WL_%=:\n\t" \
            "mbarrier.try_wait.parity.acquire.cta.shared::cta.b64 P1, [%0], %1, 0x989680;\n\t" \
            "@P1 bra.uni WD_%=;\n\t" \
            "bra.uni WL_%=;\n\t" \
            "WD_%=:\n\t}" :: "r"(_m), "r"(_p) : "memory"); \
    } } while (0)

#define TMA_LOAD_2D(smem_addr, tmap_ptr, cx, cy, mbar) \
    asm volatile("cp.async.bulk.tensor.2d.shared::cta.global.tile.mbarrier::complete_tx::bytes " \
        "[%0], [%1, {%2, %3}], [%4];" \
        :: "r"((uint32_t)(smem_addr)), "l"(tmap_ptr), "r"((int32_t)(cx)), "r"((int32_t)(cy)), \
           "r"((uint32_t)(mbar)) : "memory")

__device__ __forceinline__ uint32_t pkh(float x, float y) {
    __half2 hh = __floats2half2_rn(x, y);
    return *(uint32_t*)&hh;
}
__device__ __forceinline__ void split2h(float x, float y, uint32_t& h, uint32_t& l) {
    __half2 hh = __floats2half2_rn(x, y);
    float fx = __low2float(hh), fy = __high2float(hh);
    __half2 ll = __floats2half2_rn(x - fx, y - fy);
    h = *(uint32_t*)&hh;
    l = *(uint32_t*)&ll;
}
__device__ __forceinline__ float ex2(float x) {
    float y; asm("ex2.approx.ftz.f32 %0, %1;" : "=f"(y) : "f"(x)); return y;
}

// ---------------- batched fp32 -> fp16 conversions ------------------------
__global__ void __launch_bounds__(512)
cvt_split3(const float* __restrict__ x0, const float* __restrict__ x1,
           const float* __restrict__ x2,
           __half* __restrict__ h0, __half* __restrict__ l0_,
           __half* __restrict__ h1, __half* __restrict__ l1_,
           __half* __restrict__ h2, __half* __restrict__ l2_, int n4)
{
    const int seg = blockIdx.y;
    const float* x = seg == 0 ? x0 : (seg == 1 ? x1 : x2);
    __half* hi = seg == 0 ? h0 : (seg == 1 ? h1 : h2);
    __half* lo = seg == 0 ? l0_ : (seg == 1 ? l1_ : l2_);
    int i = blockIdx.x * blockDim.x + threadIdx.x;
    int stride = gridDim.x * blockDim.x;
    for (; i < n4; i += stride) {
        float4 v = ((const float4*)x)[i];
        uint32_t a0, b0, a1, b1;
        split2h(v.x, v.y, a0, b0);
        split2h(v.z, v.w, a1, b1);
        ((uint32_t*)hi)[2 * i] = a0;  ((uint32_t*)hi)[2 * i + 1] = a1;
        ((uint32_t*)lo)[2 * i] = b0;  ((uint32_t*)lo)[2 * i + 1] = b1;
    }
}
__global__ void __launch_bounds__(512)
cvt_single4(const float* __restrict__ x0, const float* __restrict__ x1,
            const float* __restrict__ x2, const float* __restrict__ x3,
            __half* __restrict__ w0, __half* __restrict__ w1,
            __half* __restrict__ w2, __half* __restrict__ w3, int n4)
{
    const int seg = blockIdx.y;
    const float* x = seg == 0 ? x0 : (seg == 1 ? x1 : (seg == 2 ? x2 : x3));
    __half* w = seg == 0 ? w0 : (seg == 1 ? w1 : (seg == 2 ? w2 : w3));
    int i = blockIdx.x * blockDim.x + threadIdx.x;
    int stride = gridDim.x * blockDim.x;
    for (; i < n4; i += stride) {
        float4 v = ((const float4*)x)[i];
        ((uint32_t*)w)[2 * i]     = pkh(v.x, v.y);
        ((uint32_t*)w)[2 * i + 1] = pkh(v.z, v.w);
    }
}

// ---------------- TMA projection GEMM (fp16 2-MMA: A split, B single) -----
#define KC          64
#define NCHUNKS     (D_MODEL / KC)
#define PSTAGES     3
#define RA_H        0
#define RA_L        16384
#define RB          32768
#define STAGE_BYTES 49152
#define PROJ_SMEM   (PSTAGES * STAGE_BYTES)

// mode: 0 fp32 row-major out; 1 fp16 hi/lo head layout; 2 fp16 single head layout.
__device__ __forceinline__ void proj_body(
    const CUtensorMap* pAh, const CUtensorMap* pAl, const CUtensorMap* pB,
    const float* bias, float* out, __half* oh, __half* ol, float scale,
    int mode, int m0, int n0, uint32_t dyn0, uint32_t bar0)
{
    const int tid = threadIdx.x;
    const int wid = tid >> 5, lane = tid & 31;
    const int wm = (wid & 1) << 6, wn = (wid >> 1) << 5;

    if (tid == 0) {
        for (int s = 0; s < PSTAGES; ++s) MBARRIER_INIT(bar0 + s * 8, 1);
    }
    __syncthreads();

    auto issue = [&](int s, int kc) {
        const uint32_t sb = dyn0 + s * STAGE_BYTES;
        const uint32_t fb = bar0 + s * 8;
        MBARRIER_EXPECT_TX(fb, STAGE_BYTES);
        TMA_LOAD_2D(sb + RA_H, pAh, kc * KC, m0, fb);
        TMA_LOAD_2D(sb + RA_L, pAl, kc * KC, m0, fb);
        TMA_LOAD_2D(sb + RB,   pB,  kc * KC, n0, fb);
    };
    if (tid == 0) {
        for (int c = 0; c < PSTAGES; ++c) issue(c, c);
    }

    float acc[4][4][4];
#pragma unroll
    for (int i = 0; i < 4; ++i)
#pragma unroll
        for (int j = 0; j < 4; ++j)
#pragma unroll
            for (int q = 0; q < 4; ++q) acc[i][j][q] = 0.f;

    for (int kc = 0; kc < NCHUNKS; ++kc) {
        const int s = kc % PSTAGES;
        const int ph = (kc / PSTAGES) & 1;
        MBARRIER_WAIT_PARITY(bar0 + s * 8, ph);
        const uint32_t sb = dyn0 + s * STAGE_BYTES;

#pragma unroll
        for (int k16 = 0; k16 < 4; ++k16) {
            uint32_t ah[4][4], al[4][4], bh[2][4];
#pragma unroll
            for (int am = 0; am < 4; ++am) {
                const int rowA = wm + am * 16 + (lane & 15);
                const int g = k16 * 2 + (lane >> 4);
                const uint32_t off = (rowA << 7) + ((g ^ (rowA & 7)) << 4);
                ldsm_x4(ah[am], sb + RA_H + off);
                ldsm_x4(al[am], sb + RA_L + off);
            }
#pragma unroll
            for (int p = 0; p < 2; ++p) {
                const int rowB = wn + p * 16 + ((lane >> 4) << 3) + (lane & 7);
                const int g = k16 * 2 + ((lane >> 3) & 1);
                const uint32_t off = (rowB << 7) + ((g ^ (rowB & 7)) << 4);
                ldsm_x4(bh[p], sb + RB + off);
            }
#pragma unroll
            for (int am = 0; am < 4; ++am)
#pragma unroll
                for (int an = 0; an < 4; ++an) {
                    uint32_t* B0 = &bh[an >> 1][(an & 1) * 2];
                    MMA_F16(acc[am][an], ah[am], B0);
                    MMA_F16(acc[am][an], al[am], B0);
                }
        }
        __syncthreads();
        if (tid == 0 && kc + PSTAGES < NCHUNKS) issue(s, kc + PSTAGES);
    }

#pragma unroll
    for (int am = 0; am < 4; ++am) {
#pragma unroll
        for (int an = 0; an < 4; ++an) {
            const int m = m0 + wm + am * 16 + (lane >> 2);
            const int c = n0 + wn + an * 8 + ((lane & 3) << 1);
            const float2 bv = *(const float2*)&bias[c];
#pragma unroll
            for (int h2 = 0; h2 < 2; ++h2) {
                const int row = m + h2 * 8;
                float ox = (acc[am][an][2 * h2]     + bv.x) * scale;
                float oy = (acc[am][an][2 * h2 + 1] + bv.y) * scale;
                if (mode == 0) {
                    *(float2*)(out + (size_t)row * D_MODEL + c) = make_float2(ox, oy);
                } else {
                    const int b = row >> 11, srow = row & (SEQ - 1);
                    const int hh = c >> 6, dh = c & 63;
                    const size_t idx = (((size_t)(b * NHEAD + hh) * SEQ + srow) * HEAD_DIM + dh);
                    if (mode == 1) {
                        uint32_t h, l;
                        split2h(ox, oy, h, l);
                        *(uint32_t*)(oh + idx) = h;
                        *(uint32_t*)(ol + idx) = l;
                    } else {
                        *(uint32_t*)(oh + idx) = pkh(ox, oy);
                    }
                }
            }
        }
    }
}

// Fused Q/K/V projection: z selects input/weight/bias/output/mode.
__global__ void __launch_bounds__(256)
qkv_proj(const __grid_constant__ CUtensorMap tmQxh, const __grid_constant__ CUtensorMap tmQxl,
         const __grid_constant__ CUtensorMap tmKxh, const __grid_constant__ CUtensorMap tmKxl,
         const __grid_constant__ CUtensorMap tmVxh, const __grid_constant__ CUtensorMap tmVxl,
         const __grid_constant__ CUtensorMap tmWq,  const __grid_constant__ CUtensorMap tmWk,
         const __grid_constant__ CUtensorMap tmWv,
         const float* __restrict__ bq, const float* __restrict__ bk,
         const float* __restrict__ bv,
         __half* __restrict__ oQh, __half* __restrict__ oQl,
         __half* __restrict__ oK,  __half* __restrict__ oV, float qscale)
{
    extern __shared__ __align__(1024) char smem[];
    __shared__ __align__(8) ull s_bar[PSTAGES];
    const uint32_t dyn0 = smem_u32(smem);
    const uint32_t bar0 = smem_u32(s_bar);
    const int m0 = blockIdx.y << 7, n0 = blockIdx.x << 7;
    const int z = blockIdx.z;

    const CUtensorMap* pAh = z == 0 ? &tmQxh : (z == 1 ? &tmKxh : &tmVxh);
    const CUtensorMap* pAl = z == 0 ? &tmQxl : (z == 1 ? &tmKxl : &tmVxl);
    const CUtensorMap* pB  = z == 0 ? &tmWq  : (z == 1 ? &tmWk  : &tmWv);
    const float* bias = z == 0 ? bq : (z == 1 ? bk : bv);
    __half* oh = z == 0 ? oQh : (z == 1 ? oK : oV);
    __half* ol = z == 0 ? oQl : nullptr;
    const float scale = z == 0 ? qscale : 1.0f;
    const int mode = z == 0 ? 1 : 2;

    proj_body(pAh, pAl, pB, bias, nullptr, oh, ol, scale, mode, m0, n0, dyn0, bar0);
}

// Output projection: fp32 out.
__global__ void __launch_bounds__(256)
out_proj(const __grid_constant__ CUtensorMap tmAh, const __grid_constant__ CUtensorMap tmAl,
         const __grid_constant__ CUtensorMap tmB,
         const float* __restrict__ bias, float* __restrict__ out)
{
    extern __shared__ __align__(1024) char smem[];
    __shared__ __align__(8) ull s_bar[PSTAGES];
    proj_body(&tmAh, &tmAl, &tmB, bias, out, nullptr, nullptr, 1.0f, 0,
              blockIdx.y << 7, blockIdx.x << 7, smem_u32(smem), smem_u32(s_bar));
}

// ---------------- TMA causal flash attention ------------------------------
// QK: fp16 2-MMA (Q split). PV: single fp16 P (P in [0,1], err ~2^-12).
// 2 CTAs/SM: regs capped at 128, smem 64KB/CTA (Q 32KB + 2 KV stages x 16KB).
#define KVSTAGES 2
#define KV0      32768
#define KVSB     16384
#define AT_SMEM  (KV0 + KVSTAGES * KVSB)

__global__ void __launch_bounds__(256, 2)
attn_mma(const __grid_constant__ CUtensorMap tmQh, const __grid_constant__ CUtensorMap tmQl,
         const __grid_constant__ CUtensorMap tmK,  const __grid_constant__ CUtensorMap tmV,
         __half* __restrict__ Ch, __half* __restrict__ Cl)
{
    extern __shared__ __align__(1024) char smem[];
    __shared__ __align__(8) ull s_bar[1 + KVSTAGES];
    const uint32_t dyn0 = smem_u32(smem);
    const uint32_t barq = smem_u32(s_bar);
    const uint32_t bark = barq + 8;

    const int tid = threadIdx.x, wid = tid >> 5, lane = tid & 31;
    const int bx = (int)gridDim.x - 1 - (int)blockIdx.x;   // big tiles first
    const int bh = blockIdx.y;
    const int q0 = bx << 7;
    const int yb = bh * SEQ;
    const int ktend = 2 * bx + 2;

    if (tid == 0) {
        MBARRIER_INIT(barq, 1);
        for (int s = 0; s < KVSTAGES; ++s) MBARRIER_INIT(bark + s * 8, 1);
    }
    __syncthreads();

    auto issue_kv = [&](int s, int kt) {
        const uint32_t sb = dyn0 + KV0 + s * KVSB;
        const uint32_t fb = bark + s * 8;
        const int y = yb + kt * 64;
        MBARRIER_EXPECT_TX(fb, KVSB);
        TMA_LOAD_2D(sb,        &tmK, 0, y, fb);
        TMA_LOAD_2D(sb + 8192, &tmV, 0, y, fb);
    };
    if (tid == 0) {
        MBARRIER_EXPECT_TX(barq, 32768);
        TMA_LOAD_2D(dyn0,         &tmQh, 0, yb + q0, barq);
        TMA_LOAD_2D(dyn0 + 16384, &tmQl, 0, yb + q0, barq);
        const int np = ktend < KVSTAGES ? ktend : KVSTAGES;
        for (int p = 0; p < np; ++p) issue_kv(p, p);
    }

    MBARRIER_WAIT_PARITY(barq, 0);
    uint32_t qh[4][4], ql[4][4];
#pragma unroll
    for (int k16 = 0; k16 < 4; ++k16) {
        const int rowA = wid * 16 + (lane & 15);
        const int g = k16 * 2 + (lane >> 4);
        const uint32_t off = (rowA << 7) + ((g ^ (rowA & 7)) << 4);
        ldsm_x4(qh[k16], dyn0 + off);
        ldsm_x4(ql[k16], dyn0 + 16384 + off);
    }

    float O[8][4];
#pragma unroll
    for (int j = 0; j < 8; ++j)
#pragma unroll
        for (int q = 0; q < 4; ++q) O[j][q] = 0.f;
    float m0 = -1e30f, m1 = -1e30f, l0 = 0.f, l1 = 0.f;

    const int rrow = lane >> 2;
    const int ccol = (lane & 3) << 1;

    for (int kt = 0; kt < ktend; ++kt) {
        const int s = kt % KVSTAGES;
        const int ph = (kt / KVSTAGES) & 1;
        MBARRIER_WAIT_PARITY(bark + s * 8, ph);
        const uint32_t sb = dyn0 + KV0 + s * KVSB;

        const bool active = (kt * 64 <= q0 + wid * 16 + 15);
        if (active) {
            float S[8][4];
#pragma unroll
            for (int j = 0; j < 8; ++j)
#pragma unroll
                for (int q = 0; q < 4; ++q) S[j][q] = 0.f;
#pragma unroll
            for (int p = 0; p < 4; ++p) {
#pragma unroll
                for (int k16 = 0; k16 < 4; ++k16) {
                    uint32_t bkh[4];
                    const int rowB = p * 16 + ((lane >> 4) << 3) + (lane & 7);
                    const int g = k16 * 2 + ((lane >> 3) & 1);
                    const uint32_t off = (rowB << 7) + ((g ^ (rowB & 7)) << 4);
                    ldsm_x4(bkh, sb + off);
                    MMA_F16(S[2 * p],     qh[k16], &bkh[0]);
                    MMA_F16(S[2 * p],     ql[k16], &bkh[0]);
                    MMA_F16(S[2 * p + 1], qh[k16], &bkh[2]);
                    MMA_F16(S[2 * p + 1], ql[k16], &bkh[2]);
                }
            }

            if (kt >= 2 * bx) {
                const int r0g = q0 + wid * 16 + rrow;
#pragma unroll
                for (int jt = 0; jt < 8; ++jt) {
                    const int cg = kt * 64 + jt * 8 + ccol;
                    if (cg     > r0g)     S[jt][0] = -1e30f;
                    if (cg + 1 > r0g)     S[jt][1] = -1e30f;
                    if (cg     > r0g + 8) S[jt][2] = -1e30f;
                    if (cg + 1 > r0g + 8) S[jt][3] = -1e30f;
                }
            }

            float mx0 = -1e30f, mx1 = -1e30f;
#pragma unroll
            for (int jt = 0; jt < 8; ++jt) {
                mx0 = fmaxf(mx0, fmaxf(S[jt][0], S[jt][1]));
                mx1 = fmaxf(mx1, fmaxf(S[jt][2], S[jt][3]));
            }
            mx0 = fmaxf(mx0, __shfl_xor_sync(0xffffffffu, mx0, 1));
            mx0 = fmaxf(mx0, __shfl_xor_sync(0xffffffffu, mx0, 2));
            mx1 = fmaxf(mx1, __shfl_xor_sync(0xffffffffu, mx1, 1));
            mx1 = fmaxf(mx1, __shfl_xor_sync(0xffffffffu, mx1, 2));
            const float nm0 = fmaxf(m0, mx0), nm1 = fmaxf(m1, mx1);
            const float a0 = ex2(m0 - nm0), a1 = ex2(m1 - nm1);
            m0 = nm0; m1 = nm1;
            float s0 = 0.f, s1 = 0.f;
#pragma unroll
            for (int jt = 0; jt < 8; ++jt) {
                S[jt][0] = ex2(S[jt][0] - m0);
                S[jt][1] = ex2(S[jt][1] - m0);
                S[jt][2] = ex2(S[jt][2] - m1);
                S[jt][3] = ex2(S[jt][3] - m1);
                s0 += S[jt][0] + S[jt][1];
                s1 += S[jt][2] + S[jt][3];
            }
            s0 += __shfl_xor_sync(0xffffffffu, s0, 1);
            s0 += __shfl_xor_sync(0xffffffffu, s0, 2);
            s1 += __shfl_xor_sync(0xffffffffu, s1, 1);
            s1 += __shfl_xor_sync(0xffffffffu, s1, 2);
            l0 = l0 * a0 + s0;
            l1 = l1 * a1 + s1;
#pragma unroll
            for (int jt = 0; jt < 8; ++jt) {
                O[jt][0] *= a0; O[jt][1] *= a0;
                O[jt][2] *= a1; O[jt][3] *= a1;
            }

            // ---- pack P into single-fp16 A fragments (P in [0,1])
            uint32_t pfh[4][4];
#pragma unroll
            for (int kk = 0; kk < 4; ++kk) {
                pfh[kk][0] = pkh(S[2 * kk][0],     S[2 * kk][1]);
                pfh[kk][1] = pkh(S[2 * kk][2],     S[2 * kk][3]);
                pfh[kk][2] = pkh(S[2 * kk + 1][0], S[2 * kk + 1][1]);
                pfh[kk][3] = pkh(S[2 * kk + 1][2], S[2 * kk + 1][3]);
            }

            // ---- O += P V (single-MMA P; V^T via ldmatrix.trans)
#pragma unroll
            for (int p = 0; p < 4; ++p) {
#pragma unroll
                for (int kk = 0; kk < 4; ++kk) {
                    uint32_t vh[4];
                    const int key = kk * 16 + ((lane >> 3) & 1) * 8 + (lane & 7);
                    const int nt = 2 * p + (lane >> 4);
                    const uint32_t off = (key << 7) + (((nt) ^ (key & 7)) << 4);
                    ldsm_x4_t(vh, sb + 8192 + off);
                    MMA_F16(O[2 * p],     pfh[kk], &vh[0]);
                    MMA_F16(O[2 * p + 1], pfh[kk], &vh[2]);
                }
            }
        }
        __syncthreads();
        if (tid == 0 && kt + KVSTAGES < ktend) issue_kv(s, kt + KVSTAGES);
    }

    const float inv0 = 1.f / l0, inv1 = 1.f / l1;
    const int b = bh >> 4, h = bh & 15;
    const int r0g = q0 + wid * 16 + rrow;
    const size_t mi0 = ((size_t)b * SEQ + r0g) * D_MODEL + h * 64;
    const size_t mi1 = ((size_t)b * SEQ + r0g + 8) * D_MODEL + h * 64;
#pragma unroll
    for (int jt = 0; jt < 8; ++jt) {
        const int c = jt * 8 + ccol;
        uint32_t hh, ll;
        split2h(O[jt][0] * inv0, O[jt][1] * inv0, hh, ll);
        *(uint32_t*)(Ch + mi0 + c) = hh;
        *(uint32_t*)(Cl + mi0 + c) = ll;
        split2h(O[jt][2] * inv1, O[jt][3] * inv1, hh, ll);
        *(uint32_t*)(Ch + mi1 + c) = hh;
        *(uint32_t*)(Cl + mi1 + c) = ll;
    }
}

// ---------------- host-side tensor maps -----------------------------------
typedef CUresult (*EncodeFn)(CUtensorMap*, CUtensorMapDataType, cuuint32_t, void*,
                             const cuuint64_t*, const cuuint64_t*, const cuuint32_t*,
                             const cuuint32_t*, CUtensorMapInterleave, CUtensorMapSwizzle,
                             CUtensorMapL2promotion, CUtensorMapFloatOOBfill);

static void make_map(EncodeFn enc, CUtensorMap* m, void* base,
                     uint64_t d0, uint64_t d1, uint32_t box_rows)
{
    cuuint64_t dims[2] = {d0, d1};
    cuuint64_t strides[1] = {d0 * 2};
    cuuint32_t box[2] = {64u, box_rows};
    cuuint32_t es[2] = {1u, 1u};
    enc(m, CU_TENSOR_MAP_DATA_TYPE_FLOAT16, 2, base, dims, strides, box, es,
        CU_TENSOR_MAP_INTERLEAVE_NONE, CU_TENSOR_MAP_SWIZZLE_128B,
        CU_TENSOR_MAP_L2_PROMOTION_L2_128B, CU_TENSOR_MAP_FLOAT_OOB_FILL_NONE);
}

// ---------------- launcher -------------------------------------------------
extern "C" void kernel_launch(void* const* d_in, const int* in_sizes, int n_in,
                              void* d_out, int out_size)
{
    const float* query = (const float*)d_in[0];
    const float* key_  = (const float*)d_in[1];
    const float* value = (const float*)d_in[2];
    const float* Wq = (const float*)d_in[4];
    const float* bq = (const float*)d_in[5];
    const float* Wk = (const float*)d_in[6];
    const float* bk = (const float*)d_in[7];
    const float* Wv = (const float*)d_in[8];
    const float* bv = (const float*)d_in[9];
    const float* Wo = (const float*)d_in[10];
    const float* bo = (const float*)d_in[11];
    float* out = (float*)d_out;

    __half *pQh, *pQl, *pK, *pV;
    __half *pXqh, *pXql, *pXkh, *pXkl, *pXvh, *pXvl;
    __half *pWq, *pWk, *pWv, *pWo;
    cudaGetSymbolAddress((void**)&pQh, g_Qh);
    cudaGetSymbolAddress((void**)&pQl, g_Ql);
    cudaGetSymbolAddress((void**)&pK, g_K);
    cudaGetSymbolAddress((void**)&pV, g_V);
    cudaGetSymbolAddress((void**)&pXqh, g_Xq_hi);
    cudaGetSymbolAddress((void**)&pXql, g_Xq_lo);
    cudaGetSymbolAddress((void**)&pXkh, g_Xk_hi);
    cudaGetSymbolAddress((void**)&pXkl, g_Xk_lo);
    cudaGetSymbolAddress((void**)&pXvh, g_Xv_hi);
    cudaGetSymbolAddress((void**)&pXvl, g_Xv_lo);
    cudaGetSymbolAddress((void**)&pWq, g_Wq);
    cudaGetSymbolAddress((void**)&pWk, g_Wk);
    cudaGetSymbolAddress((void**)&pWv, g_Wv);
    cudaGetSymbolAddress((void**)&pWo, g_Wo);

    void* encp = nullptr;
    cudaDriverEntryPointQueryResult qr;
    cudaGetDriverEntryPointByVersion("cuTensorMapEncodeTiled", &encp, 12000,
                                     cudaEnableDefault, &qr);
    EncodeFn enc = (EncodeFn)encp;

    const uint64_t NR = (uint64_t)BATCH * NHEAD * SEQ;
    CUtensorMap tmXqh, tmXql, tmXkh, tmXkl, tmXvh, tmXvl;
    CUtensorMap tmWq, tmWk, tmWv, tmWo, tmQh, tmQl, tmK, tmV;
    make_map(enc, &tmXqh, pXqh, D_MODEL, M_TOT, 128);
    make_map(enc, &tmXql, pXql, D_MODEL, M_TOT, 128);
    make_map(enc, &tmXkh, pXkh, D_MODEL, M_TOT, 128);
    make_map(enc, &tmXkl, pXkl, D_MODEL, M_TOT, 128);
    make_map(enc, &tmXvh, pXvh, D_MODEL, M_TOT, 128);
    make_map(enc, &tmXvl, pXvl, D_MODEL, M_TOT, 128);
    make_map(enc, &tmWq, pWq, D_MODEL, D_MODEL, 128);
    make_map(enc, &tmWk, pWk, D_MODEL, D_MODEL, 128);
    make_map(enc, &tmWv, pWv, D_MODEL, D_MODEL, 128);
    make_map(enc, &tmWo, pWo, D_MODEL, D_MODEL, 128);
    make_map(enc, &tmQh, pQh, HEAD_DIM, NR, 128);
    make_map(enc, &tmQl, pQl, HEAD_DIM, NR, 128);
    make_map(enc, &tmK,  pK,  HEAD_DIM, NR, 64);
    make_map(enc, &tmV,  pV,  HEAD_DIM, NR, 64);

    cudaFuncSetAttribute(qkv_proj, cudaFuncAttributeMaxDynamicSharedMemorySize, PROJ_SMEM);
    cudaFuncSetAttribute(out_proj, cudaFuncAttributeMaxDynamicSharedMemorySize, PROJ_SMEM);
    cudaFuncSetAttribute(attn_mma, cudaFuncAttributeMaxDynamicSharedMemorySize, AT_SMEM);

    const int NX4 = (M_TOT * D_MODEL) / 4;
    const int NW4 = (D_MODEL * D_MODEL) / 4;
    dim3 gcs(1024, 3);
    dim3 gcw(512, 4);
    dim3 gp3(D_MODEL / 128, M_TOT / 128, 3);
    dim3 gp(D_MODEL / 128, M_TOT / 128);
    dim3 ga(SEQ / 128, BATCH * NHEAD);
    const float qscale = 0.125f * 1.4426950408889634f;  // 1/sqrt(64) * log2(e)

    cvt_split3<<<gcs, 512>>>(query, key_, value, pXqh, pXql, pXkh, pXkl, pXvh, pXvl, NX4);
    cvt_single4<<<gcw, 512>>>(Wq, Wk, Wv, Wo, pWq, pWk, pWv, pWo, NW4);
    qkv_proj<<<gp3, 256, PROJ_SMEM>>>(tmXqh, tmXql, tmXkh, tmXkl, tmXvh, tmXvl,
                                      tmWq, tmWk, tmWv, bq, bk, bv,
                                      pQh, pQl, pK, pV, qscale);
    attn_mma<<<ga, 256, AT_SMEM>>>(tmQh, tmQl, tmK, tmV, pXqh, pXql);
    out_proj<<<gp, 256, PROJ_SMEM>>>(tmXqh, tmXql, tmWo, bo, out);
}

// round 12
// speedup vs baseline: 6.0163x; 1.1193x over previous
#include <cuda_runtime.h>
#include <cuda.h>
#include <cuda_fp16.h>
#include <cstdint>

#define D_MODEL 1024
#define NHEAD   16
#define HEAD_DIM 64
#define BATCH   4
#define SEQ     2048
#define M_TOT   (BATCH * SEQ)

// ---------------- scratch (static device memory; no allocations) ----------
__device__ __half g_Qh[BATCH * NHEAD * SEQ * HEAD_DIM];
__device__ __half g_Ql[BATCH * NHEAD * SEQ * HEAD_DIM];
__device__ __half g_K [BATCH * NHEAD * SEQ * HEAD_DIM];
__device__ __half g_V [BATCH * NHEAD * SEQ * HEAD_DIM];
__device__ __half g_Xq_hi[M_TOT * D_MODEL];   // also ctx (single fp16) after attn
__device__ __half g_Xq_lo[M_TOT * D_MODEL];
__device__ __half g_Xk_hi[M_TOT * D_MODEL];
__device__ __half g_Xk_lo[M_TOT * D_MODEL];
__device__ __half g_Xv_hi[M_TOT * D_MODEL];
__device__ __half g_Xv_lo[M_TOT * D_MODEL];
__device__ __half g_Wq[D_MODEL * D_MODEL];
__device__ __half g_Wk[D_MODEL * D_MODEL];
__device__ __half g_Wv[D_MODEL * D_MODEL];
__device__ __half g_Wo[D_MODEL * D_MODEL];

typedef unsigned long long ull;

// ---------------- PTX helpers ---------------------------------------------
__device__ __forceinline__ uint32_t smem_u32(const void* p) {
    uint32_t a;
    asm("{ .reg .u64 t; cvta.to.shared.u64 t, %1; cvt.u32.u64 %0, t; }"
        : "=r"(a) : "l"(p));
    return a;
}
__device__ __forceinline__ void ldsm_x4(uint32_t* r, uint32_t a) {
    asm volatile("ldmatrix.sync.aligned.m8n8.x4.shared.b16 {%0,%1,%2,%3}, [%4];"
                 : "=r"(r[0]), "=r"(r[1]), "=r"(r[2]), "=r"(r[3]) : "r"(a));
}
__device__ __forceinline__ void ldsm_x4_t(uint32_t* r, uint32_t a) {
    asm volatile("ldmatrix.sync.aligned.m8n8.x4.trans.shared.b16 {%0,%1,%2,%3}, [%4];"
                 : "=r"(r[0]), "=r"(r[1]), "=r"(r[2]), "=r"(r[3]) : "r"(a));
}
#define MMA_F16(acc, a, b) \
    asm volatile("mma.sync.aligned.m16n8k16.row.col.f32.f16.f16.f32 " \
        "{%0,%1,%2,%3}, {%4,%5,%6,%7}, {%8,%9}, {%0,%1,%2,%3};" \
        : "+f"((acc)[0]), "+f"((acc)[1]), "+f"((acc)[2]), "+f"((acc)[3]) \
        : "r"((a)[0]), "r"((a)[1]), "r"((a)[2]), "r"((a)[3]), \
          "r"((b)[0]), "r"((b)[1]))

#define MBARRIER_INIT(addr, cnt) \
    asm volatile("mbarrier.init.shared.b64 [%0], %1;" :: "r"(addr), "r"(cnt) : "memory")
#define MBARRIER_EXPECT_TX(addr, bytes) \
    asm volatile("mbarrier.arrive.expect_tx.shared.b64 _, [%0], %1;" \
                 :: "r"(addr), "r"(bytes) : "memory")
#define MBARRIER_WAIT_PARITY(addr, parity) do { \
    uint32_t _m = (uint32_t)(addr); uint32_t _p = (uint32_t)(parity); uint32_t _d; \
    asm volatile("{\n\t.reg .pred p;\n\t" \
        "mbarrier.try_wait.parity.acquire.cta.shared::cta.b64 p, [%1], %2;\n\t" \
        "selp.b32 %0, 1, 0, p;\n\t}" : "=r"(_d) : "r"(_m), "r"(_p) : "memory"); \
    if (!_d) { \
        asm volatile("{\n\t.reg .pred P1;\n\t" \
            "WL_%=:\n\t" \
            "mbarrier.try_wait.parity.acquire.cta.shared::cta.b64 P1, [%0], %1, 0x989680;\n\t" \
            "@P1 bra.uni WD_%=;\n\t" \
            "bra.uni WL_%=;\n\t" \
            "WD_%=:\n\t}" :: "r"(_m), "r"(_p) : "memory"); \
    } } while (0)

#define TMA_LOAD_2D(smem_addr, tmap_ptr, cx, cy, mbar) \
    asm volatile("cp.async.bulk.tensor.2d.shared::cta.global.tile.mbarrier::complete_tx::bytes " \
        "[%0], [%1, {%2, %3}], [%4];" \
        :: "r"((uint32_t)(smem_addr)), "l"(tmap_ptr), "r"((int32_t)(cx)), "r"((int32_t)(cy)), \
           "r"((uint32_t)(mbar)) : "memory")

__device__ __forceinline__ uint32_t pkh(float x, float y) {
    __half2 hh = __floats2half2_rn(x, y);
    return *(uint32_t*)&hh;
}
__device__ __forceinline__ void split2h(float x, float y, uint32_t& h, uint32_t& l) {
    __half2 hh = __floats2half2_rn(x, y);
    float fx = __low2float(hh), fy = __high2float(hh);
    __half2 ll = __floats2half2_rn(x - fx, y - fy);
    h = *(uint32_t*)&hh;
    l = *(uint32_t*)&ll;
}
__device__ __forceinline__ float ex2(float x) {
    float y; asm("ex2.approx.ftz.f32 %0, %1;" : "=f"(y) : "f"(x)); return y;
}

// ---------------- batched fp32 -> fp16 conversions ------------------------
__global__ void __launch_bounds__(512)
cvt_split3(const float* __restrict__ x0, const float* __restrict__ x1,
           const float* __restrict__ x2,
           __half* __restrict__ h0, __half* __restrict__ l0_,
           __half* __restrict__ h1, __half* __restrict__ l1_,
           __half* __restrict__ h2, __half* __restrict__ l2_, int n4)
{
    const int seg = blockIdx.y;
    const float* x = seg == 0 ? x0 : (seg == 1 ? x1 : x2);
    __half* hi = seg == 0 ? h0 : (seg == 1 ? h1 : h2);
    __half* lo = seg == 0 ? l0_ : (seg == 1 ? l1_ : l2_);
    int i = blockIdx.x * blockDim.x + threadIdx.x;
    int stride = gridDim.x * blockDim.x;
    for (; i < n4; i += stride) {
        float4 v = ((const float4*)x)[i];
        uint32_t a0, b0, a1, b1;
        split2h(v.x, v.y, a0, b0);
        split2h(v.z, v.w, a1, b1);
        ((uint32_t*)hi)[2 * i] = a0;  ((uint32_t*)hi)[2 * i + 1] = a1;
        ((uint32_t*)lo)[2 * i] = b0;  ((uint32_t*)lo)[2 * i + 1] = b1;
    }
}
__global__ void __launch_bounds__(512)
cvt_single4(const float* __restrict__ x0, const float* __restrict__ x1,
            const float* __restrict__ x2, const float* __restrict__ x3,
            __half* __restrict__ w0, __half* __restrict__ w1,
            __half* __restrict__ w2, __half* __restrict__ w3, int n4)
{
    const int seg = blockIdx.y;
    const float* x = seg == 0 ? x0 : (seg == 1 ? x1 : (seg == 2 ? x2 : x3));
    __half* w = seg == 0 ? w0 : (seg == 1 ? w1 : (seg == 2 ? w2 : w3));
    int i = blockIdx.x * blockDim.x + threadIdx.x;
    int stride = gridDim.x * blockDim.x;
    for (; i < n4; i += stride) {
        float4 v = ((const float4*)x)[i];
        ((uint32_t*)w)[2 * i]     = pkh(v.x, v.y);
        ((uint32_t*)w)[2 * i + 1] = pkh(v.z, v.w);
    }
}

// ---------------- TMA projection GEMM -------------------------------------
// asplit: A hi/lo split (2-MMA) or single (1-MMA).
// mode: 0 fp32 row-major out; 1 fp16 hi/lo head layout; 2 fp16 single head layout.
#define KC          64
#define NCHUNKS     (D_MODEL / KC)
#define PSTAGES     3
#define RA_H        0
#define RA_L        16384
#define RB          32768
#define STAGE_BYTES 49152
#define PROJ_SMEM   (PSTAGES * STAGE_BYTES)

__device__ __forceinline__ void proj_body(
    const CUtensorMap* pAh, const CUtensorMap* pAl, const CUtensorMap* pB,
    const float* bias, float* out, __half* oh, __half* ol, float scale,
    int mode, bool asplit, int m0, int n0, uint32_t dyn0, uint32_t bar0)
{
    const int tid = threadIdx.x;
    const int wid = tid >> 5, lane = tid & 31;
    const int wm = (wid & 1) << 6, wn = (wid >> 1) << 5;

    if (tid == 0) {
        for (int s = 0; s < PSTAGES; ++s) MBARRIER_INIT(bar0 + s * 8, 1);
    }
    __syncthreads();

    const uint32_t txbytes = asplit ? 49152u : 32768u;
    auto issue = [&](int s, int kc) {
        const uint32_t sb = dyn0 + s * STAGE_BYTES;
        const uint32_t fb = bar0 + s * 8;
        MBARRIER_EXPECT_TX(fb, txbytes);
        TMA_LOAD_2D(sb + RA_H, pAh, kc * KC, m0, fb);
        if (asplit) TMA_LOAD_2D(sb + RA_L, pAl, kc * KC, m0, fb);
        TMA_LOAD_2D(sb + RB,   pB,  kc * KC, n0, fb);
    };
    if (tid == 0) {
        for (int c = 0; c < PSTAGES; ++c) issue(c, c);
    }

    float acc[4][4][4];
#pragma unroll
    for (int i = 0; i < 4; ++i)
#pragma unroll
        for (int j = 0; j < 4; ++j)
#pragma unroll
            for (int q = 0; q < 4; ++q) acc[i][j][q] = 0.f;

    for (int kc = 0; kc < NCHUNKS; ++kc) {
        const int s = kc % PSTAGES;
        const int ph = (kc / PSTAGES) & 1;
        MBARRIER_WAIT_PARITY(bar0 + s * 8, ph);
        const uint32_t sb = dyn0 + s * STAGE_BYTES;

#pragma unroll
        for (int k16 = 0; k16 < 4; ++k16) {
            uint32_t ah[4][4], al[4][4], bh[2][4];
#pragma unroll
            for (int am = 0; am < 4; ++am) {
                const int rowA = wm + am * 16 + (lane & 15);
                const int g = k16 * 2 + (lane >> 4);
                const uint32_t off = (rowA << 7) + ((g ^ (rowA & 7)) << 4);
                ldsm_x4(ah[am], sb + RA_H + off);
                if (asplit) ldsm_x4(al[am], sb + RA_L + off);
            }
#pragma unroll
            for (int p = 0; p < 2; ++p) {
                const int rowB = wn + p * 16 + ((lane >> 4) << 3) + (lane & 7);
                const int g = k16 * 2 + ((lane >> 3) & 1);
                const uint32_t off = (rowB << 7) + ((g ^ (rowB & 7)) << 4);
                ldsm_x4(bh[p], sb + RB + off);
            }
#pragma unroll
            for (int am = 0; am < 4; ++am)
#pragma unroll
                for (int an = 0; an < 4; ++an) {
                    uint32_t* B0 = &bh[an >> 1][(an & 1) * 2];
                    MMA_F16(acc[am][an], ah[am], B0);
                    if (asplit) MMA_F16(acc[am][an], al[am], B0);
                }
        }
        __syncthreads();
        if (tid == 0 && kc + PSTAGES < NCHUNKS) issue(s, kc + PSTAGES);
    }

#pragma unroll
    for (int am = 0; am < 4; ++am) {
#pragma unroll
        for (int an = 0; an < 4; ++an) {
            const int m = m0 + wm + am * 16 + (lane >> 2);
            const int c = n0 + wn + an * 8 + ((lane & 3) << 1);
            const float2 bv = *(const float2*)&bias[c];
#pragma unroll
            for (int h2 = 0; h2 < 2; ++h2) {
                const int row = m + h2 * 8;
                float ox = (acc[am][an][2 * h2]     + bv.x) * scale;
                float oy = (acc[am][an][2 * h2 + 1] + bv.y) * scale;
                if (mode == 0) {
                    *(float2*)(out + (size_t)row * D_MODEL + c) = make_float2(ox, oy);
                } else {
                    const int b = row >> 11, srow = row & (SEQ - 1);
                    const int hh = c >> 6, dh = c & 63;
                    const size_t idx = (((size_t)(b * NHEAD + hh) * SEQ + srow) * HEAD_DIM + dh);
                    if (mode == 1) {
                        uint32_t h, l;
                        split2h(ox, oy, h, l);
                        *(uint32_t*)(oh + idx) = h;
                        *(uint32_t*)(ol + idx) = l;
                    } else {
                        *(uint32_t*)(oh + idx) = pkh(ox, oy);
                    }
                }
            }
        }
    }
}

// Fused Q/K/V projection: z selects input/weight/bias/output/mode.
// Q: A-split, hi/lo out. K: A-split, single out. V: A-single, single out.
__global__ void __launch_bounds__(256)
qkv_proj(const __grid_constant__ CUtensorMap tmQxh, const __grid_constant__ CUtensorMap tmQxl,
         const __grid_constant__ CUtensorMap tmKxh, const __grid_constant__ CUtensorMap tmKxl,
         const __grid_constant__ CUtensorMap tmVxh,
         const __grid_constant__ CUtensorMap tmWq,  const __grid_constant__ CUtensorMap tmWk,
         const __grid_constant__ CUtensorMap tmWv,
         const float* __restrict__ bq, const float* __restrict__ bk,
         const float* __restrict__ bv,
         __half* __restrict__ oQh, __half* __restrict__ oQl,
         __half* __restrict__ oK,  __half* __restrict__ oV, float qscale)
{
    extern __shared__ __align__(1024) char smem[];
    __shared__ __align__(8) ull s_bar[PSTAGES];
    const uint32_t dyn0 = smem_u32(smem);
    const uint32_t bar0 = smem_u32(s_bar);
    const int m0 = blockIdx.y << 7, n0 = blockIdx.x << 7;
    const int z = blockIdx.z;

    const CUtensorMap* pAh = z == 0 ? &tmQxh : (z == 1 ? &tmKxh : &tmVxh);
    const CUtensorMap* pAl = z == 0 ? &tmQxl : (z == 1 ? &tmKxl : &tmVxh);
    const CUtensorMap* pB  = z == 0 ? &tmWq  : (z == 1 ? &tmWk  : &tmWv);
    const float* bias = z == 0 ? bq : (z == 1 ? bk : bv);
    __half* oh = z == 0 ? oQh : (z == 1 ? oK : oV);
    __half* ol = z == 0 ? oQl : nullptr;
    const float scale = z == 0 ? qscale : 1.0f;
    const int mode = z == 0 ? 1 : 2;
    const bool asplit = (z != 2);

    proj_body(pAh, pAl, pB, bias, nullptr, oh, ol, scale, mode, asplit, m0, n0, dyn0, bar0);
}

// Output projection: A = ctx (single fp16), 1-MMA, fp32 out.
__global__ void __launch_bounds__(256)
out_proj(const __grid_constant__ CUtensorMap tmA, const __grid_constant__ CUtensorMap tmB,
         const float* __restrict__ bias, float* __restrict__ out)
{
    extern __shared__ __align__(1024) char smem[];
    __shared__ __align__(8) ull s_bar[PSTAGES];
    proj_body(&tmA, &tmA, &tmB, bias, out, nullptr, nullptr, 1.0f, 0, false,
              blockIdx.y << 7, blockIdx.x << 7, smem_u32(smem), smem_u32(s_bar));
}

// ---------------- TMA causal flash attention ------------------------------
// QK: fp16 2-MMA (Q split). PV: single fp16 P. Out: ctx single fp16.
// 2 CTAs/SM: regs capped at 128, smem 64KB/CTA (Q 32KB + 2 KV stages x 16KB).
#define KVSTAGES 2
#define KV0      32768
#define KVSB     16384
#define AT_SMEM  (KV0 + KVSTAGES * KVSB)

__global__ void __launch_bounds__(256, 2)
attn_mma(const __grid_constant__ CUtensorMap tmQh, const __grid_constant__ CUtensorMap tmQl,
         const __grid_constant__ CUtensorMap tmK,  const __grid_constant__ CUtensorMap tmV,
         __half* __restrict__ Ch)
{
    extern __shared__ __align__(1024) char smem[];
    __shared__ __align__(8) ull s_bar[1 + KVSTAGES];
    const uint32_t dyn0 = smem_u32(smem);
    const uint32_t barq = smem_u32(s_bar);
    const uint32_t bark = barq + 8;

    const int tid = threadIdx.x, wid = tid >> 5, lane = tid & 31;
    const int bx = (int)gridDim.x - 1 - (int)blockIdx.x;   // big tiles first
    const int bh = blockIdx.y;
    const int q0 = bx << 7;
    const int yb = bh * SEQ;
    const int ktend = 2 * bx + 2;

    if (tid == 0) {
        MBARRIER_INIT(barq, 1);
        for (int s = 0; s < KVSTAGES; ++s) MBARRIER_INIT(bark + s * 8, 1);
    }
    __syncthreads();

    auto issue_kv = [&](int s, int kt) {
        const uint32_t sb = dyn0 + KV0 + s * KVSB;
        const uint32_t fb = bark + s * 8;
        const int y = yb + kt * 64;
        MBARRIER_EXPECT_TX(fb, KVSB);
        TMA_LOAD_2D(sb,        &tmK, 0, y, fb);
        TMA_LOAD_2D(sb + 8192, &tmV, 0, y, fb);
    };
    if (tid == 0) {
        MBARRIER_EXPECT_TX(barq, 32768);
        TMA_LOAD_2D(dyn0,         &tmQh, 0, yb + q0, barq);
        TMA_LOAD_2D(dyn0 + 16384, &tmQl, 0, yb + q0, barq);
        const int np = ktend < KVSTAGES ? ktend : KVSTAGES;
        for (int p = 0; p < np; ++p) issue_kv(p, p);
    }

    MBARRIER_WAIT_PARITY(barq, 0);
    uint32_t qh[4][4], ql[4][4];
#pragma unroll
    for (int k16 = 0; k16 < 4; ++k16) {
        const int rowA = wid * 16 + (lane & 15);
        const int g = k16 * 2 + (lane >> 4);
        const uint32_t off = (rowA << 7) + ((g ^ (rowA & 7)) << 4);
        ldsm_x4(qh[k16], dyn0 + off);
        ldsm_x4(ql[k16], dyn0 + 16384 + off);
    }

    float O[8][4];
#pragma unroll
    for (int j = 0; j < 8; ++j)
#pragma unroll
        for (int q = 0; q < 4; ++q) O[j][q] = 0.f;
    float m0 = -1e30f, m1 = -1e30f, l0 = 0.f, l1 = 0.f;

    const int rrow = lane >> 2;
    const int ccol = (lane & 3) << 1;

    for (int kt = 0; kt < ktend; ++kt) {
        const int s = kt % KVSTAGES;
        const int ph = (kt / KVSTAGES) & 1;
        MBARRIER_WAIT_PARITY(bark + s * 8, ph);
        const uint32_t sb = dyn0 + KV0 + s * KVSB;

        const bool active = (kt * 64 <= q0 + wid * 16 + 15);
        if (active) {
            float S[8][4];
#pragma unroll
            for (int j = 0; j < 8; ++j)
#pragma unroll
                for (int q = 0; q < 4; ++q) S[j][q] = 0.f;
#pragma unroll
            for (int p = 0; p < 4; ++p) {
#pragma unroll
                for (int k16 = 0; k16 < 4; ++k16) {
                    uint32_t bkh[4];
                    const int rowB = p * 16 + ((lane >> 4) << 3) + (lane & 7);
                    const int g = k16 * 2 + ((lane >> 3) & 1);
                    const uint32_t off = (rowB << 7) + ((g ^ (rowB & 7)) << 4);
                    ldsm_x4(bkh, sb + off);
                    MMA_F16(S[2 * p],     qh[k16], &bkh[0]);
                    MMA_F16(S[2 * p],     ql[k16], &bkh[0]);
                    MMA_F16(S[2 * p + 1], qh[k16], &bkh[2]);
                    MMA_F16(S[2 * p + 1], ql[k16], &bkh[2]);
                }
            }

            if (kt >= 2 * bx) {
                const int r0g = q0 + wid * 16 + rrow;
#pragma unroll
                for (int jt = 0; jt < 8; ++jt) {
                    const int cg = kt * 64 + jt * 8 + ccol;
                    if (cg     > r0g)     S[jt][0] = -1e30f;
                    if (cg + 1 > r0g)     S[jt][1] = -1e30f;
                    if (cg     > r0g + 8) S[jt][2] = -1e30f;
                    if (cg + 1 > r0g + 8) S[jt][3] = -1e30f;
                }
            }

            float mx0 = -1e30f, mx1 = -1e30f;
#pragma unroll
            for (int jt = 0; jt < 8; ++jt) {
                mx0 = fmaxf(mx0, fmaxf(S[jt][0], S[jt][1]));
                mx1 = fmaxf(mx1, fmaxf(S[jt][2], S[jt][3]));
            }
            mx0 = fmaxf(mx0, __shfl_xor_sync(0xffffffffu, mx0, 1));
            mx0 = fmaxf(mx0, __shfl_xor_sync(0xffffffffu, mx0, 2));
            mx1 = fmaxf(mx1, __shfl_xor_sync(0xffffffffu, mx1, 1));
            mx1 = fmaxf(mx1, __shfl_xor_sync(0xffffffffu, mx1, 2));
            const float nm0 = fmaxf(m0, mx0), nm1 = fmaxf(m1, mx1);
            const float a0 = ex2(m0 - nm0), a1 = ex2(m1 - nm1);
            m0 = nm0; m1 = nm1;
            float s0 = 0.f, s1 = 0.f;
#pragma unroll
            for (int jt = 0; jt < 8; ++jt) {
                S[jt][0] = ex2(S[jt][0] - m0);
                S[jt][1] = ex2(S[jt][1] - m0);
                S[jt][2] = ex2(S[jt][2] - m1);
                S[jt][3] = ex2(S[jt][3] - m1);
                s0 += S[jt][0] + S[jt][1];
                s1 += S[jt][2] + S[jt][3];
            }
            s0 += __shfl_xor_sync(0xffffffffu, s0, 1);
            s0 += __shfl_xor_sync(0xffffffffu, s0, 2);
            s1 += __shfl_xor_sync(0xffffffffu, s1, 1);
            s1 += __shfl_xor_sync(0xffffffffu, s1, 2);
            l0 = l0 * a0 + s0;
            l1 = l1 * a1 + s1;
#pragma unroll
            for (int jt = 0; jt < 8; ++jt) {
                O[jt][0] *= a0; O[jt][1] *= a0;
                O[jt][2] *= a1; O[jt][3] *= a1;
            }

            uint32_t pfh[4][4];
#pragma unroll
            for (int kk = 0; kk < 4; ++kk) {
                pfh[kk][0] = pkh(S[2 * kk][0],     S[2 * kk][1]);
                pfh[kk][1] = pkh(S[2 * kk][2],     S[2 * kk][3]);
                pfh[kk][2] = pkh(S[2 * kk + 1][0], S[2 * kk + 1][1]);
                pfh[kk][3] = pkh(S[2 * kk + 1][2], S[2 * kk + 1][3]);
            }

#pragma unroll
            for (int p = 0; p < 4; ++p) {
#pragma unroll
                for (int kk = 0; kk < 4; ++kk) {
                    uint32_t vh[4];
                    const int key = kk * 16 + ((lane >> 3) & 1) * 8 + (lane & 7);
                    const int nt = 2 * p + (lane >> 4);
                    const uint32_t off = (key << 7) + (((nt) ^ (key & 7)) << 4);
                    ldsm_x4_t(vh, sb + 8192 + off);
                    MMA_F16(O[2 * p],     pfh[kk], &vh[0]);
                    MMA_F16(O[2 * p + 1], pfh[kk], &vh[2]);
                }
            }
        }
        __syncthreads();
        if (tid == 0 && kt + KVSTAGES < ktend) issue_kv(s, kt + KVSTAGES);
    }

    // ---- finalize: ctx single fp16 into out-proj A buffer
    const float inv0 = 1.f / l0, inv1 = 1.f / l1;
    const int b = bh >> 4, h = bh & 15;
    const int r0g = q0 + wid * 16 + rrow;
    const size_t mi0 = ((size_t)b * SEQ + r0g) * D_MODEL + h * 64;
    const size_t mi1 = ((size_t)b * SEQ + r0g + 8) * D_MODEL + h * 64;
#pragma unroll
    for (int jt = 0; jt < 8; ++jt) {
        const int c = jt * 8 + ccol;
        *(uint32_t*)(Ch + mi0 + c) = pkh(O[jt][0] * inv0, O[jt][1] * inv0);
        *(uint32_t*)(Ch + mi1 + c) = pkh(O[jt][2] * inv1, O[jt][3] * inv1);
    }
}

// ---------------- host-side tensor maps -----------------------------------
typedef CUresult (*EncodeFn)(CUtensorMap*, CUtensorMapDataType, cuuint32_t, void*,
                             const cuuint64_t*, const cuuint64_t*, const cuuint32_t*,
                             const cuuint32_t*, CUtensorMapInterleave, CUtensorMapSwizzle,
                             CUtensorMapL2promotion, CUtensorMapFloatOOBfill);

static void make_map(EncodeFn enc, CUtensorMap* m, void* base,
                     uint64_t d0, uint64_t d1, uint32_t box_rows)
{
    cuuint64_t dims[2] = {d0, d1};
    cuuint64_t strides[1] = {d0 * 2};
    cuuint32_t box[2] = {64u, box_rows};
    cuuint32_t es[2] = {1u, 1u};
    enc(m, CU_TENSOR_MAP_DATA_TYPE_FLOAT16, 2, base, dims, strides, box, es,
        CU_TENSOR_MAP_INTERLEAVE_NONE, CU_TENSOR_MAP_SWIZZLE_128B,
        CU_TENSOR_MAP_L2_PROMOTION_L2_128B, CU_TENSOR_MAP_FLOAT_OOB_FILL_NONE);
}

// ---------------- launcher -------------------------------------------------
extern "C" void kernel_launch(void* const* d_in, const int* in_sizes, int n_in,
                              void* d_out, int out_size)
{
    const float* query = (const float*)d_in[0];
    const float* key_  = (const float*)d_in[1];
    const float* value = (const float*)d_in[2];
    const float* Wq = (const float*)d_in[4];
    const float* bq = (const float*)d_in[5];
    const float* Wk = (const float*)d_in[6];
    const float* bk = (const float*)d_in[7];
    const float* Wv = (const float*)d_in[8];
    const float* bv = (const float*)d_in[9];
    const float* Wo = (const float*)d_in[10];
    const float* bo = (const float*)d_in[11];
    float* out = (float*)d_out;

    __half *pQh, *pQl, *pK, *pV;
    __half *pXqh, *pXql, *pXkh, *pXkl, *pXvh, *pXvl;
    __half *pWq, *pWk, *pWv, *pWo;
    cudaGetSymbolAddress((void**)&pQh, g_Qh);
    cudaGetSymbolAddress((void**)&pQl, g_Ql);
    cudaGetSymbolAddress((void**)&pK, g_K);
    cudaGetSymbolAddress((void**)&pV, g_V);
    cudaGetSymbolAddress((void**)&pXqh, g_Xq_hi);
    cudaGetSymbolAddress((void**)&pXql, g_Xq_lo);
    cudaGetSymbolAddress((void**)&pXkh, g_Xk_hi);
    cudaGetSymbolAddress((void**)&pXkl, g_Xk_lo);
    cudaGetSymbolAddress((void**)&pXvh, g_Xv_hi);
    cudaGetSymbolAddress((void**)&pXvl, g_Xv_lo);
    cudaGetSymbolAddress((void**)&pWq, g_Wq);
    cudaGetSymbolAddress((void**)&pWk, g_Wk);
    cudaGetSymbolAddress((void**)&pWv, g_Wv);
    cudaGetSymbolAddress((void**)&pWo, g_Wo);

    void* encp = nullptr;
    cudaDriverEntryPointQueryResult qr;
    cudaGetDriverEntryPointByVersion("cuTensorMapEncodeTiled", &encp, 12000,
                                     cudaEnableDefault, &qr);
    EncodeFn enc = (EncodeFn)encp;

    const uint64_t NR = (uint64_t)BATCH * NHEAD * SEQ;
    CUtensorMap tmXqh, tmXql, tmXkh, tmXkl, tmXvh;
    CUtensorMap tmWq, tmWk, tmWv, tmWo, tmQh, tmQl, tmK, tmV;
    make_map(enc, &tmXqh, pXqh, D_MODEL, M_TOT, 128);
    make_map(enc, &tmXql, pXql, D_MODEL, M_TOT, 128);
    make_map(enc, &tmXkh, pXkh, D_MODEL, M_TOT, 128);
    make_map(enc, &tmXkl, pXkl, D_MODEL, M_TOT, 128);
    make_map(enc, &tmXvh, pXvh, D_MODEL, M_TOT, 128);
    make_map(enc, &tmWq, pWq, D_MODEL, D_MODEL, 128);
    make_map(enc, &tmWk, pWk, D_MODEL, D_MODEL, 128);
    make_map(enc, &tmWv, pWv, D_MODEL, D_MODEL, 128);
    make_map(enc, &tmWo, pWo, D_MODEL, D_MODEL, 128);
    make_map(enc, &tmQh, pQh, HEAD_DIM, NR, 128);
    make_map(enc, &tmQl, pQl, HEAD_DIM, NR, 128);
    make_map(enc, &tmK,  pK,  HEAD_DIM, NR, 64);
    make_map(enc, &tmV,  pV,  HEAD_DIM, NR, 64);

    cudaFuncSetAttribute(qkv_proj, cudaFuncAttributeMaxDynamicSharedMemorySize, PROJ_SMEM);
    cudaFuncSetAttribute(out_proj, cudaFuncAttributeMaxDynamicSharedMemorySize, PROJ_SMEM);
    cudaFuncSetAttribute(attn_mma, cudaFuncAttributeMaxDynamicSharedMemorySize, AT_SMEM);

    const int NX4 = (M_TOT * D_MODEL) / 4;
    const int NW4 = (D_MODEL * D_MODEL) / 4;
    dim3 gcs(1024, 3);
    dim3 gcw(512, 4);
    dim3 gp3(D_MODEL / 128, M_TOT / 128, 3);
    dim3 gp(D_MODEL / 128, M_TOT / 128);
    dim3 ga(SEQ / 128, BATCH * NHEAD);
    const float qscale = 0.125f * 1.4426950408889634f;  // 1/sqrt(64) * log2(e)

    cvt_split3<<<gcs, 512>>>(query, key_, value, pXqh, pXql, pXkh, pXkl, pXvh, pXvl, NX4);
    cvt_single4<<<gcw, 512>>>(Wq, Wk, Wv, Wo, pWq, pWk, pWv, pWo, NW4);
    qkv_proj<<<gp3, 256, PROJ_SMEM>>>(tmXqh, tmXql, tmXkh, tmXkl, tmXvh,
                                      tmWq, tmWk, tmWv, bq, bk, bv,
                                      pQh, pQl, pK, pV, qscale);
    attn_mma<<<ga, 256, AT_SMEM>>>(tmQh, tmQl, tmK, tmV, pXqh);
    out_proj<<<gp, 256, PROJ_SMEM>>>(tmXqh, tmWo, bo, out);
}

// round 15
// speedup vs baseline: 6.5023x; 1.0808x over previous
#include <cuda_runtime.h>
#include <cuda.h>
#include <cuda_fp16.h>
#include <cstdint>

#define D_MODEL 1024
#define NHEAD   16
#define HEAD_DIM 64
#define BATCH   4
#define SEQ     2048
#define M_TOT   (BATCH * SEQ)

// ---------------- scratch (static device memory; no allocations) ----------
__device__ __half g_Q [BATCH * NHEAD * SEQ * HEAD_DIM];
__device__ __half g_K [BATCH * NHEAD * SEQ * HEAD_DIM];
__device__ __half g_V [BATCH * NHEAD * SEQ * HEAD_DIM];
__device__ __half g_Xq_hi[M_TOT * D_MODEL];   // also ctx (single fp16) after attn
__device__ __half g_Xq_lo[M_TOT * D_MODEL];
__device__ __half g_Xk_hi[M_TOT * D_MODEL];
__device__ __half g_Xk_lo[M_TOT * D_MODEL];
__device__ __half g_Xv_hi[M_TOT * D_MODEL];
__device__ __half g_Wq[D_MODEL * D_MODEL];
__device__ __half g_Wk[D_MODEL * D_MODEL];
__device__ __half g_Wv[D_MODEL * D_MODEL];
__device__ __half g_Wo[D_MODEL * D_MODEL];

typedef unsigned long long ull;

// ---------------- PTX helpers ---------------------------------------------
__device__ __forceinline__ uint32_t smem_u32(const void* p) {
    uint32_t a;
    asm("{ .reg .u64 t; cvta.to.shared.u64 t, %1; cvt.u32.u64 %0, t; }"
        : "=r"(a) : "l"(p));
    return a;
}
__device__ __forceinline__ void ldsm_x4(uint32_t* r, uint32_t a) {
    asm volatile("ldmatrix.sync.aligned.m8n8.x4.shared.b16 {%0,%1,%2,%3}, [%4];"
                 : "=r"(r[0]), "=r"(r[1]), "=r"(r[2]), "=r"(r[3]) : "r"(a));
}
__device__ __forceinline__ void ldsm_x4_t(uint32_t* r, uint32_t a) {
    asm volatile("ldmatrix.sync.aligned.m8n8.x4.trans.shared.b16 {%0,%1,%2,%3}, [%4];"
                 : "=r"(r[0]), "=r"(r[1]), "=r"(r[2]), "=r"(r[3]) : "r"(a));
}
#define MMA_F16(acc, a, b) \
    asm volatile("mma.sync.aligned.m16n8k16.row.col.f32.f16.f16.f32 " \
        "{%0,%1,%2,%3}, {%4,%5,%6,%7}, {%8,%9}, {%0,%1,%2,%3};" \
        : "+f"((acc)[0]), "+f"((acc)[1]), "+f"((acc)[2]), "+f"((acc)[3]) \
        : "r"((a)[0]), "r"((a)[1]), "r"((a)[2]), "r"((a)[3]), \
          "r"((b)[0]), "r"((b)[1]))

#define MBARRIER_INIT(addr, cnt) \
    asm volatile("mbarrier.init.shared.b64 [%0], %1;" :: "r"(addr), "r"(cnt) : "memory")
#define MBARRIER_EXPECT_TX(addr, bytes) \
    asm volatile("mbarrier.arrive.expect_tx.shared.b64 _, [%0], %1;" \
                 :: "r"(addr), "r"(bytes) : "memory")
#define MBARRIER_WAIT_PARITY(addr, parity) do { \
    uint32_t _m = (uint32_t)(addr); uint32_t _p = (uint32_t)(parity); uint32_t _d; \
    asm volatile("{\n\t.reg .pred p;\n\t" \
        "mbarrier.try_wait.parity.acquire.cta.shared::cta.b64 p, [%1], %2;\n\t" \
        "selp.b32 %0, 1, 0, p;\n\t}" : "=r"(_d) : "r"(_m), "r"(_p) : "memory"); \
    if (!_d) { \
        asm volatile("{\n\t.reg .pred P1;\n\t" \
            "WL_%=:\n\t" \
            "mbarrier.try_wait.parity.acquire.cta.shared::cta.b64 P1, [%0], %1, 0x989680;\n\t" \
            "@P1 bra.uni WD_%=;\n\t" \
            "bra.uni WL_%=;\n\t" \
            "WD_%=:\n\t}" :: "r"(_m), "r"(_p) : "memory"); \
    } } while (0)

#define TMA_LOAD_2D(smem_addr, tmap_ptr, cx, cy, mbar) \
    asm volatile("cp.async.bulk.tensor.2d.shared::cta.global.tile.mbarrier::complete_tx::bytes " \
        "[%0], [%1, {%2, %3}], [%4];" \
        :: "r"((uint32_t)(smem_addr)), "l"(tmap_ptr), "r"((int32_t)(cx)), "r"((int32_t)(cy)), \
           "r"((uint32_t)(mbar)) : "memory")

__device__ __forceinline__ uint32_t pkh(float x, float y) {
    __half2 hh = __floats2half2_rn(x, y);
    return *(uint32_t*)&hh;
}
__device__ __forceinline__ void split2h(float x, float y, uint32_t& h, uint32_t& l) {
    __half2 hh = __floats2half2_rn(x, y);
    float fx = __low2float(hh), fy = __high2float(hh);
    __half2 ll = __floats2half2_rn(x - fx, y - fy);
    h = *(uint32_t*)&hh;
    l = *(uint32_t*)&ll;
}
__device__ __forceinline__ float ex2(float x) {
    float y; asm("ex2.approx.ftz.f32 %0, %1;" : "=f"(y) : "f"(x)); return y;
}

// ---------------- batched fp32 -> fp16 conversions ------------------------
// seg 0: query -> hi/lo. seg 1: key -> hi/lo. seg 2: value -> hi only.
__global__ void __launch_bounds__(512)
cvt_split3(const float* __restrict__ x0, const float* __restrict__ x1,
           const float* __restrict__ x2,
           __half* __restrict__ h0, __half* __restrict__ l0_,
           __half* __restrict__ h1, __half* __restrict__ l1_,
           __half* __restrict__ h2, int n4)
{
    const int seg = blockIdx.y;
    const float* x = seg == 0 ? x0 : (seg == 1 ? x1 : x2);
    __half* hi = seg == 0 ? h0 : (seg == 1 ? h1 : h2);
    __half* lo = seg == 0 ? l0_ : (seg == 1 ? l1_ : nullptr);
    int i = blockIdx.x * blockDim.x + threadIdx.x;
    int stride = gridDim.x * blockDim.x;
    for (; i < n4; i += stride) {
        float4 v = ((const float4*)x)[i];
        if (seg < 2) {
            uint32_t a0, b0, a1, b1;
            split2h(v.x, v.y, a0, b0);
            split2h(v.z, v.w, a1, b1);
            ((uint32_t*)hi)[2 * i] = a0;  ((uint32_t*)hi)[2 * i + 1] = a1;
            ((uint32_t*)lo)[2 * i] = b0;  ((uint32_t*)lo)[2 * i + 1] = b1;
        } else {
            ((uint32_t*)hi)[2 * i]     = pkh(v.x, v.y);
            ((uint32_t*)hi)[2 * i + 1] = pkh(v.z, v.w);
        }
    }
}
__global__ void __launch_bounds__(512)
cvt_single4(const float* __restrict__ x0, const float* __restrict__ x1,
            const float* __restrict__ x2, const float* __restrict__ x3,
            __half* __restrict__ w0, __half* __restrict__ w1,
            __half* __restrict__ w2, __half* __restrict__ w3, int n4)
{
    const int seg = blockIdx.y;
    const float* x = seg == 0 ? x0 : (seg == 1 ? x1 : (seg == 2 ? x2 : x3));
    __half* w = seg == 0 ? w0 : (seg == 1 ? w1 : (seg == 2 ? w2 : w3));
    int i = blockIdx.x * blockDim.x + threadIdx.x;
    int stride = gridDim.x * blockDim.x;
    for (; i < n4; i += stride) {
        float4 v = ((const float4*)x)[i];
        ((uint32_t*)w)[2 * i]     = pkh(v.x, v.y);
        ((uint32_t*)w)[2 * i + 1] = pkh(v.z, v.w);
    }
}

// ---------------- TMA projection GEMM -------------------------------------
// asplit: A hi/lo split (2-MMA) or single (1-MMA).
// mode: 0 fp32 row-major out; 2 fp16 single head layout.
#define KC          64
#define NCHUNKS     (D_MODEL / KC)
#define PSTAGES     3
#define RA_H        0
#define RA_L        16384
#define RB          32768
#define STAGE_BYTES 49152
#define PROJ_SMEM   (PSTAGES * STAGE_BYTES)

__device__ __forceinline__ void proj_body(
    const CUtensorMap* pAh, const CUtensorMap* pAl, const CUtensorMap* pB,
    const float* bias, float* out, __half* oh, float scale,
    int mode, bool asplit, int m0, int n0, uint32_t dyn0, uint32_t bar0)
{
    const int tid = threadIdx.x;
    const int wid = tid >> 5, lane = tid & 31;
    const int wm = (wid & 1) << 6, wn = (wid >> 1) << 5;

    if (tid == 0) {
        for (int s = 0; s < PSTAGES; ++s) MBARRIER_INIT(bar0 + s * 8, 1);
    }
    __syncthreads();

    const uint32_t txbytes = asplit ? 49152u : 32768u;
    auto issue = [&](int s, int kc) {
        const uint32_t sb = dyn0 + s * STAGE_BYTES;
        const uint32_t fb = bar0 + s * 8;
        MBARRIER_EXPECT_TX(fb, txbytes);
        TMA_LOAD_2D(sb + RA_H, pAh, kc * KC, m0, fb);
        if (asplit) TMA_LOAD_2D(sb + RA_L, pAl, kc * KC, m0, fb);
        TMA_LOAD_2D(sb + RB,   pB,  kc * KC, n0, fb);
    };
    if (tid == 0) {
        for (int c = 0; c < PSTAGES; ++c) issue(c, c);
    }

    float acc[4][4][4];
#pragma unroll
    for (int i = 0; i < 4; ++i)
#pragma unroll
        for (int j = 0; j < 4; ++j)
#pragma unroll
            for (int q = 0; q < 4; ++q) acc[i][j][q] = 0.f;

    for (int kc = 0; kc < NCHUNKS; ++kc) {
        const int s = kc % PSTAGES;
        const int ph = (kc / PSTAGES) & 1;
        MBARRIER_WAIT_PARITY(bar0 + s * 8, ph);
        const uint32_t sb = dyn0 + s * STAGE_BYTES;

#pragma unroll
        for (int k16 = 0; k16 < 4; ++k16) {
            uint32_t ah[4][4], al[4][4], bh[2][4];
#pragma unroll
            for (int am = 0; am < 4; ++am) {
                const int rowA = wm + am * 16 + (lane & 15);
                const int g = k16 * 2 + (lane >> 4);
                const uint32_t off = (rowA << 7) + ((g ^ (rowA & 7)) << 4);
                ldsm_x4(ah[am], sb + RA_H + off);
                if (asplit) ldsm_x4(al[am], sb + RA_L + off);
            }
#pragma unroll
            for (int p = 0; p < 2; ++p) {
                const int rowB = wn + p * 16 + ((lane >> 4) << 3) + (lane & 7);
                const int g = k16 * 2 + ((lane >> 3) & 1);
                const uint32_t off = (rowB << 7) + ((g ^ (rowB & 7)) << 4);
                ldsm_x4(bh[p], sb + RB + off);
            }
#pragma unroll
            for (int am = 0; am < 4; ++am)
#pragma unroll
                for (int an = 0; an < 4; ++an) {
                    uint32_t* B0 = &bh[an >> 1][(an & 1) * 2];
                    MMA_F16(acc[am][an], ah[am], B0);
                    if (asplit) MMA_F16(acc[am][an], al[am], B0);
                }
        }
        __syncthreads();
        if (tid == 0 && kc + PSTAGES < NCHUNKS) issue(s, kc + PSTAGES);
    }

#pragma unroll
    for (int am = 0; am < 4; ++am) {
#pragma unroll
        for (int an = 0; an < 4; ++an) {
            const int m = m0 + wm + am * 16 + (lane >> 2);
            const int c = n0 + wn + an * 8 + ((lane & 3) << 1);
            const float2 bv = *(const float2*)&bias[c];
#pragma unroll
            for (int h2 = 0; h2 < 2; ++h2) {
                const int row = m + h2 * 8;
                float ox = (acc[am][an][2 * h2]     + bv.x) * scale;
                float oy = (acc[am][an][2 * h2 + 1] + bv.y) * scale;
                if (mode == 0) {
                    *(float2*)(out + (size_t)row * D_MODEL + c) = make_float2(ox, oy);
                } else {
                    const int b = row >> 11, srow = row & (SEQ - 1);
                    const int hh = c >> 6, dh = c & 63;
                    const size_t idx = (((size_t)(b * NHEAD + hh) * SEQ + srow) * HEAD_DIM + dh);
                    *(uint32_t*)(oh + idx) = pkh(ox, oy);
                }
            }
        }
    }
}

// Fused Q/K/V projection: z selects input/weight/bias/output.
// Q/K: A-split (2-MMA). V: A-single (1-MMA). All outputs single fp16 head layout.
__global__ void __launch_bounds__(256)
qkv_proj(const __grid_constant__ CUtensorMap tmQxh, const __grid_constant__ CUtensorMap tmQxl,
         const __grid_constant__ CUtensorMap tmKxh, const __grid_constant__ CUtensorMap tmKxl,
         const __grid_constant__ CUtensorMap tmVxh,
         const __grid_constant__ CUtensorMap tmWq,  const __grid_constant__ CUtensorMap tmWk,
         const __grid_constant__ CUtensorMap tmWv,
         const float* __restrict__ bq, const float* __restrict__ bk,
         const float* __restrict__ bv,
         __half* __restrict__ oQ, __half* __restrict__ oK, __half* __restrict__ oV,
         float qscale)
{
    extern __shared__ __align__(1024) char smem[];
    __shared__ __align__(8) ull s_bar[PSTAGES];
    const uint32_t dyn0 = smem_u32(smem);
    const uint32_t bar0 = smem_u32(s_bar);
    const int m0 = blockIdx.y << 7, n0 = blockIdx.x << 7;
    const int z = blockIdx.z;

    const CUtensorMap* pAh = z == 0 ? &tmQxh : (z == 1 ? &tmKxh : &tmVxh);
    const CUtensorMap* pAl = z == 0 ? &tmQxl : (z == 1 ? &tmKxl : &tmVxh);
    const CUtensorMap* pB  = z == 0 ? &tmWq  : (z == 1 ? &tmWk  : &tmWv);
    const float* bias = z == 0 ? bq : (z == 1 ? bk : bv);
    __half* oh = z == 0 ? oQ : (z == 1 ? oK : oV);
    const float scale = z == 0 ? qscale : 1.0f;
    const bool asplit = (z != 2);

    proj_body(pAh, pAl, pB, bias, nullptr, oh, scale, 2, asplit, m0, n0, dyn0, bar0);
}

// Output projection: A = ctx (single fp16), 1-MMA, fp32 out.
__global__ void __launch_bounds__(256)
out_proj(const __grid_constant__ CUtensorMap tmA, const __grid_constant__ CUtensorMap tmB,
         const float* __restrict__ bias, float* __restrict__ out)
{
    extern __shared__ __align__(1024) char smem[];
    __shared__ __align__(8) ull s_bar[PSTAGES];
    proj_body(&tmA, &tmA, &tmB, bias, out, nullptr, 1.0f, 0, false,
              blockIdx.y << 7, blockIdx.x << 7, smem_u32(smem), smem_u32(s_bar));
}

// ---------------- TMA causal flash attention ------------------------------
// All operands single fp16 (Q/K/V/P); errors symmetric with measured K-single.
// smem: Q 16KB + 3 KV stages x 16KB = 64KB/CTA; 2 CTAs/SM, regs capped at 128.
#define KVSTAGES 3
#define KV0      16384
#define KVSB     16384
#define AT_SMEM  (KV0 + KVSTAGES * KVSB)

__global__ void __launch_bounds__(256, 2)
attn_mma(const __grid_constant__ CUtensorMap tmQ, const __grid_constant__ CUtensorMap tmK,
         const __grid_constant__ CUtensorMap tmV, __half* __restrict__ Ch)
{
    extern __shared__ __align__(1024) char smem[];
    __shared__ __align__(8) ull s_bar[1 + KVSTAGES];
    const uint32_t dyn0 = smem_u32(smem);
    const uint32_t barq = smem_u32(s_bar);
    const uint32_t bark = barq + 8;

    const int tid = threadIdx.x, wid = tid >> 5, lane = tid & 31;
    const int bx = (int)gridDim.x - 1 - (int)blockIdx.x;   // big tiles first
    const int bh = blockIdx.y;
    const int q0 = bx << 7;
    const int yb = bh * SEQ;
    const int ktend = 2 * bx + 2;

    if (tid == 0) {
        MBARRIER_INIT(barq, 1);
        for (int s = 0; s < KVSTAGES; ++s) MBARRIER_INIT(bark + s * 8, 1);
    }
    __syncthreads();

    auto issue_kv = [&](int s, int kt) {
        const uint32_t sb = dyn0 + KV0 + s * KVSB;
        const uint32_t fb = bark + s * 8;
        const int y = yb + kt * 64;
        MBARRIER_EXPECT_TX(fb, KVSB);
        TMA_LOAD_2D(sb,        &tmK, 0, y, fb);
        TMA_LOAD_2D(sb + 8192, &tmV, 0, y, fb);
    };
    if (tid == 0) {
        MBARRIER_EXPECT_TX(barq, 16384);
        TMA_LOAD_2D(dyn0, &tmQ, 0, yb + q0, barq);
        const int np = ktend < KVSTAGES ? ktend : KVSTAGES;
        for (int p = 0; p < np; ++p) issue_kv(p, p);
    }

    MBARRIER_WAIT_PARITY(barq, 0);
    uint32_t qh[4][4];
#pragma unroll
    for (int k16 = 0; k16 < 4; ++k16) {
        const int rowA = wid * 16 + (lane & 15);
        const int g = k16 * 2 + (lane >> 4);
        const uint32_t off = (rowA << 7) + ((g ^ (rowA & 7)) << 4);
        ldsm_x4(qh[k16], dyn0 + off);
    }

    float O[8][4];
#pragma unroll
    for (int j = 0; j < 8; ++j)
#pragma unroll
        for (int q = 0; q < 4; ++q) O[j][q] = 0.f;
    float m0 = -1e30f, m1 = -1e30f, l0 = 0.f, l1 = 0.f;

    const int rrow = lane >> 2;
    const int ccol = (lane & 3) << 1;

    for (int kt = 0; kt < ktend; ++kt) {
        const int s = kt % KVSTAGES;
        const int ph = (kt / KVSTAGES) & 1;
        MBARRIER_WAIT_PARITY(bark + s * 8, ph);
        const uint32_t sb = dyn0 + KV0 + s * KVSB;

        const bool active = (kt * 64 <= q0 + wid * 16 + 15);
        if (active) {
            float S[8][4];
#pragma unroll
            for (int j = 0; j < 8; ++j)
#pragma unroll
                for (int q = 0; q < 4; ++q) S[j][q] = 0.f;
#pragma unroll
            for (int p = 0; p < 4; ++p) {
#pragma unroll
                for (int k16 = 0; k16 < 4; ++k16) {
                    uint32_t bkh[4];
                    const int rowB = p * 16 + ((lane >> 4) << 3) + (lane & 7);
                    const int g = k16 * 2 + ((lane >> 3) & 1);
                    const uint32_t off = (rowB << 7) + ((g ^ (rowB & 7)) << 4);
                    ldsm_x4(bkh, sb + off);
                    MMA_F16(S[2 * p],     qh[k16], &bkh[0]);
                    MMA_F16(S[2 * p + 1], qh[k16], &bkh[2]);
                }
            }

            if (kt >= 2 * bx) {
                const int r0g = q0 + wid * 16 + rrow;
#pragma unroll
                for (int jt = 0; jt < 8; ++jt) {
                    const int cg = kt * 64 + jt * 8 + ccol;
                    if (cg     > r0g)     S[jt][0] = -1e30f;
                    if (cg + 1 > r0g)     S[jt][1] = -1e30f;
                    if (cg     > r0g + 8) S[jt][2] = -1e30f;
                    if (cg + 1 > r0g + 8) S[jt][3] = -1e30f;
                }
            }

            float mx0 = -1e30f, mx1 = -1e30f;
#pragma unroll
            for (int jt = 0; jt < 8; ++jt) {
                mx0 = fmaxf(mx0, fmaxf(S[jt][0], S[jt][1]));
                mx1 = fmaxf(mx1, fmaxf(S[jt][2], S[jt][3]));
            }
            mx0 = fmaxf(mx0, __shfl_xor_sync(0xffffffffu, mx0, 1));
            mx0 = fmaxf(mx0, __shfl_xor_sync(0xffffffffu, mx0, 2));
            mx1 = fmaxf(mx1, __shfl_xor_sync(0xffffffffu, mx1, 1));
            mx1 = fmaxf(mx1, __shfl_xor_sync(0xffffffffu, mx1, 2));
            const float nm0 = fmaxf(m0, mx0), nm1 = fmaxf(m1, mx1);
            const float a0 = ex2(m0 - nm0), a1 = ex2(m1 - nm1);
            m0 = nm0; m1 = nm1;
            float s0 = 0.f, s1 = 0.f;
#pragma unroll
            for (int jt = 0; jt < 8; ++jt) {
                S[jt][0] = ex2(S[jt][0] - m0);
                S[jt][1] = ex2(S[jt][1] - m0);
                S[jt][2] = ex2(S[jt][2] - m1);
                S[jt][3] = ex2(S[jt][3] - m1);
                s0 += S[jt][0] + S[jt][1];
                s1 += S[jt][2] + S[jt][3];
            }
            s0 += __shfl_xor_sync(0xffffffffu, s0, 1);
            s0 += __shfl_xor_sync(0xffffffffu, s0, 2);
            s1 += __shfl_xor_sync(0xffffffffu, s1, 1);
            s1 += __shfl_xor_sync(0xffffffffu, s1, 2);
            l0 = l0 * a0 + s0;
            l1 = l1 * a1 + s1;
#pragma unroll
            for (int jt = 0; jt < 8; ++jt) {
                O[jt][0] *= a0; O[jt][1] *= a0;
                O[jt][2] *= a1; O[jt][3] *= a1;
            }

            uint32_t pfh[4][4];
#pragma unroll
            for (int kk = 0; kk < 4; ++kk) {
                pfh[kk][0] = pkh(S[2 * kk][0],     S[2 * kk][1]);
                pfh[kk][1] = pkh(S[2 * kk][2],     S[2 * kk][3]);
                pfh[kk][2] = pkh(S[2 * kk + 1][0], S[2 * kk + 1][1]);
                pfh[kk][3] = pkh(S[2 * kk + 1][2], S[2 * kk + 1][3]);
            }

#pragma unroll
            for (int p = 0; p < 4; ++p) {
#pragma unroll
                for (int kk = 0; kk < 4; ++kk) {
                    uint32_t vh[4];
                    const int key = kk * 16 + ((lane >> 3) & 1) * 8 + (lane & 7);
                    const int nt = 2 * p + (lane >> 4);
                    const uint32_t off = (key << 7) + (((nt) ^ (key & 7)) << 4);
                    ldsm_x4_t(vh, sb + 8192 + off);
                    MMA_F16(O[2 * p],     pfh[kk], &vh[0]);
                    MMA_F16(O[2 * p + 1], pfh[kk], &vh[2]);
                }
            }
        }
        __syncthreads();
        if (tid == 0 && kt + KVSTAGES < ktend) issue_kv(s, kt + KVSTAGES);
    }

    // ---- finalize: ctx single fp16 into out-proj A buffer
    const float inv0 = 1.f / l0, inv1 = 1.f / l1;
    const int b = bh >> 4, h = bh & 15;
    const int r0g = q0 + wid * 16 + rrow;
    const size_t mi0 = ((size_t)b * SEQ + r0g) * D_MODEL + h * 64;
    const size_t mi1 = ((size_t)b * SEQ + r0g + 8) * D_MODEL + h * 64;
#pragma unroll
    for (int jt = 0; jt < 8; ++jt) {
        const int c = jt * 8 + ccol;
        *(uint32_t*)(Ch + mi0 + c) = pkh(O[jt][0] * inv0, O[jt][1] * inv0);
        *(uint32_t*)(Ch + mi1 + c) = pkh(O[jt][2] * inv1, O[jt][3] * inv1);
    }
}

// ---------------- host-side tensor maps -----------------------------------
typedef CUresult (*EncodeFn)(CUtensorMap*, CUtensorMapDataType, cuuint32_t, void*,
                             const cuuint64_t*, const cuuint64_t*, const cuuint32_t*,
                             const cuuint32_t*, CUtensorMapInterleave, CUtensorMapSwizzle,
                             CUtensorMapL2promotion, CUtensorMapFloatOOBfill);

static void make_map(EncodeFn enc, CUtensorMap* m, void* base,
                     uint64_t d0, uint64_t d1, uint32_t box_rows)
{
    cuuint64_t dims[2] = {d0, d1};
    cuuint64_t strides[1] = {d0 * 2};
    cuuint32_t box[2] = {64u, box_rows};
    cuuint32_t es[2] = {1u, 1u};
    enc(m, CU_TENSOR_MAP_DATA_TYPE_FLOAT16, 2, base, dims, strides, box, es,
        CU_TENSOR_MAP_INTERLEAVE_NONE, CU_TENSOR_MAP_SWIZZLE_128B,
        CU_TENSOR_MAP_L2_PROMOTION_L2_128B, CU_TENSOR_MAP_FLOAT_OOB_FILL_NONE);
}

// ---------------- launcher -------------------------------------------------
extern "C" void kernel_launch(void* const* d_in, const int* in_sizes, int n_in,
                              void* d_out, int out_size)
{
    const float* query = (const float*)d_in[0];
    const float* key_  = (const float*)d_in[1];
    const float* value = (const float*)d_in[2];
    const float* Wq = (const float*)d_in[4];
    const float* bq = (const float*)d_in[5];
    const float* Wk = (const float*)d_in[6];
    const float* bk = (const float*)d_in[7];
    const float* Wv = (const float*)d_in[8];
    const float* bv = (const float*)d_in[9];
    const float* Wo = (const float*)d_in[10];
    const float* bo = (const float*)d_in[11];
    float* out = (float*)d_out;

    __half *pQ, *pK, *pV;
    __half *pXqh, *pXql, *pXkh, *pXkl, *pXvh;
    __half *pWq, *pWk, *pWv, *pWo;
    cudaGetSymbolAddress((void**)&pQ, g_Q);
    cudaGetSymbolAddress((void**)&pK, g_K);
    cudaGetSymbolAddress((void**)&pV, g_V);
    cudaGetSymbolAddress((void**)&pXqh, g_Xq_hi);
    cudaGetSymbolAddress((void**)&pXql, g_Xq_lo);
    cudaGetSymbolAddress((void**)&pXkh, g_Xk_hi);
    cudaGetSymbolAddress((void**)&pXkl, g_Xk_lo);
    cudaGetSymbolAddress((void**)&pXvh, g_Xv_hi);
    cudaGetSymbolAddress((void**)&pWq, g_Wq);
    cudaGetSymbolAddress((void**)&pWk, g_Wk);
    cudaGetSymbolAddress((void**)&pWv, g_Wv);
    cudaGetSymbolAddress((void**)&pWo, g_Wo);

    void* encp = nullptr;
    cudaDriverEntryPointQueryResult qr;
    cudaGetDriverEntryPointByVersion("cuTensorMapEncodeTiled", &encp, 12000,
                                     cudaEnableDefault, &qr);
    EncodeFn enc = (EncodeFn)encp;

    const uint64_t NR = (uint64_t)BATCH * NHEAD * SEQ;
    CUtensorMap tmXqh, tmXql, tmXkh, tmXkl, tmXvh;
    CUtensorMap tmWq, tmWk, tmWv, tmWo, tmQ, tmK, tmV;
    make_map(enc, &tmXqh, pXqh, D_MODEL, M_TOT, 128);
    make_map(enc, &tmXql, pXql, D_MODEL, M_TOT, 128);
    make_map(enc, &tmXkh, pXkh, D_MODEL, M_TOT, 128);
    make_map(enc, &tmXkl, pXkl, D_MODEL, M_TOT, 128);
    make_map(enc, &tmXvh, pXvh, D_MODEL, M_TOT, 128);
    make_map(enc, &tmWq, pWq, D_MODEL, D_MODEL, 128);
    make_map(enc, &tmWk, pWk, D_MODEL, D_MODEL, 128);
    make_map(enc, &tmWv, pWv, D_MODEL, D_MODEL, 128);
    make_map(enc, &tmWo, pWo, D_MODEL, D_MODEL, 128);
    make_map(enc, &tmQ, pQ, HEAD_DIM, NR, 128);
    make_map(enc, &tmK, pK, HEAD_DIM, NR, 64);
    make_map(enc, &tmV, pV, HEAD_DIM, NR, 64);

    cudaFuncSetAttribute(qkv_proj, cudaFuncAttributeMaxDynamicSharedMemorySize, PROJ_SMEM);
    cudaFuncSetAttribute(out_proj, cudaFuncAttributeMaxDynamicSharedMemorySize, PROJ_SMEM);
    cudaFuncSetAttribute(attn_mma, cudaFuncAttributeMaxDynamicSharedMemorySize, AT_SMEM);

    const int NX4 = (M_TOT * D_MODEL) / 4;
    const int NW4 = (D_MODEL * D_MODEL) / 4;
    dim3 gcs(1024, 3);
    dim3 gcw(512, 4);
    dim3 gp3(D_MODEL / 128, M_TOT / 128, 3);
    dim3 gp(D_MODEL / 128, M_TOT / 128);
    dim3 ga(SEQ / 128, BATCH * NHEAD);
    const float qscale = 0.125f * 1.4426950408889634f;  // 1/sqrt(64) * log2(e)

    cvt_split3<<<gcs, 512>>>(query, key_, value, pXqh, pXql, pXkh, pXkl, pXvh, NX4);
    cvt_single4<<<gcw, 512>>>(Wq, Wk, Wv, Wo, pWq, pWk, pWv, pWo, NW4);
    qkv_proj<<<gp3, 256, PROJ_SMEM>>>(tmXqh, tmXql, tmXkh, tmXkl, tmXvh,
                                      tmWq, tmWk, tmWv, bq, bk, bv,
                                      pQ, pK, pV, qscale);
    attn_mma<<<ga, 256, AT_SMEM>>>(tmQ, tmK, tmV, pXqh);
    out_proj<<<gp, 256, PROJ_SMEM>>>(tmXqh, tmWo, bo, out);
}

// round 17
// speedup vs baseline: 9.3209x; 1.4335x over previous
#include <cuda_runtime.h>
#include <cuda.h>
#include <cuda_fp16.h>
#include <cstdint>

#define D_MODEL 1024
#define NHEAD   16
#define HEAD_DIM 64
#define BATCH   4
#define SEQ     2048
#define M_TOT   (BATCH * SEQ)

// ---------------- scratch (static device memory; no allocations) ----------
__device__ __half g_Q [BATCH * NHEAD * SEQ * HEAD_DIM];
__device__ __half g_K [BATCH * NHEAD * SEQ * HEAD_DIM];
__device__ __half g_V [BATCH * NHEAD * SEQ * HEAD_DIM];
__device__ __half g_Xq[M_TOT * D_MODEL];   // also ctx (single fp16) after attn
__device__ __half g_Xk[M_TOT * D_MODEL];
__device__ __half g_Xv[M_TOT * D_MODEL];
__device__ __half g_Wq[D_MODEL * D_MODEL];
__device__ __half g_Wk[D_MODEL * D_MODEL];
__device__ __half g_Wv[D_MODEL * D_MODEL];
__device__ __half g_Wo[D_MODEL * D_MODEL];

typedef unsigned long long ull;

// ---------------- PTX helpers ---------------------------------------------
__device__ __forceinline__ uint32_t smem_u32(const void* p) {
    uint32_t a;
    asm("{ .reg .u64 t; cvta.to.shared.u64 t, %1; cvt.u32.u64 %0, t; }"
        : "=r"(a) : "l"(p));
    return a;
}
__device__ __forceinline__ void ldsm_x4(uint32_t* r, uint32_t a) {
    asm volatile("ldmatrix.sync.aligned.m8n8.x4.shared.b16 {%0,%1,%2,%3}, [%4];"
                 : "=r"(r[0]), "=r"(r[1]), "=r"(r[2]), "=r"(r[3]) : "r"(a));
}
__device__ __forceinline__ void ldsm_x4_t(uint32_t* r, uint32_t a) {
    asm volatile("ldmatrix.sync.aligned.m8n8.x4.trans.shared.b16 {%0,%1,%2,%3}, [%4];"
                 : "=r"(r[0]), "=r"(r[1]), "=r"(r[2]), "=r"(r[3]) : "r"(a));
}
#define MMA_F16(acc, a, b) \
    asm volatile("mma.sync.aligned.m16n8k16.row.col.f32.f16.f16.f32 " \
        "{%0,%1,%2,%3}, {%4,%5,%6,%7}, {%8,%9}, {%0,%1,%2,%3};" \
        : "+f"((acc)[0]), "+f"((acc)[1]), "+f"((acc)[2]), "+f"((acc)[3]) \
        : "r"((a)[0]), "r"((a)[1]), "r"((a)[2]), "r"((a)[3]), \
          "r"((b)[0]), "r"((b)[1]))

#define MBARRIER_INIT(addr, cnt) \
    asm volatile("mbarrier.init.shared.b64 [%0], %1;" :: "r"(addr), "r"(cnt) : "memory")
#define MBARRIER_EXPECT_TX(addr, bytes) \
    asm volatile("mbarrier.arrive.expect_tx.shared.b64 _, [%0], %1;" \
                 :: "r"(addr), "r"(bytes) : "memory")
#define MBARRIER_WAIT_PARITY(addr, parity) do { \
    uint32_t _m = (uint32_t)(addr); uint32_t _p = (uint32_t)(parity); uint32_t _d; \
    asm volatile("{\n\t.reg .pred p;\n\t" \
        "mbarrier.try_wait.parity.acquire.cta.shared::cta.b64 p, [%1], %2;\n\t" \
        "selp.b32 %0, 1, 0, p;\n\t}" : "=r"(_d) : "r"(_m), "r"(_p) : "memory"); \
    if (!_d) { \
        asm volatile("{\n\t.reg .pred P1;\n\t" \
            "WL_%=:\n\t" \
            "mbarrier.try_wait.parity.acquire.cta.shared::cta.b64 P1, [%0], %1, 0x989680;\n\t" \
            "@P1 bra.uni WD_%=;\n\t" \
            "bra.uni WL_%=;\n\t" \
            "WD_%=:\n\t}" :: "r"(_m), "r"(_p) : "memory"); \
    } } while (0)

#define TMA_LOAD_2D(smem_addr, tmap_ptr, cx, cy, mbar) \
    asm volatile("cp.async.bulk.tensor.2d.shared::cta.global.tile.mbarrier::complete_tx::bytes " \
        "[%0], [%1, {%2, %3}], [%4];" \
        :: "r"((uint32_t)(smem_addr)), "l"(tmap_ptr), "r"((int32_t)(cx)), "r"((int32_t)(cy)), \
           "r"((uint32_t)(mbar)) : "memory")

__device__ __forceinline__ uint32_t pkh(float x, float y) {
    __half2 hh = __floats2half2_rn(x, y);
    return *(uint32_t*)&hh;
}
__device__ __forceinline__ float ex2(float x) {
    float y; asm("ex2.approx.ftz.f32 %0, %1;" : "=f"(y) : "f"(x)); return y;
}

// ---------------- batched fp32 -> fp16 conversions ------------------------
__global__ void __launch_bounds__(512)
cvt3(const float* __restrict__ x0, const float* __restrict__ x1,
     const float* __restrict__ x2,
     __half* __restrict__ o0, __half* __restrict__ o1, __half* __restrict__ o2,
     int n4)
{
    const int seg = blockIdx.y;
    const float* x = seg == 0 ? x0 : (seg == 1 ? x1 : x2);
    __half* o = seg == 0 ? o0 : (seg == 1 ? o1 : o2);
    int i = blockIdx.x * blockDim.x + threadIdx.x;
    int stride = gridDim.x * blockDim.x;
    for (; i < n4; i += stride) {
        float4 v = ((const float4*)x)[i];
        ((uint32_t*)o)[2 * i]     = pkh(v.x, v.y);
        ((uint32_t*)o)[2 * i + 1] = pkh(v.z, v.w);
    }
}
__global__ void __launch_bounds__(512)
cvt4(const float* __restrict__ x0, const float* __restrict__ x1,
     const float* __restrict__ x2, const float* __restrict__ x3,
     __half* __restrict__ w0, __half* __restrict__ w1,
     __half* __restrict__ w2, __half* __restrict__ w3, int n4)
{
    const int seg = blockIdx.y;
    const float* x = seg == 0 ? x0 : (seg == 1 ? x1 : (seg == 2 ? x2 : x3));
    __half* w = seg == 0 ? w0 : (seg == 1 ? w1 : (seg == 2 ? w2 : w3));
    int i = blockIdx.x * blockDim.x + threadIdx.x;
    int stride = gridDim.x * blockDim.x;
    for (; i < n4; i += stride) {
        float4 v = ((const float4*)x)[i];
        ((uint32_t*)w)[2 * i]     = pkh(v.x, v.y);
        ((uint32_t*)w)[2 * i + 1] = pkh(v.z, v.w);
    }
}

// ---------------- TMA projection GEMM (all 1-MMA fp16) --------------------
// mode: 0 fp32 row-major out; 2 fp16 single head layout.
#define KC          64
#define NCHUNKS     (D_MODEL / KC)
#define PSTAGES     3
#define RA          0
#define RB          16384
#define STAGE_BYTES 32768
#define PROJ_SMEM   (PSTAGES * STAGE_BYTES)

__device__ __forceinline__ void proj_body(
    const CUtensorMap* pA, const CUtensorMap* pB,
    const float* bias, float* out, __half* oh, float scale,
    int mode, int m0, int n0, uint32_t dyn0, uint32_t bar0)
{
    const int tid = threadIdx.x;
    const int wid = tid >> 5, lane = tid & 31;
    const int wm = (wid & 1) << 6, wn = (wid >> 1) << 5;

    if (tid == 0) {
        for (int s = 0; s < PSTAGES; ++s) MBARRIER_INIT(bar0 + s * 8, 1);
    }
    __syncthreads();

    auto issue = [&](int s, int kc) {
        const uint32_t sb = dyn0 + s * STAGE_BYTES;
        const uint32_t fb = bar0 + s * 8;
        MBARRIER_EXPECT_TX(fb, (uint32_t)STAGE_BYTES);
        TMA_LOAD_2D(sb + RA, pA, kc * KC, m0, fb);
        TMA_LOAD_2D(sb + RB, pB, kc * KC, n0, fb);
    };
    if (tid == 0) {
        for (int c = 0; c < PSTAGES; ++c) issue(c, c);
    }

    float acc[4][4][4];
#pragma unroll
    for (int i = 0; i < 4; ++i)
#pragma unroll
        for (int j = 0; j < 4; ++j)
#pragma unroll
            for (int q = 0; q < 4; ++q) acc[i][j][q] = 0.f;

    for (int kc = 0; kc < NCHUNKS; ++kc) {
        const int s = kc % PSTAGES;
        const int ph = (kc / PSTAGES) & 1;
        MBARRIER_WAIT_PARITY(bar0 + s * 8, ph);
        const uint32_t sb = dyn0 + s * STAGE_BYTES;

#pragma unroll
        for (int k16 = 0; k16 < 4; ++k16) {
            uint32_t ah[4][4], bh[2][4];
#pragma unroll
            for (int am = 0; am < 4; ++am) {
                const int rowA = wm + am * 16 + (lane & 15);
                const int g = k16 * 2 + (lane >> 4);
                const uint32_t off = (rowA << 7) + ((g ^ (rowA & 7)) << 4);
                ldsm_x4(ah[am], sb + RA + off);
            }
#pragma unroll
            for (int p = 0; p < 2; ++p) {
                const int rowB = wn + p * 16 + ((lane >> 4) << 3) + (lane & 7);
                const int g = k16 * 2 + ((lane >> 3) & 1);
                const uint32_t off = (rowB << 7) + ((g ^ (rowB & 7)) << 4);
                ldsm_x4(bh[p], sb + RB + off);
            }
#pragma unroll
            for (int am = 0; am < 4; ++am)
#pragma unroll
                for (int an = 0; an < 4; ++an) {
                    uint32_t* B0 = &bh[an >> 1][(an & 1) * 2];
                    MMA_F16(acc[am][an], ah[am], B0);
                }
        }
        __syncthreads();
        if (tid == 0 && kc + PSTAGES < NCHUNKS) issue(s, kc + PSTAGES);
    }

#pragma unroll
    for (int am = 0; am < 4; ++am) {
#pragma unroll
        for (int an = 0; an < 4; ++an) {
            const int m = m0 + wm + am * 16 + (lane >> 2);
            const int c = n0 + wn + an * 8 + ((lane & 3) << 1);
            const float2 bv = *(const float2*)&bias[c];
#pragma unroll
            for (int h2 = 0; h2 < 2; ++h2) {
                const int row = m + h2 * 8;
                float ox = (acc[am][an][2 * h2]     + bv.x) * scale;
                float oy = (acc[am][an][2 * h2 + 1] + bv.y) * scale;
                if (mode == 0) {
                    *(float2*)(out + (size_t)row * D_MODEL + c) = make_float2(ox, oy);
                } else {
                    const int b = row >> 11, srow = row & (SEQ - 1);
                    const int hh = c >> 6, dh = c & 63;
                    const size_t idx = (((size_t)(b * NHEAD + hh) * SEQ + srow) * HEAD_DIM + dh);
                    *(uint32_t*)(oh + idx) = pkh(ox, oy);
                }
            }
        }
    }
}

// Fused Q/K/V projection: z selects input/weight/bias/output. All 1-MMA.
__global__ void __launch_bounds__(256, 2)
qkv_proj(const __grid_constant__ CUtensorMap tmXq, const __grid_constant__ CUtensorMap tmXk,
         const __grid_constant__ CUtensorMap tmXv,
         const __grid_constant__ CUtensorMap tmWq, const __grid_constant__ CUtensorMap tmWk,
         const __grid_constant__ CUtensorMap tmWv,
         const float* __restrict__ bq, const float* __restrict__ bk,
         const float* __restrict__ bv,
         __half* __restrict__ oQ, __half* __restrict__ oK, __half* __restrict__ oV,
         float qscale)
{
    extern __shared__ __align__(1024) char smem[];
    __shared__ __align__(8) ull s_bar[PSTAGES];
    const uint32_t dyn0 = smem_u32(smem);
    const uint32_t bar0 = smem_u32(s_bar);
    const int m0 = blockIdx.y << 7, n0 = blockIdx.x << 7;
    const int z = blockIdx.z;

    const CUtensorMap* pA = z == 0 ? &tmXq : (z == 1 ? &tmXk : &tmXv);
    const CUtensorMap* pB = z == 0 ? &tmWq : (z == 1 ? &tmWk : &tmWv);
    const float* bias = z == 0 ? bq : (z == 1 ? bk : bv);
    __half* oh = z == 0 ? oQ : (z == 1 ? oK : oV);
    const float scale = z == 0 ? qscale : 1.0f;

    proj_body(pA, pB, bias, nullptr, oh, scale, 2, m0, n0, dyn0, bar0);
}

// Output projection: A = ctx (single fp16), 1-MMA, fp32 out.
__global__ void __launch_bounds__(256, 2)
out_proj(const __grid_constant__ CUtensorMap tmA, const __grid_constant__ CUtensorMap tmB,
         const float* __restrict__ bias, float* __restrict__ out)
{
    extern __shared__ __align__(1024) char smem[];
    __shared__ __align__(8) ull s_bar[PSTAGES];
    proj_body(&tmA, &tmB, bias, out, nullptr, 1.0f, 0,
              blockIdx.y << 7, blockIdx.x << 7, smem_u32(smem), smem_u32(s_bar));
}

// ---------------- TMA causal flash attention (unchanged) ------------------
// All operands single fp16 (Q/K/V/P).
// smem: Q 16KB + 3 KV stages x 16KB = 64KB/CTA; 2 CTAs/SM, regs capped at 128.
#define KVSTAGES 3
#define KV0      16384
#define KVSB     16384
#define AT_SMEM  (KV0 + KVSTAGES * KVSB)

__global__ void __launch_bounds__(256, 2)
attn_mma(const __grid_constant__ CUtensorMap tmQ, const __grid_constant__ CUtensorMap tmK,
         const __grid_constant__ CUtensorMap tmV, __half* __restrict__ Ch)
{
    extern __shared__ __align__(1024) char smem[];
    __shared__ __align__(8) ull s_bar[1 + KVSTAGES];
    const uint32_t dyn0 = smem_u32(smem);
    const uint32_t barq = smem_u32(s_bar);
    const uint32_t bark = barq + 8;

    const int tid = threadIdx.x, wid = tid >> 5, lane = tid & 31;
    const int bx = (int)gridDim.x - 1 - (int)blockIdx.x;   // big tiles first
    const int bh = blockIdx.y;
    const int q0 = bx << 7;
    const int yb = bh * SEQ;
    const int ktend = 2 * bx + 2;

    if (tid == 0) {
        MBARRIER_INIT(barq, 1);
        for (int s = 0; s < KVSTAGES; ++s) MBARRIER_INIT(bark + s * 8, 1);
    }
    __syncthreads();

    auto issue_kv = [&](int s, int kt) {
        const uint32_t sb = dyn0 + KV0 + s * KVSB;
        const uint32_t fb = bark + s * 8;
        const int y = yb + kt * 64;
        MBARRIER_EXPECT_TX(fb, KVSB);
        TMA_LOAD_2D(sb,        &tmK, 0, y, fb);
        TMA_LOAD_2D(sb + 8192, &tmV, 0, y, fb);
    };
    if (tid == 0) {
        MBARRIER_EXPECT_TX(barq, 16384);
        TMA_LOAD_2D(dyn0, &tmQ, 0, yb + q0, barq);
        const int np = ktend < KVSTAGES ? ktend : KVSTAGES;
        for (int p = 0; p < np; ++p) issue_kv(p, p);
    }

    MBARRIER_WAIT_PARITY(barq, 0);
    uint32_t qh[4][4];
#pragma unroll
    for (int k16 = 0; k16 < 4; ++k16) {
        const int rowA = wid * 16 + (lane & 15);
        const int g = k16 * 2 + (lane >> 4);
        const uint32_t off = (rowA << 7) + ((g ^ (rowA & 7)) << 4);
        ldsm_x4(qh[k16], dyn0 + off);
    }

    float O[8][4];
#pragma unroll
    for (int j = 0; j < 8; ++j)
#pragma unroll
        for (int q = 0; q < 4; ++q) O[j][q] = 0.f;
    float m0 = -1e30f, m1 = -1e30f, l0 = 0.f, l1 = 0.f;

    const int rrow = lane >> 2;
    const int ccol = (lane & 3) << 1;

    for (int kt = 0; kt < ktend; ++kt) {
        const int s = kt % KVSTAGES;
        const int ph = (kt / KVSTAGES) & 1;
        MBARRIER_WAIT_PARITY(bark + s * 8, ph);
        const uint32_t sb = dyn0 + KV0 + s * KVSB;

        const bool active = (kt * 64 <= q0 + wid * 16 + 15);
        if (active) {
            float S[8][4];
#pragma unroll
            for (int j = 0; j < 8; ++j)
#pragma unroll
                for (int q = 0; q < 4; ++q) S[j][q] = 0.f;
#pragma unroll
            for (int p = 0; p < 4; ++p) {
#pragma unroll
                for (int k16 = 0; k16 < 4; ++k16) {
                    uint32_t bkh[4];
                    const int rowB = p * 16 + ((lane >> 4) << 3) + (lane & 7);
                    const int g = k16 * 2 + ((lane >> 3) & 1);
                    const uint32_t off = (rowB << 7) + ((g ^ (rowB & 7)) << 4);
                    ldsm_x4(bkh, sb + off);
                    MMA_F16(S[2 * p],     qh[k16], &bkh[0]);
                    MMA_F16(S[2 * p + 1], qh[k16], &bkh[2]);
                }
            }

            if (kt >= 2 * bx) {
                const int r0g = q0 + wid * 16 + rrow;
#pragma unroll
                for (int jt = 0; jt < 8; ++jt) {
                    const int cg = kt * 64 + jt * 8 + ccol;
                    if (cg     > r0g)     S[jt][0] = -1e30f;
                    if (cg + 1 > r0g)     S[jt][1] = -1e30f;
                    if (cg     > r0g + 8) S[jt][2] = -1e30f;
                    if (cg + 1 > r0g + 8) S[jt][3] = -1e30f;
                }
            }

            float mx0 = -1e30f, mx1 = -1e30f;
#pragma unroll
            for (int jt = 0; jt < 8; ++jt) {
                mx0 = fmaxf(mx0, fmaxf(S[jt][0], S[jt][1]));
                mx1 = fmaxf(mx1, fmaxf(S[jt][2], S[jt][3]));
            }
            mx0 = fmaxf(mx0, __shfl_xor_sync(0xffffffffu, mx0, 1));
            mx0 = fmaxf(mx0, __shfl_xor_sync(0xffffffffu, mx0, 2));
            mx1 = fmaxf(mx1, __shfl_xor_sync(0xffffffffu, mx1, 1));
            mx1 = fmaxf(mx1, __shfl_xor_sync(0xffffffffu, mx1, 2));
            const float nm0 = fmaxf(m0, mx0), nm1 = fmaxf(m1, mx1);
            const float a0 = ex2(m0 - nm0), a1 = ex2(m1 - nm1);
            m0 = nm0; m1 = nm1;
            float s0 = 0.f, s1 = 0.f;
#pragma unroll
            for (int jt = 0; jt < 8; ++jt) {
                S[jt][0] = ex2(S[jt][0] - m0);
                S[jt][1] = ex2(S[jt][1] - m0);
                S[jt][2] = ex2(S[jt][2] - m1);
                S[jt][3] = ex2(S[jt][3] - m1);
                s0 += S[jt][0] + S[jt][1];
                s1 += S[jt][2] + S[jt][3];
            }
            s0 += __shfl_xor_sync(0xffffffffu, s0, 1);
            s0 += __shfl_xor_sync(0xffffffffu, s0, 2);
            s1 += __shfl_xor_sync(0xffffffffu, s1, 1);
            s1 += __shfl_xor_sync(0xffffffffu, s1, 2);
            l0 = l0 * a0 + s0;
            l1 = l1 * a1 + s1;
#pragma unroll
            for (int jt = 0; jt < 8; ++jt) {
                O[jt][0] *= a0; O[jt][1] *= a0;
                O[jt][2] *= a1; O[jt][3] *= a1;
            }

            uint32_t pfh[4][4];
#pragma unroll
            for (int kk = 0; kk < 4; ++kk) {
                pfh[kk][0] = pkh(S[2 * kk][0],     S[2 * kk][1]);
                pfh[kk][1] = pkh(S[2 * kk][2],     S[2 * kk][3]);
                pfh[kk][2] = pkh(S[2 * kk + 1][0], S[2 * kk + 1][1]);
                pfh[kk][3] = pkh(S[2 * kk + 1][2], S[2 * kk + 1][3]);
            }

#pragma unroll
            for (int p = 0; p < 4; ++p) {
#pragma unroll
                for (int kk = 0; kk < 4; ++kk) {
                    uint32_t vh[4];
                    const int key = kk * 16 + ((lane >> 3) & 1) * 8 + (lane & 7);
                    const int nt = 2 * p + (lane >> 4);
                    const uint32_t off = (key << 7) + (((nt) ^ (key & 7)) << 4);
                    ldsm_x4_t(vh, sb + 8192 + off);
                    MMA_F16(O[2 * p],     pfh[kk], &vh[0]);
                    MMA_F16(O[2 * p + 1], pfh[kk], &vh[2]);
                }
            }
        }
        __syncthreads();
        if (tid == 0 && kt + KVSTAGES < ktend) issue_kv(s, kt + KVSTAGES);
    }

    // ---- finalize: ctx single fp16 into out-proj A buffer
    const float inv0 = 1.f / l0, inv1 = 1.f / l1;
    const int b = bh >> 4, h = bh & 15;
    const int r0g = q0 + wid * 16 + rrow;
    const size_t mi0 = ((size_t)b * SEQ + r0g) * D_MODEL + h * 64;
    const size_t mi1 = ((size_t)b * SEQ + r0g + 8) * D_MODEL + h * 64;
#pragma unroll
    for (int jt = 0; jt < 8; ++jt) {
        const int c = jt * 8 + ccol;
        *(uint32_t*)(Ch + mi0 + c) = pkh(O[jt][0] * inv0, O[jt][1] * inv0);
        *(uint32_t*)(Ch + mi1 + c) = pkh(O[jt][2] * inv1, O[jt][3] * inv1);
    }
}

// ---------------- host-side tensor maps -----------------------------------
typedef CUresult (*EncodeFn)(CUtensorMap*, CUtensorMapDataType, cuuint32_t, void*,
                             const cuuint64_t*, const cuuint64_t*, const cuuint32_t*,
                             const cuuint32_t*, CUtensorMapInterleave, CUtensorMapSwizzle,
                             CUtensorMapL2promotion, CUtensorMapFloatOOBfill);

static void make_map(EncodeFn enc, CUtensorMap* m, void* base,
                     uint64_t d0, uint64_t d1, uint32_t box_rows)
{
    cuuint64_t dims[2] = {d0, d1};
    cuuint64_t strides[1] = {d0 * 2};
    cuuint32_t box[2] = {64u, box_rows};
    cuuint32_t es[2] = {1u, 1u};
    enc(m, CU_TENSOR_MAP_DATA_TYPE_FLOAT16, 2, base, dims, strides, box, es,
        CU_TENSOR_MAP_INTERLEAVE_NONE, CU_TENSOR_MAP_SWIZZLE_128B,
        CU_TENSOR_MAP_L2_PROMOTION_L2_128B, CU_TENSOR_MAP_FLOAT_OOB_FILL_NONE);
}

// ---------------- launcher -------------------------------------------------
extern "C" void kernel_launch(void* const* d_in, const int* in_sizes, int n_in,
                              void* d_out, int out_size)
{
    const float* query = (const float*)d_in[0];
    const float* key_  = (const float*)d_in[1];
    const float* value = (const float*)d_in[2];
    const float* Wq = (const float*)d_in[4];
    const float* bq = (const float*)d_in[5];
    const float* Wk = (const float*)d_in[6];
    const float* bk = (const float*)d_in[7];
    const float* Wv = (const float*)d_in[8];
    const float* bv = (const float*)d_in[9];
    const float* Wo = (const float*)d_in[10];
    const float* bo = (const float*)d_in[11];
    float* out = (float*)d_out;

    __half *pQ, *pK, *pV, *pXq, *pXk, *pXv, *pWq, *pWk, *pWv, *pWo;
    cudaGetSymbolAddress((void**)&pQ, g_Q);
    cudaGetSymbolAddress((void**)&pK, g_K);
    cudaGetSymbolAddress((void**)&pV, g_V);
    cudaGetSymbolAddress((void**)&pXq, g_Xq);
    cudaGetSymbolAddress((void**)&pXk, g_Xk);
    cudaGetSymbolAddress((void**)&pXv, g_Xv);
    cudaGetSymbolAddress((void**)&pWq, g_Wq);
    cudaGetSymbolAddress((void**)&pWk, g_Wk);
    cudaGetSymbolAddress((void**)&pWv, g_Wv);
    cudaGetSymbolAddress((void**)&pWo, g_Wo);

    void* encp = nullptr;
    cudaDriverEntryPointQueryResult qr;
    cudaGetDriverEntryPointByVersion("cuTensorMapEncodeTiled", &encp, 12000,
                                     cudaEnableDefault, &qr);
    EncodeFn enc = (EncodeFn)encp;

    const uint64_t NR = (uint64_t)BATCH * NHEAD * SEQ;
    CUtensorMap tmXq, tmXk, tmXv, tmWq, tmWk, tmWv, tmWo, tmQ, tmK, tmV;
    make_map(enc, &tmXq, pXq, D_MODEL, M_TOT, 128);
    make_map(enc, &tmXk, pXk, D_MODEL, M_TOT, 128);
    make_map(enc, &tmXv, pXv, D_MODEL, M_TOT, 128);
    make_map(enc, &tmWq, pWq, D_MODEL, D_MODEL, 128);
    make_map(enc, &tmWk, pWk, D_MODEL, D_MODEL, 128);
    make_map(enc, &tmWv, pWv, D_MODEL, D_MODEL, 128);
    make_map(enc, &tmWo, pWo, D_MODEL, D_MODEL, 128);
    make_map(enc, &tmQ, pQ, HEAD_DIM, NR, 128);
    make_map(enc, &tmK, pK, HEAD_DIM, NR, 64);
    make_map(enc, &tmV, pV, HEAD_DIM, NR, 64);

    cudaFuncSetAttribute(qkv_proj, cudaFuncAttributeMaxDynamicSharedMemorySize, PROJ_SMEM);
    cudaFuncSetAttribute(out_proj, cudaFuncAttributeMaxDynamicSharedMemorySize, PROJ_SMEM);
    cudaFuncSetAttribute(attn_mma, cudaFuncAttributeMaxDynamicSharedMemorySize, AT_SMEM);

    const int NX4 = (M_TOT * D_MODEL) / 4;
    const int NW4 = (D_MODEL * D_MODEL) / 4;
    dim3 gcs(1024, 3);
    dim3 gcw(512, 4);
    dim3 gp3(D_MODEL / 128, M_TOT / 128, 3);
    dim3 gp(D_MODEL / 128, M_TOT / 128);
    dim3 ga(SEQ / 128, BATCH * NHEAD);
    const float qscale = 0.125f * 1.4426950408889634f;  // 1/sqrt(64) * log2(e)

    cvt3<<<gcs, 512>>>(query, key_, value, pXq, pXk, pXv, NX4);
    cvt4<<<gcw, 512>>>(Wq, Wk, Wv, Wo, pWq, pWk, pWv, pWo, NW4);
    qkv_proj<<<gp3, 256, PROJ_SMEM>>>(tmXq, tmXk, tmXv, tmWq, tmWk, tmWv,
                                      bq, bk, bv, pQ, pK, pV, qscale);
    attn_mma<<<ga, 256, AT_SMEM>>>(tmQ, tmK, tmV, pXq);
    out_proj<<<gp, 256, PROJ_SMEM>>>(tmXq, tmWo, bo, out);
}